// round 2
// baseline (speedup 1.0000x reference)
#include <cuda_runtime.h>
#include <cuda_bf16.h>
#include <math.h>

// Problem constants (fixed by the dataset)
#define BATCH   32
#define DIM     4096
#define NH      32
#define NKV     8
#define HD      128
#define NREP    4          // NH / NKV
#define MAXSEQ  4096
#define NQKV    6144       // 4096 (q) + 1024 (k) + 1024 (v)
#define KC      256        // k-chunk for split-K GEMMs
#define NCH     16         // 4096 / KC
#define NSPLIT  4          // KV splits in attention
#define TSPLIT  1024       // MAXSEQ / NSPLIT

// Scratch (device globals; no allocation allowed)
__device__ float g_part [NCH * BATCH * NQKV];   // QKV split-K partials
__device__ float g_q    [BATCH * NH * HD];      // rope'd q
__device__ float g_k    [BATCH * NKV * HD];     // rope'd new k
__device__ float g_v    [BATCH * NKV * HD];     // new v
__device__ float g_att  [BATCH * NH * HD];      // attention output (b, nh*HD+d)
__device__ float g_opart[NCH * BATCH * DIM];    // O-proj split-K partials
// Attention split-KV partials
__device__ float g_pm  [BATCH * NKV * NSPLIT * NREP];
__device__ float g_pl  [BATCH * NKV * NSPLIT * NREP];
__device__ float g_pacc[BATCH * NKV * NSPLIT * NREP * HD];

// ---------------------------------------------------------------------------
// Kernel A: QKV projection, split-K.
// grid (48, 16), block 128. Block = 128 columns x 32 batches x 256 K.
// ---------------------------------------------------------------------------
__global__ __launch_bounds__(128)
void qkv_gemm(const float* __restrict__ x,
              const float* __restrict__ wq,
              const float* __restrict__ wk,
              const float* __restrict__ wv)
{
    __shared__ float xs[BATCH * KC];   // 32 KB
    const int tx = threadIdx.x;
    const int bx = blockIdx.x;         // column tile (0..47)
    const int by = blockIdx.y;         // k chunk (0..15)
    const int k0 = by * KC;

    #pragma unroll
    for (int i = 0; i < 16; i++) {
        int s  = tx + i * 128;          // float4 slot 0..2047
        int b  = s >> 6;
        int k4 = s & 63;
        float4 v = *(const float4*)&x[b * DIM + k0 + k4 * 4];
        *(float4*)&xs[b * KC + k4 * 4] = v;
    }
    __syncthreads();

    const int q  = tx & 31;            // column quad id
    const int g  = tx >> 5;            // batch group 0..3
    const int b0 = g * 8;
    const int gcol = bx * 128 + q * 4; // global column 0..6143

    const float* w; int ncols; int wcol;
    if (gcol < 4096)      { w = wq; ncols = 4096; wcol = gcol; }
    else if (gcol < 5120) { w = wk; ncols = 1024; wcol = gcol - 4096; }
    else                  { w = wv; ncols = 1024; wcol = gcol - 5120; }
    const float* wp = w + (size_t)k0 * ncols + wcol;

    float acc[8][4];
    #pragma unroll
    for (int i = 0; i < 8; i++)
        #pragma unroll
        for (int j = 0; j < 4; j++) acc[i][j] = 0.f;

    for (int kk = 0; kk < KC; kk += 4) {
        float xv[8][4];
        #pragma unroll
        for (int i = 0; i < 8; i++) {
            float4 t4 = *(const float4*)&xs[(b0 + i) * KC + kk];
            xv[i][0] = t4.x; xv[i][1] = t4.y; xv[i][2] = t4.z; xv[i][3] = t4.w;
        }
        #pragma unroll
        for (int j = 0; j < 4; j++) {
            float4 w4 = *(const float4*)&wp[(size_t)(kk + j) * ncols];
            #pragma unroll
            for (int i = 0; i < 8; i++) {
                acc[i][0] = fmaf(xv[i][j], w4.x, acc[i][0]);
                acc[i][1] = fmaf(xv[i][j], w4.y, acc[i][1]);
                acc[i][2] = fmaf(xv[i][j], w4.z, acc[i][2]);
                acc[i][3] = fmaf(xv[i][j], w4.w, acc[i][3]);
            }
        }
    }

    #pragma unroll
    for (int i = 0; i < 8; i++) {
        float4 r = make_float4(acc[i][0], acc[i][1], acc[i][2], acc[i][3]);
        *(float4*)&g_part[((size_t)by * BATCH + b0 + i) * NQKV + gcol] = r;
    }
}

// ---------------------------------------------------------------------------
// Kernel B: reduce split-K partials + RoPE -> g_q, g_k, g_v.
// ---------------------------------------------------------------------------
__global__ __launch_bounds__(256)
void rope_reduce(const float* __restrict__ fcos, const float* __restrict__ fsin)
{
    int idx = blockIdx.x * 256 + threadIdx.x;     // 0 .. 98303
    int b = idx / (NQKV / 2);
    int p = idx % (NQKV / 2);
    int col = 2 * p;

    float v0 = 0.f, v1 = 0.f;
    #pragma unroll
    for (int c = 0; c < NCH; c++) {
        float2 t = *(const float2*)&g_part[((size_t)c * BATCH + b) * NQKV + col];
        v0 += t.x; v1 += t.y;
    }

    if (col < 4096) {                 // Q with rope
        int d = col & (HD - 1);
        int dp = d >> 1;
        float c = fcos[dp], s = fsin[dp];
        g_q[b * 4096 + col]     = v0 * c - v1 * s;
        g_q[b * 4096 + col + 1] = v0 * s + v1 * c;
    } else if (col < 5120) {          // K with rope
        int cc = col - 4096;
        int d = cc & (HD - 1);
        int dp = d >> 1;
        float c = fcos[dp], s = fsin[dp];
        g_k[b * 1024 + cc]     = v0 * c - v1 * s;
        g_k[b * 1024 + cc + 1] = v0 * s + v1 * c;
    } else {                          // V passthrough
        int cc = col - 5120;
        g_v[b * 1024 + cc]     = v0;
        g_v[b * 1024 + cc + 1] = v1;
    }
}

// ---------------------------------------------------------------------------
// Kernel C: flash-decode GQA attention with split-KV.
// grid (NKV, BATCH, NSPLIT), block 256 (8 warps). Warp w: t = t0+w, +8,...
// Lane l owns head-dims 4l..4l+3. Per-head softmax denominators (the R1 fix).
// ---------------------------------------------------------------------------
#define ATT_STEP(k4, v4)                                                      \
    {                                                                         \
        float s0 = qv[0][0]*k4.x + qv[0][1]*k4.y + qv[0][2]*k4.z + qv[0][3]*k4.w; \
        float s1 = qv[1][0]*k4.x + qv[1][1]*k4.y + qv[1][2]*k4.z + qv[1][3]*k4.w; \
        float s2 = qv[2][0]*k4.x + qv[2][1]*k4.y + qv[2][2]*k4.z + qv[2][3]*k4.w; \
        float s3 = qv[3][0]*k4.x + qv[3][1]*k4.y + qv[3][2]*k4.z + qv[3][3]*k4.w; \
        _Pragma("unroll")                                                     \
        for (int off = 16; off > 0; off >>= 1) {                              \
            s0 += __shfl_xor_sync(0xffffffffu, s0, off);                      \
            s1 += __shfl_xor_sync(0xffffffffu, s1, off);                      \
            s2 += __shfl_xor_sync(0xffffffffu, s2, off);                      \
            s3 += __shfl_xor_sync(0xffffffffu, s3, off);                      \
        }                                                                     \
        float mx = fmaxf(fmaxf(s0, s1), fmaxf(s2, s3));                       \
        if (mx > m) {                                                         \
            float alpha = exp2f(m - mx);                                      \
            _Pragma("unroll")                                                 \
            for (int qi = 0; qi < NREP; qi++) {                               \
                lsum[qi] *= alpha;                                            \
                acc[qi][0] *= alpha; acc[qi][1] *= alpha;                     \
                acc[qi][2] *= alpha; acc[qi][3] *= alpha;                     \
            }                                                                 \
            m = mx;                                                           \
        }                                                                     \
        float p0 = exp2f(s0 - m), p1 = exp2f(s1 - m);                         \
        float p2 = exp2f(s2 - m), p3 = exp2f(s3 - m);                         \
        lsum[0] += p0; lsum[1] += p1; lsum[2] += p2; lsum[3] += p3;           \
        acc[0][0] += p0*v4.x; acc[0][1] += p0*v4.y; acc[0][2] += p0*v4.z; acc[0][3] += p0*v4.w; \
        acc[1][0] += p1*v4.x; acc[1][1] += p1*v4.y; acc[1][2] += p1*v4.z; acc[1][3] += p1*v4.w; \
        acc[2][0] += p2*v4.x; acc[2][1] += p2*v4.y; acc[2][2] += p2*v4.z; acc[2][3] += p2*v4.w; \
        acc[3][0] += p3*v4.x; acc[3][1] += p3*v4.y; acc[3][2] += p3*v4.z; acc[3][3] += p3*v4.w; \
    }

__global__ __launch_bounds__(256)
void attention(const float* __restrict__ cache_k,
               const float* __restrict__ cache_v,
               const int* __restrict__ start_pos)
{
    const int h   = blockIdx.x;
    const int b   = blockIdx.y;
    const int spl = blockIdx.z;
    const int tx = threadIdx.x;
    const int w  = tx >> 5;
    const int l  = tx & 31;

    const int sp = *start_pos;            // 4095
    const int t0 = spl * TSPLIT;
    const int t1 = min(t0 + TSPLIT, sp + 1);
    const int tmain = min(t1, sp);        // positions < sp come from the cache

    // q scaled by log2(e)/sqrt(HD)
    const float qscale = 1.4426950408889634f * 0.08838834764831845f;
    float qv[NREP][4];
    #pragma unroll
    for (int qi = 0; qi < NREP; qi++) {
        float4 t4 = *(const float4*)&g_q[b * 4096 + (h * NREP + qi) * HD + l * 4];
        qv[qi][0] = t4.x * qscale; qv[qi][1] = t4.y * qscale;
        qv[qi][2] = t4.z * qscale; qv[qi][3] = t4.w * qscale;
    }

    float m = -1e30f;
    float lsum[NREP] = {0.f, 0.f, 0.f, 0.f};
    float acc[NREP][4];
    #pragma unroll
    for (int qi = 0; qi < NREP; qi++)
        #pragma unroll
        for (int j = 0; j < 4; j++) acc[qi][j] = 0.f;

    const size_t base = ((size_t)b * MAXSEQ * NKV + h) * HD + l * 4;
    const float* kbase = cache_k + base;
    const float* vbase = cache_v + base;

    #pragma unroll 4
    for (int t = t0 + w; t < tmain; t += 8) {
        float4 k4 = *(const float4*)&kbase[(size_t)t * (NKV * HD)];
        float4 v4 = *(const float4*)&vbase[(size_t)t * (NKV * HD)];
        ATT_STEP(k4, v4)
    }
    // New token (t == sp): lives in g_k/g_v, owned by warp (sp & 7) of its split
    if (sp >= t0 && sp < t1 && (sp & 7) == w) {
        float4 k4 = *(const float4*)&g_k[b * (NKV * HD) + h * HD + l * 4];
        float4 v4 = *(const float4*)&g_v[b * (NKV * HD) + h * HD + l * 4];
        ATT_STEP(k4, v4)
    }

    // Merge 8 warp-partials through smem
    __shared__ float sm_acc[8][NREP][HD];   // 16 KB
    __shared__ float sm_m[8];
    __shared__ float sm_l[8][NREP];
    #pragma unroll
    for (int qi = 0; qi < NREP; qi++) {
        sm_acc[w][qi][l * 4 + 0] = acc[qi][0];
        sm_acc[w][qi][l * 4 + 1] = acc[qi][1];
        sm_acc[w][qi][l * 4 + 2] = acc[qi][2];
        sm_acc[w][qi][l * 4 + 3] = acc[qi][3];
    }
    if (l < NREP) sm_l[w][l] = lsum[l];
    if (l == 4)  sm_m[w] = m;
    __syncthreads();

    #pragma unroll
    for (int r = 0; r < 2; r++) {
        int o  = tx + r * 256;        // 0..511
        int qi = o >> 7;
        int d  = o & (HD - 1);
        float M = sm_m[0];
        #pragma unroll
        for (int w2 = 1; w2 < 8; w2++) M = fmaxf(M, sm_m[w2]);
        float den = 0.f, num = 0.f;
        #pragma unroll
        for (int w2 = 0; w2 < 8; w2++) {
            float wgt = exp2f(sm_m[w2] - M);
            den += wgt * sm_l[w2][qi];
            num += wgt * sm_acc[w2][qi][d];
        }
        int pbase = (((b * NKV + h) * NSPLIT + spl) * NREP + qi);
        g_pacc[(size_t)pbase * HD + d] = num;
        if (d == 0) { g_pl[pbase] = den; g_pm[pbase] = M; }
    }
}

// ---------------------------------------------------------------------------
// Kernel C2: merge the NSPLIT partials -> g_att
// grid (BATCH*NKV), block 512: thread = (qi, d)
// ---------------------------------------------------------------------------
__global__ __launch_bounds__(512)
void att_merge()
{
    const int bh = blockIdx.x;            // b*NKV + h
    const int o  = threadIdx.x;           // 0..511
    const int qi = o >> 7;
    const int d  = o & (HD - 1);
    const int base = bh * NSPLIT * NREP + qi;

    float M = -1e30f;
    #pragma unroll
    for (int s = 0; s < NSPLIT; s++) M = fmaxf(M, g_pm[base + s * NREP]);
    float num = 0.f, den = 0.f;
    #pragma unroll
    for (int s = 0; s < NSPLIT; s++) {
        int p = base + s * NREP;
        float wgt = exp2f(g_pm[p] - M);
        num += wgt * g_pacc[(size_t)p * HD + d];
        den += wgt * g_pl[p];
    }
    const int b = bh >> 3, h = bh & 7;
    g_att[b * 4096 + (h * NREP + qi) * HD + d] = num / den;
}

// ---------------------------------------------------------------------------
// Kernel D: output projection att[32,4096] @ wo[4096,4096], split-K.
// ---------------------------------------------------------------------------
__global__ __launch_bounds__(128)
void o_gemm(const float* __restrict__ wo)
{
    __shared__ float xs[BATCH * KC];
    const int tx = threadIdx.x;
    const int bx = blockIdx.x;         // column tile (0..31)
    const int by = blockIdx.y;         // k chunk (0..15)
    const int k0 = by * KC;

    #pragma unroll
    for (int i = 0; i < 16; i++) {
        int s  = tx + i * 128;
        int b  = s >> 6;
        int k4 = s & 63;
        float4 v = *(const float4*)&g_att[b * DIM + k0 + k4 * 4];
        *(float4*)&xs[b * KC + k4 * 4] = v;
    }
    __syncthreads();

    const int q  = tx & 31;
    const int g  = tx >> 5;
    const int b0 = g * 8;
    const int gcol = bx * 128 + q * 4;
    const float* wp = wo + (size_t)k0 * DIM + gcol;

    float acc[8][4];
    #pragma unroll
    for (int i = 0; i < 8; i++)
        #pragma unroll
        for (int j = 0; j < 4; j++) acc[i][j] = 0.f;

    for (int kk = 0; kk < KC; kk += 4) {
        float xv[8][4];
        #pragma unroll
        for (int i = 0; i < 8; i++) {
            float4 t4 = *(const float4*)&xs[(b0 + i) * KC + kk];
            xv[i][0] = t4.x; xv[i][1] = t4.y; xv[i][2] = t4.z; xv[i][3] = t4.w;
        }
        #pragma unroll
        for (int j = 0; j < 4; j++) {
            float4 w4 = *(const float4*)&wp[(size_t)(kk + j) * DIM];
            #pragma unroll
            for (int i = 0; i < 8; i++) {
                acc[i][0] = fmaf(xv[i][j], w4.x, acc[i][0]);
                acc[i][1] = fmaf(xv[i][j], w4.y, acc[i][1]);
                acc[i][2] = fmaf(xv[i][j], w4.z, acc[i][2]);
                acc[i][3] = fmaf(xv[i][j], w4.w, acc[i][3]);
            }
        }
    }

    #pragma unroll
    for (int i = 0; i < 8; i++) {
        float4 r = make_float4(acc[i][0], acc[i][1], acc[i][2], acc[i][3]);
        *(float4*)&g_opart[((size_t)by * BATCH + b0 + i) * DIM + gcol] = r;
    }
}

// ---------------------------------------------------------------------------
// Kernel E: reduce O partials -> d_out
// ---------------------------------------------------------------------------
__global__ __launch_bounds__(256)
void o_reduce(float* __restrict__ out)
{
    int idx = blockIdx.x * 256 + threadIdx.x;   // 0 .. 131071
    float v = 0.f;
    #pragma unroll
    for (int c = 0; c < NCH; c++)
        v += g_opart[(size_t)c * (BATCH * DIM) + idx];
    out[idx] = v;
}

// ---------------------------------------------------------------------------
extern "C" void kernel_launch(void* const* d_in, const int* in_sizes, int n_in,
                              void* d_out, int out_size)
{
    const float* x        = (const float*)d_in[0];
    const float* cache_k  = (const float*)d_in[1];
    const float* cache_v  = (const float*)d_in[2];
    const float* fcos     = (const float*)d_in[3];
    const float* fsin     = (const float*)d_in[4];
    const float* wq       = (const float*)d_in[5];
    const float* wk       = (const float*)d_in[6];
    const float* wv       = (const float*)d_in[7];
    const float* wo       = (const float*)d_in[8];
    const int*   sp       = (const int*)d_in[9];
    float* out            = (float*)d_out;

    qkv_gemm<<<dim3(48, 16), 128>>>(x, wq, wk, wv);
    rope_reduce<<<(BATCH * (NQKV / 2)) / 256, 256>>>(fcos, fsin);
    attention<<<dim3(NKV, BATCH, NSPLIT), 256>>>(cache_k, cache_v, sp);
    att_merge<<<BATCH * NKV, 512>>>();
    o_gemm<<<dim3(32, 16), 128>>>(wo);
    o_reduce<<<(BATCH * DIM) / 256, 256>>>(out);
}

// round 3
// speedup vs baseline: 1.0070x; 1.0070x over previous
#include <cuda_runtime.h>
#include <cuda_bf16.h>
#include <math.h>

// Problem constants (fixed by the dataset)
#define BATCH   32
#define DIM     4096
#define NH      32
#define NKV     8
#define HD      128
#define NREP    4          // NH / NKV
#define MAXSEQ  4096
#define NQKV    6144       // 4096 (q) + 1024 (k) + 1024 (v)
#define KC      256        // k-chunk for split-K GEMMs
#define NCH     16         // 4096 / KC
#define NSPLIT  8          // KV splits in attention
#define TSPLIT  512        // MAXSEQ / NSPLIT
#define TILE    64         // tokens per smem tile
#define KPAD    132        // padded row stride (floats) for K/q smem

// Scratch (device globals; no allocation allowed)
__device__ float g_part [NCH * BATCH * NQKV];   // QKV split-K partials
__device__ float g_q    [BATCH * NH * HD];      // rope'd q
__device__ float g_k    [BATCH * NKV * HD];     // rope'd new k
__device__ float g_v    [BATCH * NKV * HD];     // new v
__device__ float g_att  [BATCH * NH * HD];      // attention output
__device__ float g_opart[NCH * BATCH * DIM];    // O-proj split-K partials
// Attention split-KV partials
__device__ float g_pm  [BATCH * NKV * NSPLIT * NREP];
__device__ float g_pl  [BATCH * NKV * NSPLIT * NREP];
__device__ float g_pacc[BATCH * NKV * NSPLIT * NREP * HD];

// ---------------------------------------------------------------------------
// Kernel A: QKV projection, split-K. grid (48,16), block 128.
// ---------------------------------------------------------------------------
__global__ __launch_bounds__(128)
void qkv_gemm(const float* __restrict__ x,
              const float* __restrict__ wq,
              const float* __restrict__ wk,
              const float* __restrict__ wv)
{
    __shared__ float xs[BATCH * KC];   // 32 KB
    const int tx = threadIdx.x;
    const int bx = blockIdx.x;
    const int by = blockIdx.y;
    const int k0 = by * KC;

    #pragma unroll
    for (int i = 0; i < 16; i++) {
        int s  = tx + i * 128;
        int b  = s >> 6;
        int k4 = s & 63;
        float4 v = *(const float4*)&x[b * DIM + k0 + k4 * 4];
        *(float4*)&xs[b * KC + k4 * 4] = v;
    }
    __syncthreads();

    const int q  = tx & 31;
    const int g  = tx >> 5;
    const int b0 = g * 8;
    const int gcol = bx * 128 + q * 4;

    const float* w; int ncols; int wcol;
    if (gcol < 4096)      { w = wq; ncols = 4096; wcol = gcol; }
    else if (gcol < 5120) { w = wk; ncols = 1024; wcol = gcol - 4096; }
    else                  { w = wv; ncols = 1024; wcol = gcol - 5120; }
    const float* wp = w + (size_t)k0 * ncols + wcol;

    float acc[8][4];
    #pragma unroll
    for (int i = 0; i < 8; i++)
        #pragma unroll
        for (int j = 0; j < 4; j++) acc[i][j] = 0.f;

    for (int kk = 0; kk < KC; kk += 4) {
        float xv[8][4];
        #pragma unroll
        for (int i = 0; i < 8; i++) {
            float4 t4 = *(const float4*)&xs[(b0 + i) * KC + kk];
            xv[i][0] = t4.x; xv[i][1] = t4.y; xv[i][2] = t4.z; xv[i][3] = t4.w;
        }
        #pragma unroll
        for (int j = 0; j < 4; j++) {
            float4 w4 = *(const float4*)&wp[(size_t)(kk + j) * ncols];
            #pragma unroll
            for (int i = 0; i < 8; i++) {
                acc[i][0] = fmaf(xv[i][j], w4.x, acc[i][0]);
                acc[i][1] = fmaf(xv[i][j], w4.y, acc[i][1]);
                acc[i][2] = fmaf(xv[i][j], w4.z, acc[i][2]);
                acc[i][3] = fmaf(xv[i][j], w4.w, acc[i][3]);
            }
        }
    }

    #pragma unroll
    for (int i = 0; i < 8; i++) {
        float4 r = make_float4(acc[i][0], acc[i][1], acc[i][2], acc[i][3]);
        *(float4*)&g_part[((size_t)by * BATCH + b0 + i) * NQKV + gcol] = r;
    }
}

// ---------------------------------------------------------------------------
// Kernel B: reduce split-K partials + RoPE -> g_q, g_k, g_v.
// ---------------------------------------------------------------------------
__global__ __launch_bounds__(256)
void rope_reduce(const float* __restrict__ fcos, const float* __restrict__ fsin)
{
    int idx = blockIdx.x * 256 + threadIdx.x;
    int b = idx / (NQKV / 2);
    int p = idx % (NQKV / 2);
    int col = 2 * p;

    float v0 = 0.f, v1 = 0.f;
    #pragma unroll
    for (int c = 0; c < NCH; c++) {
        float2 t = *(const float2*)&g_part[((size_t)c * BATCH + b) * NQKV + col];
        v0 += t.x; v1 += t.y;
    }

    if (col < 4096) {
        int d = col & (HD - 1);
        int dp = d >> 1;
        float c = fcos[dp], s = fsin[dp];
        g_q[b * 4096 + col]     = v0 * c - v1 * s;
        g_q[b * 4096 + col + 1] = v0 * s + v1 * c;
    } else if (col < 5120) {
        int cc = col - 4096;
        int d = cc & (HD - 1);
        int dp = d >> 1;
        float c = fcos[dp], s = fsin[dp];
        g_k[b * 1024 + cc]     = v0 * c - v1 * s;
        g_k[b * 1024 + cc + 1] = v0 * s + v1 * c;
    } else {
        int cc = col - 5120;
        g_v[b * 1024 + cc]     = v0;
        g_v[b * 1024 + cc + 1] = v1;
    }
}

// ---------------------------------------------------------------------------
// Kernel C: flash-decode GQA attention, smem-tiled, no per-token shuffles.
// grid (NKV, BATCH, NSPLIT), block 256 (8 warps). Tile = 64 tokens.
// Score phase: thread = (token, dim-quarter) reading K from smem.
// V phase:     lane = dim-quad, warp strides tokens; p broadcast from smem.
// ---------------------------------------------------------------------------
__global__ __launch_bounds__(256)
void attention(const float* __restrict__ cache_k,
               const float* __restrict__ cache_v,
               const int* __restrict__ start_pos)
{
    __shared__ float ksm[TILE * KPAD];        // 33792 B (reused for acc merge)
    __shared__ float qsm[4 * KPAD];           // 2112 B
    __shared__ float ssm[4 * TILE * 5];       // 5120 B  (padded stride 5)
    __shared__ float psm[TILE * 4];           // 1024 B
    __shared__ float wred[2][4];
    __shared__ float wsum[2][4];
    __shared__ float Msm[4], Lsm[4], Asm[4];

    const int hh  = blockIdx.x;               // kv head
    const int b   = blockIdx.y;
    const int spl = blockIdx.z;
    const int tx  = threadIdx.x;
    const int w   = tx >> 5;
    const int l   = tx & 31;

    const int sp = *start_pos;                // 4095
    const int t0 = spl * TSPLIT;

    // load q (scaled) into smem: 4 heads x 128 dims
    const float qscale = 1.4426950408889634f * 0.08838834764831845f;
    #pragma unroll
    for (int r = 0; r < 2; r++) {
        int o = tx + r * 256;                 // 0..511
        int h = o >> 7, d = o & (HD - 1);
        qsm[h * KPAD + d] = g_q[b * 4096 + (hh * NREP + h) * HD + d] * qscale;
    }
    if (tx < 4) { Msm[tx] = -1e30f; Lsm[tx] = 0.f; }

    float acc[NREP][4];
    #pragma unroll
    for (int qi = 0; qi < NREP; qi++)
        #pragma unroll
        for (int j = 0; j < 4; j++) acc[qi][j] = 0.f;

    const size_t kv_bh = (size_t)b * MAXSEQ * NKV * HD + hh * HD;

    for (int tile = 0; tile < TSPLIT / TILE; tile++) {
        const int tbase = t0 + tile * TILE;
        __syncthreads();   // protect ksm/psm from previous iteration's readers

        // ---- stage K tile (coalesced) ----
        #pragma unroll
        for (int i = 0; i < 8; i++) {
            int s   = tx + i * 256;           // 0..2047
            int row = s >> 5;
            int ch  = s & 31;
            int tg  = tbase + row;
            const float* src = (tg == sp) ? &g_k[(b * NKV + hh) * HD]
                                          : &cache_k[kv_bh + (size_t)tg * (NKV * HD)];
            float4 v = (tg <= sp) ? *(const float4*)&src[ch * 4]
                                  : make_float4(0.f, 0.f, 0.f, 0.f);
            *(float4*)&ksm[row * KPAD + ch * 4] = v;
        }
        __syncthreads();

        // ---- score phase: thread = (token, quarter) ----
        {
            const int token = tx & 63;
            const int qr    = tx >> 6;        // 0..3, 32 dims each
            float s0 = 0.f, s1 = 0.f, s2 = 0.f, s3 = 0.f;
            #pragma unroll
            for (int c = 0; c < 8; c++) {
                int ch = qr * 8 + c;
                float4 k4 = *(const float4*)&ksm[token * KPAD + ch * 4];
                float4 q0 = *(const float4*)&qsm[0 * KPAD + ch * 4];
                float4 q1 = *(const float4*)&qsm[1 * KPAD + ch * 4];
                float4 q2 = *(const float4*)&qsm[2 * KPAD + ch * 4];
                float4 q3 = *(const float4*)&qsm[3 * KPAD + ch * 4];
                s0 += k4.x*q0.x + k4.y*q0.y + k4.z*q0.z + k4.w*q0.w;
                s1 += k4.x*q1.x + k4.y*q1.y + k4.z*q1.z + k4.w*q1.w;
                s2 += k4.x*q2.x + k4.y*q2.y + k4.z*q2.z + k4.w*q2.w;
                s3 += k4.x*q3.x + k4.y*q3.y + k4.z*q3.z + k4.w*q3.w;
            }
            ssm[qr * (TILE * 5) + token * 5 + 0] = s0;
            ssm[qr * (TILE * 5) + token * 5 + 1] = s1;
            ssm[qr * (TILE * 5) + token * 5 + 2] = s2;
            ssm[qr * (TILE * 5) + token * 5 + 3] = s3;
        }
        __syncthreads();

        // ---- R1: combine quarters, per-head tile max (warp = (head, 32-grp)) ----
        const int rh = w & 3;                 // head
        const int rg = w >> 2;                // token group
        const int rt = rg * 32 + l;           // token in tile
        float stot = ssm[0 * (TILE*5) + rt * 5 + rh]
                   + ssm[1 * (TILE*5) + rt * 5 + rh]
                   + ssm[2 * (TILE*5) + rt * 5 + rh]
                   + ssm[3 * (TILE*5) + rt * 5 + rh];
        if (tbase + rt > sp) stot = -1e30f;
        {
            float mloc = stot;
            #pragma unroll
            for (int off = 16; off > 0; off >>= 1)
                mloc = fmaxf(mloc, __shfl_xor_sync(0xffffffffu, mloc, off));
            if (l == 0) wred[rg][rh] = mloc;
        }
        __syncthreads();

        // ---- R2: update running max, compute alpha ----
        if (tx < 4) {
            float mt = fmaxf(wred[0][tx], wred[1][tx]);
            float Mn = fmaxf(Msm[tx], mt);
            Asm[tx] = exp2f(Msm[tx] - Mn);
            Msm[tx] = Mn;
        }
        __syncthreads();

        // ---- R3: p = exp2(s - M), per-head tile sum ----
        {
            float p = exp2f(stot - Msm[rh]);
            psm[rt * 4 + rh] = p;
            #pragma unroll
            for (int off = 16; off > 0; off >>= 1)
                p += __shfl_xor_sync(0xffffffffu, p, off);
            if (l == 0) wsum[rg][rh] = p;
        }
        __syncthreads();

        // ---- V phase prologue: update lsum; rescale acc ----
        if (tx < 4) Lsm[tx] = Lsm[tx] * Asm[tx] + wsum[0][tx] + wsum[1][tx];
        {
            float a0 = Asm[0], a1 = Asm[1], a2 = Asm[2], a3 = Asm[3];
            #pragma unroll
            for (int j = 0; j < 4; j++) {
                acc[0][j] *= a0; acc[1][j] *= a1;
                acc[2][j] *= a2; acc[3][j] *= a3;
            }
        }

        // ---- V phase: warp strides tokens, lane = dim-quad ----
        const size_t vlane = kv_bh + l * 4;
        #pragma unroll 2
        for (int i = 0; i < TILE / 8; i++) {
            int tt = w + i * 8;
            int tg = tbase + tt;
            const float* vp = (tg == sp) ? &g_v[(b * NKV + hh) * HD + l * 4]
                                         : &cache_v[vlane + (size_t)tg * (NKV * HD)];
            float4 v4 = *(const float4*)vp;
            float4 p4 = *(const float4*)&psm[tt * 4];
            acc[0][0] += p4.x*v4.x; acc[0][1] += p4.x*v4.y; acc[0][2] += p4.x*v4.z; acc[0][3] += p4.x*v4.w;
            acc[1][0] += p4.y*v4.x; acc[1][1] += p4.y*v4.y; acc[1][2] += p4.y*v4.z; acc[1][3] += p4.y*v4.w;
            acc[2][0] += p4.z*v4.x; acc[2][1] += p4.z*v4.y; acc[2][2] += p4.z*v4.z; acc[2][3] += p4.z*v4.w;
            acc[3][0] += p4.w*v4.x; acc[3][1] += p4.w*v4.y; acc[3][2] += p4.w*v4.z; acc[3][3] += p4.w*v4.w;
        }
    }

    // ---- merge 8 warp accs (reuse ksm; stride 132 keeps float4 alignment) ----
    __syncthreads();
    #pragma unroll
    for (int qi = 0; qi < NREP; qi++)
        *(float4*)&ksm[w * 528 + qi * 132 + l * 4] =
            make_float4(acc[qi][0], acc[qi][1], acc[qi][2], acc[qi][3]);
    __syncthreads();

    #pragma unroll
    for (int r = 0; r < 2; r++) {
        int o  = tx + r * 256;                // 0..511
        int qi = o >> 7;
        int d  = o & (HD - 1);
        float num = 0.f;
        #pragma unroll
        for (int w2 = 0; w2 < 8; w2++) num += ksm[w2 * 528 + qi * 132 + d];
        int pbase = ((b * NKV + hh) * NSPLIT + spl) * NREP + qi;
        g_pacc[(size_t)pbase * HD + d] = num;
        if (d == 0) { g_pl[pbase] = Lsm[qi]; g_pm[pbase] = Msm[qi]; }
    }
}

// ---------------------------------------------------------------------------
// Kernel C2: merge the NSPLIT partials -> g_att. grid 256, block 512.
// ---------------------------------------------------------------------------
__global__ __launch_bounds__(512)
void att_merge()
{
    const int bh = blockIdx.x;
    const int o  = threadIdx.x;
    const int qi = o >> 7;
    const int d  = o & (HD - 1);
    const int base = bh * NSPLIT * NREP + qi;

    float M = -1e30f;
    #pragma unroll
    for (int s = 0; s < NSPLIT; s++) M = fmaxf(M, g_pm[base + s * NREP]);
    float num = 0.f, den = 0.f;
    #pragma unroll
    for (int s = 0; s < NSPLIT; s++) {
        int p = base + s * NREP;
        float wgt = exp2f(g_pm[p] - M);
        num += wgt * g_pacc[(size_t)p * HD + d];
        den += wgt * g_pl[p];
    }
    const int b = bh >> 3, h = bh & 7;
    g_att[b * 4096 + (h * NREP + qi) * HD + d] = num / den;
}

// ---------------------------------------------------------------------------
// Kernel D: output projection, split-K. grid (32,16), block 128.
// ---------------------------------------------------------------------------
__global__ __launch_bounds__(128)
void o_gemm(const float* __restrict__ wo)
{
    __shared__ float xs[BATCH * KC];
    const int tx = threadIdx.x;
    const int bx = blockIdx.x;
    const int by = blockIdx.y;
    const int k0 = by * KC;

    #pragma unroll
    for (int i = 0; i < 16; i++) {
        int s  = tx + i * 128;
        int b  = s >> 6;
        int k4 = s & 63;
        float4 v = *(const float4*)&g_att[b * DIM + k0 + k4 * 4];
        *(float4*)&xs[b * KC + k4 * 4] = v;
    }
    __syncthreads();

    const int q  = tx & 31;
    const int g  = tx >> 5;
    const int b0 = g * 8;
    const int gcol = bx * 128 + q * 4;
    const float* wp = wo + (size_t)k0 * DIM + gcol;

    float acc[8][4];
    #pragma unroll
    for (int i = 0; i < 8; i++)
        #pragma unroll
        for (int j = 0; j < 4; j++) acc[i][j] = 0.f;

    for (int kk = 0; kk < KC; kk += 4) {
        float xv[8][4];
        #pragma unroll
        for (int i = 0; i < 8; i++) {
            float4 t4 = *(const float4*)&xs[(b0 + i) * KC + kk];
            xv[i][0] = t4.x; xv[i][1] = t4.y; xv[i][2] = t4.z; xv[i][3] = t4.w;
        }
        #pragma unroll
        for (int j = 0; j < 4; j++) {
            float4 w4 = *(const float4*)&wp[(size_t)(kk + j) * DIM];
            #pragma unroll
            for (int i = 0; i < 8; i++) {
                acc[i][0] = fmaf(xv[i][j], w4.x, acc[i][0]);
                acc[i][1] = fmaf(xv[i][j], w4.y, acc[i][1]);
                acc[i][2] = fmaf(xv[i][j], w4.z, acc[i][2]);
                acc[i][3] = fmaf(xv[i][j], w4.w, acc[i][3]);
            }
        }
    }

    #pragma unroll
    for (int i = 0; i < 8; i++) {
        float4 r = make_float4(acc[i][0], acc[i][1], acc[i][2], acc[i][3]);
        *(float4*)&g_opart[((size_t)by * BATCH + b0 + i) * DIM + gcol] = r;
    }
}

// ---------------------------------------------------------------------------
// Kernel E: reduce O partials -> d_out
// ---------------------------------------------------------------------------
__global__ __launch_bounds__(256)
void o_reduce(float* __restrict__ out)
{
    int idx = blockIdx.x * 256 + threadIdx.x;
    float v = 0.f;
    #pragma unroll
    for (int c = 0; c < NCH; c++)
        v += g_opart[(size_t)c * (BATCH * DIM) + idx];
    out[idx] = v;
}

// ---------------------------------------------------------------------------
extern "C" void kernel_launch(void* const* d_in, const int* in_sizes, int n_in,
                              void* d_out, int out_size)
{
    const float* x        = (const float*)d_in[0];
    const float* cache_k  = (const float*)d_in[1];
    const float* cache_v  = (const float*)d_in[2];
    const float* fcos     = (const float*)d_in[3];
    const float* fsin     = (const float*)d_in[4];
    const float* wq       = (const float*)d_in[5];
    const float* wk       = (const float*)d_in[6];
    const float* wv       = (const float*)d_in[7];
    const float* wo       = (const float*)d_in[8];
    const int*   sp       = (const int*)d_in[9];
    float* out            = (float*)d_out;

    qkv_gemm<<<dim3(48, 16), 128>>>(x, wq, wk, wv);
    rope_reduce<<<(BATCH * (NQKV / 2)) / 256, 256>>>(fcos, fsin);
    attention<<<dim3(NKV, BATCH, NSPLIT), 256>>>(cache_k, cache_v, sp);
    att_merge<<<BATCH * NKV, 512>>>();
    o_gemm<<<dim3(32, 16), 128>>>(wo);
    o_reduce<<<(BATCH * DIM) / 256, 256>>>(out);
}

// round 4
// speedup vs baseline: 1.1324x; 1.1246x over previous
#include <cuda_runtime.h>
#include <cuda_bf16.h>
#include <math.h>

// Problem constants (fixed by the dataset)
#define BATCH   32
#define DIM     4096
#define NH      32
#define NKV     8
#define HD      128
#define NREP    4          // NH / NKV
#define MAXSEQ  4096
#define NQKV    6144       // 4096 (q) + 1024 (k) + 1024 (v)
#define KC      256        // k-chunk for split-K GEMMs
#define NCH     16         // 4096 / KC
#define NSPLIT  8          // KV splits in attention
#define TSPLIT  512        // MAXSEQ / NSPLIT
#define NCHUNK  16         // TSPLIT / 32 token-chunks per split

// Scratch (device globals; no allocation allowed)
__device__ float g_part [NCH * BATCH * NQKV];   // QKV split-K partials
__device__ float g_q    [BATCH * NH * HD];      // rope'd q
__device__ float g_k    [BATCH * NKV * HD];     // rope'd new k
__device__ float g_v    [BATCH * NKV * HD];     // new v
__device__ float g_att  [BATCH * NH * HD];      // attention output
__device__ float g_opart[NCH * BATCH * DIM];    // O-proj split-K partials
// Attention split-KV partials
__device__ float g_pm  [BATCH * NKV * NSPLIT * NREP];
__device__ float g_pl  [BATCH * NKV * NSPLIT * NREP];
__device__ float g_pacc[BATCH * NKV * NSPLIT * NREP * HD];

// ---------------------------------------------------------------------------
// Kernel A: QKV projection, split-K. grid (48,16), block 128.
// ---------------------------------------------------------------------------
__global__ __launch_bounds__(128)
void qkv_gemm(const float* __restrict__ x,
              const float* __restrict__ wq,
              const float* __restrict__ wk,
              const float* __restrict__ wv)
{
    __shared__ float xs[BATCH * KC];   // 32 KB
    const int tx = threadIdx.x;
    const int bx = blockIdx.x;
    const int by = blockIdx.y;
    const int k0 = by * KC;

    #pragma unroll
    for (int i = 0; i < 16; i++) {
        int s  = tx + i * 128;
        int b  = s >> 6;
        int k4 = s & 63;
        float4 v = *(const float4*)&x[b * DIM + k0 + k4 * 4];
        *(float4*)&xs[b * KC + k4 * 4] = v;
    }
    __syncthreads();

    const int q  = tx & 31;
    const int g  = tx >> 5;
    const int b0 = g * 8;
    const int gcol = bx * 128 + q * 4;

    const float* w; int ncols; int wcol;
    if (gcol < 4096)      { w = wq; ncols = 4096; wcol = gcol; }
    else if (gcol < 5120) { w = wk; ncols = 1024; wcol = gcol - 4096; }
    else                  { w = wv; ncols = 1024; wcol = gcol - 5120; }
    const float* wp = w + (size_t)k0 * ncols + wcol;

    float acc[8][4];
    #pragma unroll
    for (int i = 0; i < 8; i++)
        #pragma unroll
        for (int j = 0; j < 4; j++) acc[i][j] = 0.f;

    for (int kk = 0; kk < KC; kk += 4) {
        float xv[8][4];
        #pragma unroll
        for (int i = 0; i < 8; i++) {
            float4 t4 = *(const float4*)&xs[(b0 + i) * KC + kk];
            xv[i][0] = t4.x; xv[i][1] = t4.y; xv[i][2] = t4.z; xv[i][3] = t4.w;
        }
        #pragma unroll
        for (int j = 0; j < 4; j++) {
            float4 w4 = *(const float4*)&wp[(size_t)(kk + j) * ncols];
            #pragma unroll
            for (int i = 0; i < 8; i++) {
                acc[i][0] = fmaf(xv[i][j], w4.x, acc[i][0]);
                acc[i][1] = fmaf(xv[i][j], w4.y, acc[i][1]);
                acc[i][2] = fmaf(xv[i][j], w4.z, acc[i][2]);
                acc[i][3] = fmaf(xv[i][j], w4.w, acc[i][3]);
            }
        }
    }

    #pragma unroll
    for (int i = 0; i < 8; i++) {
        float4 r = make_float4(acc[i][0], acc[i][1], acc[i][2], acc[i][3]);
        *(float4*)&g_part[((size_t)by * BATCH + b0 + i) * NQKV + gcol] = r;
    }
}

// ---------------------------------------------------------------------------
// Kernel B: reduce split-K partials + RoPE -> g_q, g_k, g_v.
// ---------------------------------------------------------------------------
__global__ __launch_bounds__(256)
void rope_reduce(const float* __restrict__ fcos, const float* __restrict__ fsin)
{
    int idx = blockIdx.x * 256 + threadIdx.x;
    int b = idx / (NQKV / 2);
    int p = idx % (NQKV / 2);
    int col = 2 * p;

    float v0 = 0.f, v1 = 0.f;
    #pragma unroll
    for (int c = 0; c < NCH; c++) {
        float2 t = *(const float2*)&g_part[((size_t)c * BATCH + b) * NQKV + col];
        v0 += t.x; v1 += t.y;
    }

    if (col < 4096) {
        int d = col & (HD - 1);
        int dp = d >> 1;
        float c = fcos[dp], s = fsin[dp];
        g_q[b * 4096 + col]     = v0 * c - v1 * s;
        g_q[b * 4096 + col + 1] = v0 * s + v1 * c;
    } else if (col < 5120) {
        int cc = col - 4096;
        int d = cc & (HD - 1);
        int dp = d >> 1;
        float c = fcos[dp], s = fsin[dp];
        g_k[b * 1024 + cc]     = v0 * c - v1 * s;
        g_k[b * 1024 + cc + 1] = v0 * s + v1 * c;
    } else {
        int cc = col - 5120;
        g_v[b * 1024 + cc]     = v0;
        g_v[b * 1024 + cc + 1] = v1;
    }
}

// ---------------------------------------------------------------------------
// Kernel C: warp-autonomous flash-decode GQA attention.
// grid (NKV, BATCH, NSPLIT), block 256 (8 warps). No block barriers in the
// main loop. Score phase: lane = token (q via smem broadcast). V phase:
// lane = dim-quad (p via warp-private smem broadcast).
// ---------------------------------------------------------------------------
__global__ __launch_bounds__(256)
void attention(const float* __restrict__ cache_k,
               const float* __restrict__ cache_v,
               const int* __restrict__ start_pos)
{
    __shared__ float qsm[4 * HD];             // 2 KB
    __shared__ float psm[8][128];             // 4 KB, warp-private slots
    __shared__ float accsm[8][NREP][HD];      // 16 KB
    __shared__ float msm[8][NREP], lsm[8][NREP];

    const int hh  = blockIdx.x;               // kv head
    const int b   = blockIdx.y;
    const int spl = blockIdx.z;
    const int tx  = threadIdx.x;
    const int w   = tx >> 5;
    const int l   = tx & 31;

    const int sp = *start_pos;                // 4095
    const int t0 = spl * TSPLIT;

    // q (pre-scaled by log2e/sqrt(HD)) into smem
    const float qscale = 1.4426950408889634f * 0.08838834764831845f;
    #pragma unroll
    for (int r = 0; r < 2; r++) {
        int o = tx + r * 256;
        qsm[o] = g_q[b * 4096 + (hh * NREP) * HD + o] * qscale;
    }
    __syncthreads();

    float m0 = -1e30f, m1 = -1e30f, m2 = -1e30f, m3 = -1e30f;
    float ls0 = 0.f, ls1 = 0.f, ls2 = 0.f, ls3 = 0.f;   // lane-local partials
    float acc[NREP][4];
    #pragma unroll
    for (int qi = 0; qi < NREP; qi++)
        #pragma unroll
        for (int j = 0; j < 4; j++) acc[qi][j] = 0.f;

    const size_t kv_bh = (size_t)b * MAXSEQ * NKV * HD + hh * HD;
    const float* gk = &g_k[(b * NKV + hh) * HD];
    const float* gv = &g_v[(b * NKV + hh) * HD];

    for (int c = w; c < NCHUNK; c += 8) {
        const int tb = t0 + c * 32;
        const int t  = tb + l;

        // ---- score: lane = token, stream own K row, q broadcast from smem ----
        const float* krow = (t == sp) ? gk
                                      : cache_k + kv_bh + (size_t)t * (NKV * HD);
        float s0 = 0.f, s1 = 0.f, s2 = 0.f, s3 = 0.f;
        #pragma unroll 8
        for (int ch = 0; ch < 32; ch++) {
            float4 k4 = *(const float4*)&krow[ch * 4];
            float4 q0 = *(const float4*)&qsm[0 * HD + ch * 4];
            float4 q1 = *(const float4*)&qsm[1 * HD + ch * 4];
            float4 q2 = *(const float4*)&qsm[2 * HD + ch * 4];
            float4 q3 = *(const float4*)&qsm[3 * HD + ch * 4];
            s0 += k4.x*q0.x + k4.y*q0.y + k4.z*q0.z + k4.w*q0.w;
            s1 += k4.x*q1.x + k4.y*q1.y + k4.z*q1.z + k4.w*q1.w;
            s2 += k4.x*q2.x + k4.y*q2.y + k4.z*q2.z + k4.w*q2.w;
            s3 += k4.x*q3.x + k4.y*q3.y + k4.z*q3.z + k4.w*q3.w;
        }

        // ---- per-head chunk max (butterfly), online rescale ----
        float c0 = s0, c1 = s1, c2 = s2, c3 = s3;
        #pragma unroll
        for (int off = 16; off > 0; off >>= 1) {
            c0 = fmaxf(c0, __shfl_xor_sync(0xffffffffu, c0, off));
            c1 = fmaxf(c1, __shfl_xor_sync(0xffffffffu, c1, off));
            c2 = fmaxf(c2, __shfl_xor_sync(0xffffffffu, c2, off));
            c3 = fmaxf(c3, __shfl_xor_sync(0xffffffffu, c3, off));
        }
        if (c0 > m0) { float a = exp2f(m0 - c0); ls0 *= a;
            acc[0][0]*=a; acc[0][1]*=a; acc[0][2]*=a; acc[0][3]*=a; m0 = c0; }
        if (c1 > m1) { float a = exp2f(m1 - c1); ls1 *= a;
            acc[1][0]*=a; acc[1][1]*=a; acc[1][2]*=a; acc[1][3]*=a; m1 = c1; }
        if (c2 > m2) { float a = exp2f(m2 - c2); ls2 *= a;
            acc[2][0]*=a; acc[2][1]*=a; acc[2][2]*=a; acc[2][3]*=a; m2 = c2; }
        if (c3 > m3) { float a = exp2f(m3 - c3); ls3 *= a;
            acc[3][0]*=a; acc[3][1]*=a; acc[3][2]*=a; acc[3][3]*=a; m3 = c3; }

        float p0 = exp2f(s0 - m0), p1 = exp2f(s1 - m1);
        float p2 = exp2f(s2 - m2), p3 = exp2f(s3 - m3);
        ls0 += p0; ls1 += p1; ls2 += p2; ls3 += p3;

        *(float4*)&psm[w][l * 4] = make_float4(p0, p1, p2, p3);
        __syncwarp();

        // ---- V: lane = dim-quad, warp strides tokens; p broadcast ----
        const float* vlane = cache_v + kv_bh + l * 4;
        #pragma unroll 8
        for (int tt = 0; tt < 32; tt++) {
            int t2 = tb + tt;
            const float* vp = (t2 == sp) ? gv + l * 4
                                         : vlane + (size_t)t2 * (NKV * HD);
            float4 v4 = *(const float4*)vp;
            float4 p4 = *(const float4*)&psm[w][tt * 4];
            acc[0][0] += p4.x*v4.x; acc[0][1] += p4.x*v4.y; acc[0][2] += p4.x*v4.z; acc[0][3] += p4.x*v4.w;
            acc[1][0] += p4.y*v4.x; acc[1][1] += p4.y*v4.y; acc[1][2] += p4.y*v4.z; acc[1][3] += p4.y*v4.w;
            acc[2][0] += p4.z*v4.x; acc[2][1] += p4.z*v4.y; acc[2][2] += p4.z*v4.z; acc[2][3] += p4.z*v4.w;
            acc[3][0] += p4.w*v4.x; acc[3][1] += p4.w*v4.y; acc[3][2] += p4.w*v4.z; acc[3][3] += p4.w*v4.w;
        }
        __syncwarp();
    }

    // ---- lane-reduce lsums (butterfly add) ----
    #pragma unroll
    for (int off = 16; off > 0; off >>= 1) {
        ls0 += __shfl_xor_sync(0xffffffffu, ls0, off);
        ls1 += __shfl_xor_sync(0xffffffffu, ls1, off);
        ls2 += __shfl_xor_sync(0xffffffffu, ls2, off);
        ls3 += __shfl_xor_sync(0xffffffffu, ls3, off);
    }

    // ---- store warp partials ----
    #pragma unroll
    for (int qi = 0; qi < NREP; qi++)
        *(float4*)&accsm[w][qi][l * 4] =
            make_float4(acc[qi][0], acc[qi][1], acc[qi][2], acc[qi][3]);
    if (l == 0) {
        msm[w][0] = m0; msm[w][1] = m1; msm[w][2] = m2; msm[w][3] = m3;
        lsm[w][0] = ls0; lsm[w][1] = ls1; lsm[w][2] = ls2; lsm[w][3] = ls3;
    }
    __syncthreads();

    // ---- block merge across 8 warps ----
    #pragma unroll
    for (int r = 0; r < 2; r++) {
        int o  = tx + r * 256;                // 0..511
        int qi = o >> 7;
        int d  = o & (HD - 1);
        float M = msm[0][qi];
        #pragma unroll
        for (int w2 = 1; w2 < 8; w2++) M = fmaxf(M, msm[w2][qi]);
        float num = 0.f, den = 0.f;
        #pragma unroll
        for (int w2 = 0; w2 < 8; w2++) {
            float wgt = exp2f(msm[w2][qi] - M);
            num += wgt * accsm[w2][qi][d];
            den += wgt * lsm[w2][qi];
        }
        int pbase = ((b * NKV + hh) * NSPLIT + spl) * NREP + qi;
        g_pacc[(size_t)pbase * HD + d] = num;
        if (d == 0) { g_pl[pbase] = den; g_pm[pbase] = M; }
    }
}

// ---------------------------------------------------------------------------
// Kernel C2: merge the NSPLIT partials -> g_att. grid 256, block 512.
// ---------------------------------------------------------------------------
__global__ __launch_bounds__(512)
void att_merge()
{
    const int bh = blockIdx.x;
    const int o  = threadIdx.x;
    const int qi = o >> 7;
    const int d  = o & (HD - 1);
    const int base = bh * NSPLIT * NREP + qi;

    float M = -1e30f;
    #pragma unroll
    for (int s = 0; s < NSPLIT; s++) M = fmaxf(M, g_pm[base + s * NREP]);
    float num = 0.f, den = 0.f;
    #pragma unroll
    for (int s = 0; s < NSPLIT; s++) {
        int p = base + s * NREP;
        float wgt = exp2f(g_pm[p] - M);
        num += wgt * g_pacc[(size_t)p * HD + d];
        den += wgt * g_pl[p];
    }
    const int b = bh >> 3, h = bh & 7;
    g_att[b * 4096 + (h * NREP + qi) * HD + d] = num / den;
}

// ---------------------------------------------------------------------------
// Kernel D: output projection, split-K. grid (32,16), block 128.
// ---------------------------------------------------------------------------
__global__ __launch_bounds__(128)
void o_gemm(const float* __restrict__ wo)
{
    __shared__ float xs[BATCH * KC];
    const int tx = threadIdx.x;
    const int bx = blockIdx.x;
    const int by = blockIdx.y;
    const int k0 = by * KC;

    #pragma unroll
    for (int i = 0; i < 16; i++) {
        int s  = tx + i * 128;
        int b  = s >> 6;
        int k4 = s & 63;
        float4 v = *(const float4*)&g_att[b * DIM + k0 + k4 * 4];
        *(float4*)&xs[b * KC + k4 * 4] = v;
    }
    __syncthreads();

    const int q  = tx & 31;
    const int g  = tx >> 5;
    const int b0 = g * 8;
    const int gcol = bx * 128 + q * 4;
    const float* wp = wo + (size_t)k0 * DIM + gcol;

    float acc[8][4];
    #pragma unroll
    for (int i = 0; i < 8; i++)
        #pragma unroll
        for (int j = 0; j < 4; j++) acc[i][j] = 0.f;

    for (int kk = 0; kk < KC; kk += 4) {
        float xv[8][4];
        #pragma unroll
        for (int i = 0; i < 8; i++) {
            float4 t4 = *(const float4*)&xs[(b0 + i) * KC + kk];
            xv[i][0] = t4.x; xv[i][1] = t4.y; xv[i][2] = t4.z; xv[i][3] = t4.w;
        }
        #pragma unroll
        for (int j = 0; j < 4; j++) {
            float4 w4 = *(const float4*)&wp[(size_t)(kk + j) * DIM];
            #pragma unroll
            for (int i = 0; i < 8; i++) {
                acc[i][0] = fmaf(xv[i][j], w4.x, acc[i][0]);
                acc[i][1] = fmaf(xv[i][j], w4.y, acc[i][1]);
                acc[i][2] = fmaf(xv[i][j], w4.z, acc[i][2]);
                acc[i][3] = fmaf(xv[i][j], w4.w, acc[i][3]);
            }
        }
    }

    #pragma unroll
    for (int i = 0; i < 8; i++) {
        float4 r = make_float4(acc[i][0], acc[i][1], acc[i][2], acc[i][3]);
        *(float4*)&g_opart[((size_t)by * BATCH + b0 + i) * DIM + gcol] = r;
    }
}

// ---------------------------------------------------------------------------
// Kernel E: reduce O partials -> d_out
// ---------------------------------------------------------------------------
__global__ __launch_bounds__(256)
void o_reduce(float* __restrict__ out)
{
    int idx = blockIdx.x * 256 + threadIdx.x;
    float v = 0.f;
    #pragma unroll
    for (int c = 0; c < NCH; c++)
        v += g_opart[(size_t)c * (BATCH * DIM) + idx];
    out[idx] = v;
}

// ---------------------------------------------------------------------------
extern "C" void kernel_launch(void* const* d_in, const int* in_sizes, int n_in,
                              void* d_out, int out_size)
{
    const float* x        = (const float*)d_in[0];
    const float* cache_k  = (const float*)d_in[1];
    const float* cache_v  = (const float*)d_in[2];
    const float* fcos     = (const float*)d_in[3];
    const float* fsin     = (const float*)d_in[4];
    const float* wq       = (const float*)d_in[5];
    const float* wk       = (const float*)d_in[6];
    const float* wv       = (const float*)d_in[7];
    const float* wo       = (const float*)d_in[8];
    const int*   sp       = (const int*)d_in[9];
    float* out            = (float*)d_out;

    qkv_gemm<<<dim3(48, 16), 128>>>(x, wq, wk, wv);
    rope_reduce<<<(BATCH * (NQKV / 2)) / 256, 256>>>(fcos, fsin);
    attention<<<dim3(NKV, BATCH, NSPLIT), 256>>>(cache_k, cache_v, sp);
    att_merge<<<BATCH * NKV, 512>>>();
    o_gemm<<<dim3(32, 16), 128>>>(wo);
    o_reduce<<<(BATCH * DIM) / 256, 256>>>(out);
}

// round 5
// speedup vs baseline: 1.2443x; 1.0988x over previous
#include <cuda_runtime.h>
#include <cuda_bf16.h>
#include <math.h>

// Problem constants (fixed by the dataset)
#define BATCH   32
#define DIM     4096
#define NH      32
#define NKV     8
#define HD      128
#define NREP    4          // NH / NKV
#define MAXSEQ  4096
#define NQKV    6144       // 4096 (q) + 1024 (k) + 1024 (v)
#define KC      256        // k-chunk for split-K GEMMs
#define NCH     16         // 4096 / KC
#define NSPLIT  8          // KV splits in attention
#define TSPLIT  512        // MAXSEQ / NSPLIT
#define CHT     16         // tokens per warp-chunk
#define NCHUNK  32         // TSPLIT / CHT

// Scratch (device globals; no allocation allowed)
__device__ float g_part [NCH * BATCH * NQKV];   // QKV split-K partials
__device__ float g_q    [BATCH * NH * HD];      // rope'd q
__device__ float g_k    [BATCH * NKV * HD];     // rope'd new k
__device__ float g_v    [BATCH * NKV * HD];     // new v
__device__ float g_att  [BATCH * NH * HD];      // attention output
__device__ float g_opart[NCH * BATCH * DIM];    // O-proj split-K partials
// Attention split-KV partials
__device__ float g_pm  [BATCH * NKV * NSPLIT * NREP];
__device__ float g_pl  [BATCH * NKV * NSPLIT * NREP];
__device__ float g_pacc[BATCH * NKV * NSPLIT * NREP * HD];

// ---------------------------------------------------------------------------
// Kernel A: QKV projection, split-K. grid (48,16), block 128.
// ---------------------------------------------------------------------------
__global__ __launch_bounds__(128)
void qkv_gemm(const float* __restrict__ x,
              const float* __restrict__ wq,
              const float* __restrict__ wk,
              const float* __restrict__ wv)
{
    __shared__ float xs[BATCH * KC];   // 32 KB
    const int tx = threadIdx.x;
    const int bx = blockIdx.x;
    const int by = blockIdx.y;
    const int k0 = by * KC;

    #pragma unroll
    for (int i = 0; i < 16; i++) {
        int s  = tx + i * 128;
        int b  = s >> 6;
        int k4 = s & 63;
        float4 v = *(const float4*)&x[b * DIM + k0 + k4 * 4];
        *(float4*)&xs[b * KC + k4 * 4] = v;
    }
    __syncthreads();

    const int q  = tx & 31;
    const int g  = tx >> 5;
    const int b0 = g * 8;
    const int gcol = bx * 128 + q * 4;

    const float* w; int ncols; int wcol;
    if (gcol < 4096)      { w = wq; ncols = 4096; wcol = gcol; }
    else if (gcol < 5120) { w = wk; ncols = 1024; wcol = gcol - 4096; }
    else                  { w = wv; ncols = 1024; wcol = gcol - 5120; }
    const float* wp = w + (size_t)k0 * ncols + wcol;

    float acc[8][4];
    #pragma unroll
    for (int i = 0; i < 8; i++)
        #pragma unroll
        for (int j = 0; j < 4; j++) acc[i][j] = 0.f;

    for (int kk = 0; kk < KC; kk += 4) {
        float xv[8][4];
        #pragma unroll
        for (int i = 0; i < 8; i++) {
            float4 t4 = *(const float4*)&xs[(b0 + i) * KC + kk];
            xv[i][0] = t4.x; xv[i][1] = t4.y; xv[i][2] = t4.z; xv[i][3] = t4.w;
        }
        #pragma unroll
        for (int j = 0; j < 4; j++) {
            float4 w4 = *(const float4*)&wp[(size_t)(kk + j) * ncols];
            #pragma unroll
            for (int i = 0; i < 8; i++) {
                acc[i][0] = fmaf(xv[i][j], w4.x, acc[i][0]);
                acc[i][1] = fmaf(xv[i][j], w4.y, acc[i][1]);
                acc[i][2] = fmaf(xv[i][j], w4.z, acc[i][2]);
                acc[i][3] = fmaf(xv[i][j], w4.w, acc[i][3]);
            }
        }
    }

    #pragma unroll
    for (int i = 0; i < 8; i++) {
        float4 r = make_float4(acc[i][0], acc[i][1], acc[i][2], acc[i][3]);
        *(float4*)&g_part[((size_t)by * BATCH + b0 + i) * NQKV + gcol] = r;
    }
}

// ---------------------------------------------------------------------------
// Kernel B: reduce split-K partials + RoPE -> g_q, g_k, g_v.
// ---------------------------------------------------------------------------
__global__ __launch_bounds__(256)
void rope_reduce(const float* __restrict__ fcos, const float* __restrict__ fsin)
{
    int idx = blockIdx.x * 256 + threadIdx.x;
    int b = idx / (NQKV / 2);
    int p = idx % (NQKV / 2);
    int col = 2 * p;

    float v0 = 0.f, v1 = 0.f;
    #pragma unroll
    for (int c = 0; c < NCH; c++) {
        float2 t = *(const float2*)&g_part[((size_t)c * BATCH + b) * NQKV + col];
        v0 += t.x; v1 += t.y;
    }

    if (col < 4096) {
        int d = col & (HD - 1);
        int dp = d >> 1;
        float c = fcos[dp], s = fsin[dp];
        g_q[b * 4096 + col]     = v0 * c - v1 * s;
        g_q[b * 4096 + col + 1] = v0 * s + v1 * c;
    } else if (col < 5120) {
        int cc = col - 4096;
        int d = cc & (HD - 1);
        int dp = d >> 1;
        float c = fcos[dp], s = fsin[dp];
        g_k[b * 1024 + cc]     = v0 * c - v1 * s;
        g_k[b * 1024 + cc + 1] = v0 * s + v1 * c;
    } else {
        int cc = col - 5120;
        g_v[b * 1024 + cc]     = v0;
        g_v[b * 1024 + cc + 1] = v1;
    }
}

// ---------------------------------------------------------------------------
// Kernel C: flash-decode GQA attention, fully coalesced.
// grid (NKV, BATCH, NSPLIT), block 256 (8 warps), warp-autonomous main loop.
// Per 16-token chunk: stage K rows coalesced into XOR-swizzled smem (4 wf per
// row), score phase lane=(token,half) reads smem conflict-free, V phase
// lane=dim coalesced. No block barriers in the loop.
// ---------------------------------------------------------------------------
__global__ __launch_bounds__(256)
void attention(const float* __restrict__ cache_k,
               const float* __restrict__ cache_v,
               const int* __restrict__ start_pos)
{
    __shared__ float4 ksm[8][CHT][32];        // 64 KB; reused for acc merge
    __shared__ float  qsm[4 * HD];            // 2 KB
    __shared__ float  psm[8][CHT * 4];        // 2 KB, warp-private
    __shared__ float  msm[8][NREP], lsm[8][NREP];

    const int hh  = blockIdx.x;               // kv head
    const int b   = blockIdx.y;
    const int spl = blockIdx.z;
    const int tx  = threadIdx.x;
    const int w   = tx >> 5;
    const int l   = tx & 31;
    const int tok = l & 15;                   // token within chunk
    const int hf  = l >> 4;                   // half of head-dim

    const int sp = *start_pos;                // 4095
    const int t0 = spl * TSPLIT;

    // q (pre-scaled by log2e/sqrt(HD)) into smem
    const float qscale = 1.4426950408889634f * 0.08838834764831845f;
    #pragma unroll
    for (int r = 0; r < 2; r++) {
        int o = tx + r * 256;
        qsm[o] = g_q[b * 4096 + (hh * NREP) * HD + o] * qscale;
    }
    __syncthreads();

    float m0 = -1e30f, m1 = -1e30f, m2 = -1e30f, m3 = -1e30f;
    float ls0 = 0.f, ls1 = 0.f, ls2 = 0.f, ls3 = 0.f;
    float acc[NREP][4];
    #pragma unroll
    for (int qi = 0; qi < NREP; qi++)
        #pragma unroll
        for (int j = 0; j < 4; j++) acc[qi][j] = 0.f;

    const size_t kv_bh = (size_t)b * MAXSEQ * NKV * HD + hh * HD;
    const float* gk = &g_k[(b * NKV + hh) * HD];
    const float* gv = &g_v[(b * NKV + hh) * HD];

    for (int c = w; c < NCHUNK; c += 8) {
        const int tb = t0 + c * CHT;

        // ---- stage K: 16 coalesced row loads -> swizzled smem ----
        #pragma unroll
        for (int r = 0; r < CHT; r++) {
            int tg = tb + r;
            const float* krow = (tg == sp) ? gk
                                           : cache_k + kv_bh + (size_t)tg * (NKV * HD);
            ksm[w][r][l ^ (r & 7)] = *(const float4*)&krow[l * 4];
        }
        __syncwarp();

        // ---- score: lane = (token, half), 64 dims each ----
        float s0 = 0.f, s1 = 0.f, s2 = 0.f, s3 = 0.f;
        #pragma unroll
        for (int i = 0; i < 16; i++) {
            int col = hf * 16 + i;
            float4 k4 = ksm[w][tok][col ^ (tok & 7)];
            float4 q0 = *(const float4*)&qsm[0 * HD + col * 4];
            float4 q1 = *(const float4*)&qsm[1 * HD + col * 4];
            float4 q2 = *(const float4*)&qsm[2 * HD + col * 4];
            float4 q3 = *(const float4*)&qsm[3 * HD + col * 4];
            s0 += k4.x*q0.x + k4.y*q0.y + k4.z*q0.z + k4.w*q0.w;
            s1 += k4.x*q1.x + k4.y*q1.y + k4.z*q1.z + k4.w*q1.w;
            s2 += k4.x*q2.x + k4.y*q2.y + k4.z*q2.z + k4.w*q2.w;
            s3 += k4.x*q3.x + k4.y*q3.y + k4.z*q3.z + k4.w*q3.w;
        }
        // combine the two halves (lanes l and l^16 hold the halves)
        s0 += __shfl_xor_sync(0xffffffffu, s0, 16);
        s1 += __shfl_xor_sync(0xffffffffu, s1, 16);
        s2 += __shfl_xor_sync(0xffffffffu, s2, 16);
        s3 += __shfl_xor_sync(0xffffffffu, s3, 16);
        // mask beyond-kv tokens
        if (tb + tok > sp) { s0 = -1e30f; s1 = -1e30f; s2 = -1e30f; s3 = -1e30f; }

        // ---- chunk max over the 16 tokens ----
        float c0 = s0, c1 = s1, c2 = s2, c3 = s3;
        #pragma unroll
        for (int off = 8; off > 0; off >>= 1) {
            c0 = fmaxf(c0, __shfl_xor_sync(0xffffffffu, c0, off));
            c1 = fmaxf(c1, __shfl_xor_sync(0xffffffffu, c1, off));
            c2 = fmaxf(c2, __shfl_xor_sync(0xffffffffu, c2, off));
            c3 = fmaxf(c3, __shfl_xor_sync(0xffffffffu, c3, off));
        }
        // online rescale (rare)
        if (c0 > m0) { float a = exp2f(m0 - c0); ls0 *= a;
            acc[0][0]*=a; acc[0][1]*=a; acc[0][2]*=a; acc[0][3]*=a; m0 = c0; }
        if (c1 > m1) { float a = exp2f(m1 - c1); ls1 *= a;
            acc[1][0]*=a; acc[1][1]*=a; acc[1][2]*=a; acc[1][3]*=a; m1 = c1; }
        if (c2 > m2) { float a = exp2f(m2 - c2); ls2 *= a;
            acc[2][0]*=a; acc[2][1]*=a; acc[2][2]*=a; acc[2][3]*=a; m2 = c2; }
        if (c3 > m3) { float a = exp2f(m3 - c3); ls3 *= a;
            acc[3][0]*=a; acc[3][1]*=a; acc[3][2]*=a; acc[3][3]*=a; m3 = c3; }

        float p0 = exp2f(s0 - m0), p1 = exp2f(s1 - m1);
        float p2 = exp2f(s2 - m2), p3 = exp2f(s3 - m3);
        if (hf == 0) {                        // lanes 16-31 are duplicates
            ls0 += p0; ls1 += p1; ls2 += p2; ls3 += p3;
            *(float4*)&psm[w][tok * 4] = make_float4(p0, p1, p2, p3);
        }
        __syncwarp();

        // ---- V: lane = dim-quad, coalesced; p broadcast from smem ----
        const float* vlane = cache_v + kv_bh + l * 4;
        #pragma unroll
        for (int tt = 0; tt < CHT; tt++) {
            int tg = tb + tt;
            const float* vp = (tg == sp) ? gv + l * 4
                                         : vlane + (size_t)tg * (NKV * HD);
            float4 v4 = *(const float4*)vp;
            float4 p4 = *(const float4*)&psm[w][tt * 4];
            acc[0][0] += p4.x*v4.x; acc[0][1] += p4.x*v4.y; acc[0][2] += p4.x*v4.z; acc[0][3] += p4.x*v4.w;
            acc[1][0] += p4.y*v4.x; acc[1][1] += p4.y*v4.y; acc[1][2] += p4.y*v4.z; acc[1][3] += p4.y*v4.w;
            acc[2][0] += p4.z*v4.x; acc[2][1] += p4.z*v4.y; acc[2][2] += p4.z*v4.z; acc[2][3] += p4.z*v4.w;
            acc[3][0] += p4.w*v4.x; acc[3][1] += p4.w*v4.y; acc[3][2] += p4.w*v4.z; acc[3][3] += p4.w*v4.w;
        }
        __syncwarp();
    }

    // ---- lane-reduce lsums ----
    #pragma unroll
    for (int off = 16; off > 0; off >>= 1) {
        ls0 += __shfl_xor_sync(0xffffffffu, ls0, off);
        ls1 += __shfl_xor_sync(0xffffffffu, ls1, off);
        ls2 += __shfl_xor_sync(0xffffffffu, ls2, off);
        ls3 += __shfl_xor_sync(0xffffffffu, ls3, off);
    }

    // ---- store warp partials (reuse ksm region for accs) ----
    __syncthreads();                          // all warps done with ksm
    float* accs = (float*)ksm;                // [8][NREP][HD]
    #pragma unroll
    for (int qi = 0; qi < NREP; qi++)
        *(float4*)&accs[(w * NREP + qi) * HD + l * 4] =
            make_float4(acc[qi][0], acc[qi][1], acc[qi][2], acc[qi][3]);
    if (l == 0) {
        msm[w][0] = m0; msm[w][1] = m1; msm[w][2] = m2; msm[w][3] = m3;
        lsm[w][0] = ls0; lsm[w][1] = ls1; lsm[w][2] = ls2; lsm[w][3] = ls3;
    }
    __syncthreads();

    // ---- block merge across 8 warps ----
    #pragma unroll
    for (int r = 0; r < 2; r++) {
        int o  = tx + r * 256;                // 0..511
        int qi = o >> 7;
        int d  = o & (HD - 1);
        float M = msm[0][qi];
        #pragma unroll
        for (int w2 = 1; w2 < 8; w2++) M = fmaxf(M, msm[w2][qi]);
        float num = 0.f, den = 0.f;
        #pragma unroll
        for (int w2 = 0; w2 < 8; w2++) {
            float wgt = exp2f(msm[w2][qi] - M);
            num += wgt * accs[(w2 * NREP + qi) * HD + d];
            den += wgt * lsm[w2][qi];
        }
        int pbase = ((b * NKV + hh) * NSPLIT + spl) * NREP + qi;
        g_pacc[(size_t)pbase * HD + d] = num;
        if (d == 0) { g_pl[pbase] = den; g_pm[pbase] = M; }
    }
}

// ---------------------------------------------------------------------------
// Kernel C2: merge the NSPLIT partials -> g_att. grid 256, block 512.
// ---------------------------------------------------------------------------
__global__ __launch_bounds__(512)
void att_merge()
{
    const int bh = blockIdx.x;
    const int o  = threadIdx.x;
    const int qi = o >> 7;
    const int d  = o & (HD - 1);
    const int base = bh * NSPLIT * NREP + qi;

    float M = -1e30f;
    #pragma unroll
    for (int s = 0; s < NSPLIT; s++) M = fmaxf(M, g_pm[base + s * NREP]);
    float num = 0.f, den = 0.f;
    #pragma unroll
    for (int s = 0; s < NSPLIT; s++) {
        int p = base + s * NREP;
        float wgt = exp2f(g_pm[p] - M);
        num += wgt * g_pacc[(size_t)p * HD + d];
        den += wgt * g_pl[p];
    }
    const int b = bh >> 3, h = bh & 7;
    g_att[b * 4096 + (h * NREP + qi) * HD + d] = num / den;
}

// ---------------------------------------------------------------------------
// Kernel D: output projection, split-K. grid (32,16), block 128.
// ---------------------------------------------------------------------------
__global__ __launch_bounds__(128)
void o_gemm(const float* __restrict__ wo)
{
    __shared__ float xs[BATCH * KC];
    const int tx = threadIdx.x;
    const int bx = blockIdx.x;
    const int by = blockIdx.y;
    const int k0 = by * KC;

    #pragma unroll
    for (int i = 0; i < 16; i++) {
        int s  = tx + i * 128;
        int b  = s >> 6;
        int k4 = s & 63;
        float4 v = *(const float4*)&g_att[b * DIM + k0 + k4 * 4];
        *(float4*)&xs[b * KC + k4 * 4] = v;
    }
    __syncthreads();

    const int q  = tx & 31;
    const int g  = tx >> 5;
    const int b0 = g * 8;
    const int gcol = bx * 128 + q * 4;
    const float* wp = wo + (size_t)k0 * DIM + gcol;

    float acc[8][4];
    #pragma unroll
    for (int i = 0; i < 8; i++)
        #pragma unroll
        for (int j = 0; j < 4; j++) acc[i][j] = 0.f;

    for (int kk = 0; kk < KC; kk += 4) {
        float xv[8][4];
        #pragma unroll
        for (int i = 0; i < 8; i++) {
            float4 t4 = *(const float4*)&xs[(b0 + i) * KC + kk];
            xv[i][0] = t4.x; xv[i][1] = t4.y; xv[i][2] = t4.z; xv[i][3] = t4.w;
        }
        #pragma unroll
        for (int j = 0; j < 4; j++) {
            float4 w4 = *(const float4*)&wp[(size_t)(kk + j) * DIM];
            #pragma unroll
            for (int i = 0; i < 8; i++) {
                acc[i][0] = fmaf(xv[i][j], w4.x, acc[i][0]);
                acc[i][1] = fmaf(xv[i][j], w4.y, acc[i][1]);
                acc[i][2] = fmaf(xv[i][j], w4.z, acc[i][2]);
                acc[i][3] = fmaf(xv[i][j], w4.w, acc[i][3]);
            }
        }
    }

    #pragma unroll
    for (int i = 0; i < 8; i++) {
        float4 r = make_float4(acc[i][0], acc[i][1], acc[i][2], acc[i][3]);
        *(float4*)&g_opart[((size_t)by * BATCH + b0 + i) * DIM + gcol] = r;
    }
}

// ---------------------------------------------------------------------------
// Kernel E: reduce O partials -> d_out
// ---------------------------------------------------------------------------
__global__ __launch_bounds__(256)
void o_reduce(float* __restrict__ out)
{
    int idx = blockIdx.x * 256 + threadIdx.x;
    float v = 0.f;
    #pragma unroll
    for (int c = 0; c < NCH; c++)
        v += g_opart[(size_t)c * (BATCH * DIM) + idx];
    out[idx] = v;
}

// ---------------------------------------------------------------------------
extern "C" void kernel_launch(void* const* d_in, const int* in_sizes, int n_in,
                              void* d_out, int out_size)
{
    const float* x        = (const float*)d_in[0];
    const float* cache_k  = (const float*)d_in[1];
    const float* cache_v  = (const float*)d_in[2];
    const float* fcos     = (const float*)d_in[3];
    const float* fsin     = (const float*)d_in[4];
    const float* wq       = (const float*)d_in[5];
    const float* wk       = (const float*)d_in[6];
    const float* wv       = (const float*)d_in[7];
    const float* wo       = (const float*)d_in[8];
    const int*   sp       = (const int*)d_in[9];
    float* out            = (float*)d_out;

    qkv_gemm<<<dim3(48, 16), 128>>>(x, wq, wk, wv);
    rope_reduce<<<(BATCH * (NQKV / 2)) / 256, 256>>>(fcos, fsin);
    attention<<<dim3(NKV, BATCH, NSPLIT), 256>>>(cache_k, cache_v, sp);
    att_merge<<<BATCH * NKV, 512>>>();
    o_gemm<<<dim3(32, 16), 128>>>(wo);
    o_reduce<<<(BATCH * DIM) / 256, 256>>>(out);
}

// round 6
// speedup vs baseline: 1.3308x; 1.0696x over previous
#include <cuda_runtime.h>
#include <cuda_bf16.h>
#include <math.h>

// Problem constants (fixed by the dataset)
#define BATCH   32
#define DIM     4096
#define NH      32
#define NKV     8
#define HD      128
#define NREP    4          // NH / NKV
#define MAXSEQ  4096
#define NQKV    6144       // 4096 (q) + 1024 (k) + 1024 (v)
#define KC      256        // k-chunk for split-K GEMMs
#define NCH     16         // 4096 / KC
#define NSPLIT  8          // KV splits in attention
#define TSPLIT  512        // MAXSEQ / NSPLIT
#define CHT     16         // tokens per warp-chunk
#define NCHUNK  32         // TSPLIT / CHT

typedef unsigned long long ull;

// Packed f32x2 helpers (Blackwell): FFMA2 only reachable via PTX fma.rn.f32x2
__device__ __forceinline__ ull pk2(float lo, float hi) {
    ull r; asm("mov.b64 %0, {%1, %2};" : "=l"(r) : "f"(lo), "f"(hi)); return r;
}
__device__ __forceinline__ ull fma2(ull a, ull b, ull c) {
    ull d; asm("fma.rn.f32x2 %0, %1, %2, %3;" : "=l"(d) : "l"(a), "l"(b), "l"(c));
    return d;
}
__device__ __forceinline__ void upk2(ull v, float& lo, float& hi) {
    asm("mov.b64 {%0, %1}, %2;" : "=f"(lo), "=f"(hi) : "l"(v));
}

// Scratch (device globals; no allocation allowed)
__device__ float g_part [NCH * BATCH * NQKV];   // QKV split-K partials
__device__ float g_q    [BATCH * NH * HD];      // rope'd q
__device__ float g_k    [BATCH * NKV * HD];     // rope'd new k
__device__ float g_v    [BATCH * NKV * HD];     // new v
__device__ float g_att  [BATCH * NH * HD];      // attention output
__device__ float g_opart[NCH * BATCH * DIM];    // O-proj split-K partials
// Attention split-KV partials
__device__ float g_pm  [BATCH * NKV * NSPLIT * NREP];
__device__ float g_pl  [BATCH * NKV * NSPLIT * NREP];
__device__ float g_pacc[BATCH * NKV * NSPLIT * NREP * HD];

// ---------------------------------------------------------------------------
// Kernel A: QKV projection, split-K, packed f32x2 FMA. grid (48,16), block 128.
// ---------------------------------------------------------------------------
__global__ __launch_bounds__(128)
void qkv_gemm(const float* __restrict__ x,
              const float* __restrict__ wq,
              const float* __restrict__ wk,
              const float* __restrict__ wv)
{
    __shared__ float xs[BATCH * KC];   // 32 KB
    const int tx = threadIdx.x;
    const int bx = blockIdx.x;
    const int by = blockIdx.y;
    const int k0 = by * KC;

    #pragma unroll
    for (int i = 0; i < 16; i++) {
        int s  = tx + i * 128;
        int b  = s >> 6;
        int k4 = s & 63;
        float4 v = *(const float4*)&x[b * DIM + k0 + k4 * 4];
        *(float4*)&xs[b * KC + k4 * 4] = v;
    }
    __syncthreads();

    const int q  = tx & 31;
    const int g  = tx >> 5;
    const int b0 = g * 8;
    const int gcol = bx * 128 + q * 4;

    const float* w; int ncols; int wcol;
    if (gcol < 4096)      { w = wq; ncols = 4096; wcol = gcol; }
    else if (gcol < 5120) { w = wk; ncols = 1024; wcol = gcol - 4096; }
    else                  { w = wv; ncols = 1024; wcol = gcol - 5120; }
    const float* wp = w + (size_t)k0 * ncols + wcol;

    ull acc01[8], acc23[8];
    #pragma unroll
    for (int i = 0; i < 8; i++) { acc01[i] = 0ULL; acc23[i] = 0ULL; }

    for (int kk = 0; kk < KC; kk += 4) {
        float xv[8][4];
        #pragma unroll
        for (int i = 0; i < 8; i++) {
            float4 t4 = *(const float4*)&xs[(b0 + i) * KC + kk];
            xv[i][0] = t4.x; xv[i][1] = t4.y; xv[i][2] = t4.z; xv[i][3] = t4.w;
        }
        #pragma unroll
        for (int j = 0; j < 4; j++) {
            float4 w4 = *(const float4*)&wp[(size_t)(kk + j) * ncols];
            ull w01 = pk2(w4.x, w4.y);
            ull w23 = pk2(w4.z, w4.w);
            #pragma unroll
            for (int i = 0; i < 8; i++) {
                ull xp = pk2(xv[i][j], xv[i][j]);
                acc01[i] = fma2(xp, w01, acc01[i]);
                acc23[i] = fma2(xp, w23, acc23[i]);
            }
        }
    }

    #pragma unroll
    for (int i = 0; i < 8; i++) {
        float4 r;
        upk2(acc01[i], r.x, r.y);
        upk2(acc23[i], r.z, r.w);
        *(float4*)&g_part[((size_t)by * BATCH + b0 + i) * NQKV + gcol] = r;
    }
}

// ---------------------------------------------------------------------------
// Kernel B: reduce split-K partials + RoPE -> g_q, g_k, g_v.
// ---------------------------------------------------------------------------
__global__ __launch_bounds__(256)
void rope_reduce(const float* __restrict__ fcos, const float* __restrict__ fsin)
{
    int idx = blockIdx.x * 256 + threadIdx.x;
    int b = idx / (NQKV / 2);
    int p = idx % (NQKV / 2);
    int col = 2 * p;

    float v0 = 0.f, v1 = 0.f;
    #pragma unroll
    for (int c = 0; c < NCH; c++) {
        float2 t = *(const float2*)&g_part[((size_t)c * BATCH + b) * NQKV + col];
        v0 += t.x; v1 += t.y;
    }

    if (col < 4096) {
        int d = col & (HD - 1);
        int dp = d >> 1;
        float c = fcos[dp], s = fsin[dp];
        g_q[b * 4096 + col]     = v0 * c - v1 * s;
        g_q[b * 4096 + col + 1] = v0 * s + v1 * c;
    } else if (col < 5120) {
        int cc = col - 4096;
        int d = cc & (HD - 1);
        int dp = d >> 1;
        float c = fcos[dp], s = fsin[dp];
        g_k[b * 1024 + cc]     = v0 * c - v1 * s;
        g_k[b * 1024 + cc + 1] = v0 * s + v1 * c;
    } else {
        int cc = col - 5120;
        g_v[b * 1024 + cc]     = v0;
        g_v[b * 1024 + cc + 1] = v1;
    }
}

// ---------------------------------------------------------------------------
// Kernel C: flash-decode GQA attention (unchanged from R5 winner).
// ---------------------------------------------------------------------------
__global__ __launch_bounds__(256)
void attention(const float* __restrict__ cache_k,
               const float* __restrict__ cache_v,
               const int* __restrict__ start_pos)
{
    __shared__ float4 ksm[8][CHT][32];        // 64 KB; reused for acc merge
    __shared__ float  qsm[4 * HD];            // 2 KB
    __shared__ float  psm[8][CHT * 4];        // 2 KB, warp-private
    __shared__ float  msm[8][NREP], lsm[8][NREP];

    const int hh  = blockIdx.x;               // kv head
    const int b   = blockIdx.y;
    const int spl = blockIdx.z;
    const int tx  = threadIdx.x;
    const int w   = tx >> 5;
    const int l   = tx & 31;
    const int tok = l & 15;                   // token within chunk
    const int hf  = l >> 4;                   // half of head-dim

    const int sp = *start_pos;                // 4095
    const int t0 = spl * TSPLIT;

    const float qscale = 1.4426950408889634f * 0.08838834764831845f;
    #pragma unroll
    for (int r = 0; r < 2; r++) {
        int o = tx + r * 256;
        qsm[o] = g_q[b * 4096 + (hh * NREP) * HD + o] * qscale;
    }
    __syncthreads();

    float m0 = -1e30f, m1 = -1e30f, m2 = -1e30f, m3 = -1e30f;
    float ls0 = 0.f, ls1 = 0.f, ls2 = 0.f, ls3 = 0.f;
    float acc[NREP][4];
    #pragma unroll
    for (int qi = 0; qi < NREP; qi++)
        #pragma unroll
        for (int j = 0; j < 4; j++) acc[qi][j] = 0.f;

    const size_t kv_bh = (size_t)b * MAXSEQ * NKV * HD + hh * HD;
    const float* gk = &g_k[(b * NKV + hh) * HD];
    const float* gv = &g_v[(b * NKV + hh) * HD];

    for (int c = w; c < NCHUNK; c += 8) {
        const int tb = t0 + c * CHT;

        #pragma unroll
        for (int r = 0; r < CHT; r++) {
            int tg = tb + r;
            const float* krow = (tg == sp) ? gk
                                           : cache_k + kv_bh + (size_t)tg * (NKV * HD);
            ksm[w][r][l ^ (r & 7)] = *(const float4*)&krow[l * 4];
        }
        __syncwarp();

        float s0 = 0.f, s1 = 0.f, s2 = 0.f, s3 = 0.f;
        #pragma unroll
        for (int i = 0; i < 16; i++) {
            int col = hf * 16 + i;
            float4 k4 = ksm[w][tok][col ^ (tok & 7)];
            float4 q0 = *(const float4*)&qsm[0 * HD + col * 4];
            float4 q1 = *(const float4*)&qsm[1 * HD + col * 4];
            float4 q2 = *(const float4*)&qsm[2 * HD + col * 4];
            float4 q3 = *(const float4*)&qsm[3 * HD + col * 4];
            s0 += k4.x*q0.x + k4.y*q0.y + k4.z*q0.z + k4.w*q0.w;
            s1 += k4.x*q1.x + k4.y*q1.y + k4.z*q1.z + k4.w*q1.w;
            s2 += k4.x*q2.x + k4.y*q2.y + k4.z*q2.z + k4.w*q2.w;
            s3 += k4.x*q3.x + k4.y*q3.y + k4.z*q3.z + k4.w*q3.w;
        }
        s0 += __shfl_xor_sync(0xffffffffu, s0, 16);
        s1 += __shfl_xor_sync(0xffffffffu, s1, 16);
        s2 += __shfl_xor_sync(0xffffffffu, s2, 16);
        s3 += __shfl_xor_sync(0xffffffffu, s3, 16);
        if (tb + tok > sp) { s0 = -1e30f; s1 = -1e30f; s2 = -1e30f; s3 = -1e30f; }

        float c0 = s0, c1 = s1, c2 = s2, c3 = s3;
        #pragma unroll
        for (int off = 8; off > 0; off >>= 1) {
            c0 = fmaxf(c0, __shfl_xor_sync(0xffffffffu, c0, off));
            c1 = fmaxf(c1, __shfl_xor_sync(0xffffffffu, c1, off));
            c2 = fmaxf(c2, __shfl_xor_sync(0xffffffffu, c2, off));
            c3 = fmaxf(c3, __shfl_xor_sync(0xffffffffu, c3, off));
        }
        if (c0 > m0) { float a = exp2f(m0 - c0); ls0 *= a;
            acc[0][0]*=a; acc[0][1]*=a; acc[0][2]*=a; acc[0][3]*=a; m0 = c0; }
        if (c1 > m1) { float a = exp2f(m1 - c1); ls1 *= a;
            acc[1][0]*=a; acc[1][1]*=a; acc[1][2]*=a; acc[1][3]*=a; m1 = c1; }
        if (c2 > m2) { float a = exp2f(m2 - c2); ls2 *= a;
            acc[2][0]*=a; acc[2][1]*=a; acc[2][2]*=a; acc[2][3]*=a; m2 = c2; }
        if (c3 > m3) { float a = exp2f(m3 - c3); ls3 *= a;
            acc[3][0]*=a; acc[3][1]*=a; acc[3][2]*=a; acc[3][3]*=a; m3 = c3; }

        float p0 = exp2f(s0 - m0), p1 = exp2f(s1 - m1);
        float p2 = exp2f(s2 - m2), p3 = exp2f(s3 - m3);
        if (hf == 0) {
            ls0 += p0; ls1 += p1; ls2 += p2; ls3 += p3;
            *(float4*)&psm[w][tok * 4] = make_float4(p0, p1, p2, p3);
        }
        __syncwarp();

        const float* vlane = cache_v + kv_bh + l * 4;
        #pragma unroll
        for (int tt = 0; tt < CHT; tt++) {
            int tg = tb + tt;
            const float* vp = (tg == sp) ? gv + l * 4
                                         : vlane + (size_t)tg * (NKV * HD);
            float4 v4 = *(const float4*)vp;
            float4 p4 = *(const float4*)&psm[w][tt * 4];
            acc[0][0] += p4.x*v4.x; acc[0][1] += p4.x*v4.y; acc[0][2] += p4.x*v4.z; acc[0][3] += p4.x*v4.w;
            acc[1][0] += p4.y*v4.x; acc[1][1] += p4.y*v4.y; acc[1][2] += p4.y*v4.z; acc[1][3] += p4.y*v4.w;
            acc[2][0] += p4.z*v4.x; acc[2][1] += p4.z*v4.y; acc[2][2] += p4.z*v4.z; acc[2][3] += p4.z*v4.w;
            acc[3][0] += p4.w*v4.x; acc[3][1] += p4.w*v4.y; acc[3][2] += p4.w*v4.z; acc[3][3] += p4.w*v4.w;
        }
        __syncwarp();
    }

    #pragma unroll
    for (int off = 16; off > 0; off >>= 1) {
        ls0 += __shfl_xor_sync(0xffffffffu, ls0, off);
        ls1 += __shfl_xor_sync(0xffffffffu, ls1, off);
        ls2 += __shfl_xor_sync(0xffffffffu, ls2, off);
        ls3 += __shfl_xor_sync(0xffffffffu, ls3, off);
    }

    __syncthreads();
    float* accs = (float*)ksm;                // [8][NREP][HD]
    #pragma unroll
    for (int qi = 0; qi < NREP; qi++)
        *(float4*)&accs[(w * NREP + qi) * HD + l * 4] =
            make_float4(acc[qi][0], acc[qi][1], acc[qi][2], acc[qi][3]);
    if (l == 0) {
        msm[w][0] = m0; msm[w][1] = m1; msm[w][2] = m2; msm[w][3] = m3;
        lsm[w][0] = ls0; lsm[w][1] = ls1; lsm[w][2] = ls2; lsm[w][3] = ls3;
    }
    __syncthreads();

    #pragma unroll
    for (int r = 0; r < 2; r++) {
        int o  = tx + r * 256;
        int qi = o >> 7;
        int d  = o & (HD - 1);
        float M = msm[0][qi];
        #pragma unroll
        for (int w2 = 1; w2 < 8; w2++) M = fmaxf(M, msm[w2][qi]);
        float num = 0.f, den = 0.f;
        #pragma unroll
        for (int w2 = 0; w2 < 8; w2++) {
            float wgt = exp2f(msm[w2][qi] - M);
            num += wgt * accs[(w2 * NREP + qi) * HD + d];
            den += wgt * lsm[w2][qi];
        }
        int pbase = ((b * NKV + hh) * NSPLIT + spl) * NREP + qi;
        g_pacc[(size_t)pbase * HD + d] = num;
        if (d == 0) { g_pl[pbase] = den; g_pm[pbase] = M; }
    }
}

// ---------------------------------------------------------------------------
// Kernel C2: merge the NSPLIT partials -> g_att. grid 256, block 512.
// ---------------------------------------------------------------------------
__global__ __launch_bounds__(512)
void att_merge()
{
    const int bh = blockIdx.x;
    const int o  = threadIdx.x;
    const int qi = o >> 7;
    const int d  = o & (HD - 1);
    const int base = bh * NSPLIT * NREP + qi;

    float M = -1e30f;
    #pragma unroll
    for (int s = 0; s < NSPLIT; s++) M = fmaxf(M, g_pm[base + s * NREP]);
    float num = 0.f, den = 0.f;
    #pragma unroll
    for (int s = 0; s < NSPLIT; s++) {
        int p = base + s * NREP;
        float wgt = exp2f(g_pm[p] - M);
        num += wgt * g_pacc[(size_t)p * HD + d];
        den += wgt * g_pl[p];
    }
    const int b = bh >> 3, h = bh & 7;
    g_att[b * 4096 + (h * NREP + qi) * HD + d] = num / den;
}

// ---------------------------------------------------------------------------
// Kernel D: output projection, split-K, packed f32x2 FMA. grid (32,16), 128.
// ---------------------------------------------------------------------------
__global__ __launch_bounds__(128)
void o_gemm(const float* __restrict__ wo)
{
    __shared__ float xs[BATCH * KC];
    const int tx = threadIdx.x;
    const int bx = blockIdx.x;
    const int by = blockIdx.y;
    const int k0 = by * KC;

    #pragma unroll
    for (int i = 0; i < 16; i++) {
        int s  = tx + i * 128;
        int b  = s >> 6;
        int k4 = s & 63;
        float4 v = *(const float4*)&g_att[b * DIM + k0 + k4 * 4];
        *(float4*)&xs[b * KC + k4 * 4] = v;
    }
    __syncthreads();

    const int q  = tx & 31;
    const int g  = tx >> 5;
    const int b0 = g * 8;
    const int gcol = bx * 128 + q * 4;
    const float* wp = wo + (size_t)k0 * DIM + gcol;

    ull acc01[8], acc23[8];
    #pragma unroll
    for (int i = 0; i < 8; i++) { acc01[i] = 0ULL; acc23[i] = 0ULL; }

    for (int kk = 0; kk < KC; kk += 4) {
        float xv[8][4];
        #pragma unroll
        for (int i = 0; i < 8; i++) {
            float4 t4 = *(const float4*)&xs[(b0 + i) * KC + kk];
            xv[i][0] = t4.x; xv[i][1] = t4.y; xv[i][2] = t4.z; xv[i][3] = t4.w;
        }
        #pragma unroll
        for (int j = 0; j < 4; j++) {
            float4 w4 = *(const float4*)&wp[(size_t)(kk + j) * DIM];
            ull w01 = pk2(w4.x, w4.y);
            ull w23 = pk2(w4.z, w4.w);
            #pragma unroll
            for (int i = 0; i < 8; i++) {
                ull xp = pk2(xv[i][j], xv[i][j]);
                acc01[i] = fma2(xp, w01, acc01[i]);
                acc23[i] = fma2(xp, w23, acc23[i]);
            }
        }
    }

    #pragma unroll
    for (int i = 0; i < 8; i++) {
        float4 r;
        upk2(acc01[i], r.x, r.y);
        upk2(acc23[i], r.z, r.w);
        *(float4*)&g_opart[((size_t)by * BATCH + b0 + i) * DIM + gcol] = r;
    }
}

// ---------------------------------------------------------------------------
// Kernel E: reduce O partials -> d_out
// ---------------------------------------------------------------------------
__global__ __launch_bounds__(256)
void o_reduce(float* __restrict__ out)
{
    int idx = blockIdx.x * 256 + threadIdx.x;
    float v = 0.f;
    #pragma unroll
    for (int c = 0; c < NCH; c++)
        v += g_opart[(size_t)c * (BATCH * DIM) + idx];
    out[idx] = v;
}

// ---------------------------------------------------------------------------
extern "C" void kernel_launch(void* const* d_in, const int* in_sizes, int n_in,
                              void* d_out, int out_size)
{
    const float* x        = (const float*)d_in[0];
    const float* cache_k  = (const float*)d_in[1];
    const float* cache_v  = (const float*)d_in[2];
    const float* fcos     = (const float*)d_in[3];
    const float* fsin     = (const float*)d_in[4];
    const float* wq       = (const float*)d_in[5];
    const float* wk       = (const float*)d_in[6];
    const float* wv       = (const float*)d_in[7];
    const float* wo       = (const float*)d_in[8];
    const int*   sp       = (const int*)d_in[9];
    float* out            = (float*)d_out;

    qkv_gemm<<<dim3(48, 16), 128>>>(x, wq, wk, wv);
    rope_reduce<<<(BATCH * (NQKV / 2)) / 256, 256>>>(fcos, fsin);
    attention<<<dim3(NKV, BATCH, NSPLIT), 256>>>(cache_k, cache_v, sp);
    att_merge<<<BATCH * NKV, 512>>>();
    o_gemm<<<dim3(32, 16), 128>>>(wo);
    o_reduce<<<(BATCH * DIM) / 256, 256>>>(out);
}

// round 11
// speedup vs baseline: 1.4207x; 1.0675x over previous
#include <cuda_runtime.h>
#include <cuda_bf16.h>
#include <math.h>
#include <cstdint>

// Problem constants (fixed by the dataset)
#define BATCH   32
#define DIM     4096
#define NH      32
#define NKV     8
#define HD      128
#define NREP    4          // NH / NKV
#define MAXSEQ  4096
#define NQKV    6144       // 4096 (q) + 1024 (k) + 1024 (v)
#define KC      256        // k-chunk for split-K GEMMs
#define NCH     16         // 4096 / KC
#define NSPLIT  8          // KV splits in attention
#define TSPLIT  512        // MAXSEQ / NSPLIT
#define CHT     8          // tokens per warp-chunk (double-buffered)
#define NCHUNK  64         // TSPLIT / CHT

typedef unsigned long long ull;
typedef unsigned int u32;

// Packed f32x2 helpers (Blackwell): FFMA2 only reachable via PTX fma.rn.f32x2
__device__ __forceinline__ ull pk2(float lo, float hi) {
    ull r; asm("mov.b64 %0, {%1, %2};" : "=l"(r) : "f"(lo), "f"(hi)); return r;
}
__device__ __forceinline__ ull fma2(ull a, ull b, ull c) {
    ull d; asm("fma.rn.f32x2 %0, %1, %2, %3;" : "=l"(d) : "l"(a), "l"(b), "l"(c));
    return d;
}
__device__ __forceinline__ void upk2(ull v, float& lo, float& hi) {
    asm("mov.b64 {%0, %1}, %2;" : "=f"(lo), "=f"(hi) : "l"(v));
}

// cp.async helpers
__device__ __forceinline__ u32 smem_u32(const void* p) {
    return (u32)__cvta_generic_to_shared(p);
}
__device__ __forceinline__ void cp16(u32 dst, const void* src) {
    asm volatile("cp.async.cg.shared.global [%0], [%1], 16;" :: "r"(dst), "l"(src));
}
__device__ __forceinline__ void cp_commit() {
    asm volatile("cp.async.commit_group;");
}
template<int N> __device__ __forceinline__ void cp_wait() {
    asm volatile("cp.async.wait_group %0;" :: "n"(N));
}

// Scratch (device globals; no allocation allowed)
__device__ float g_part [NCH * BATCH * NQKV];   // QKV split-K partials
__device__ float g_q    [BATCH * NH * HD];      // rope'd q
__device__ float g_k    [BATCH * NKV * HD];     // rope'd new k
__device__ float g_v    [BATCH * NKV * HD];     // new v
__device__ float g_att  [BATCH * NH * HD];      // attention output
__device__ float g_opart[NCH * BATCH * DIM];    // O-proj split-K partials
// Attention split-KV partials
__device__ float g_pm  [BATCH * NKV * NSPLIT * NREP];
__device__ float g_pl  [BATCH * NKV * NSPLIT * NREP];
__device__ float g_pacc[BATCH * NKV * NSPLIT * NREP * HD];

// ---------------------------------------------------------------------------
// Kernel A: QKV projection, split-K, packed f32x2 FMA. grid (48,16), block 128.
// ---------------------------------------------------------------------------
__global__ __launch_bounds__(128)
void qkv_gemm(const float* __restrict__ x,
              const float* __restrict__ wq,
              const float* __restrict__ wk,
              const float* __restrict__ wv)
{
    __shared__ float xs[BATCH * KC];   // 32 KB
    const int tx = threadIdx.x;
    const int bx = blockIdx.x;
    const int by = blockIdx.y;
    const int k0 = by * KC;

    #pragma unroll
    for (int i = 0; i < 16; i++) {
        int s  = tx + i * 128;
        int b  = s >> 6;
        int k4 = s & 63;
        float4 v = *(const float4*)&x[b * DIM + k0 + k4 * 4];
        *(float4*)&xs[b * KC + k4 * 4] = v;
    }
    __syncthreads();

    const int q  = tx & 31;
    const int g  = tx >> 5;
    const int b0 = g * 8;
    const int gcol = bx * 128 + q * 4;

    const float* w; int ncols; int wcol;
    if (gcol < 4096)      { w = wq; ncols = 4096; wcol = gcol; }
    else if (gcol < 5120) { w = wk; ncols = 1024; wcol = gcol - 4096; }
    else                  { w = wv; ncols = 1024; wcol = gcol - 5120; }
    const float* wp = w + (size_t)k0 * ncols + wcol;

    ull acc01[8], acc23[8];
    #pragma unroll
    for (int i = 0; i < 8; i++) { acc01[i] = 0ULL; acc23[i] = 0ULL; }

    for (int kk = 0; kk < KC; kk += 4) {
        float xv[8][4];
        #pragma unroll
        for (int i = 0; i < 8; i++) {
            float4 t4 = *(const float4*)&xs[(b0 + i) * KC + kk];
            xv[i][0] = t4.x; xv[i][1] = t4.y; xv[i][2] = t4.z; xv[i][3] = t4.w;
        }
        #pragma unroll
        for (int j = 0; j < 4; j++) {
            float4 w4 = *(const float4*)&wp[(size_t)(kk + j) * ncols];
            ull w01 = pk2(w4.x, w4.y);
            ull w23 = pk2(w4.z, w4.w);
            #pragma unroll
            for (int i = 0; i < 8; i++) {
                ull xp = pk2(xv[i][j], xv[i][j]);
                acc01[i] = fma2(xp, w01, acc01[i]);
                acc23[i] = fma2(xp, w23, acc23[i]);
            }
        }
    }

    #pragma unroll
    for (int i = 0; i < 8; i++) {
        float4 r;
        upk2(acc01[i], r.x, r.y);
        upk2(acc23[i], r.z, r.w);
        *(float4*)&g_part[((size_t)by * BATCH + b0 + i) * NQKV + gcol] = r;
    }
}

// ---------------------------------------------------------------------------
// Kernel B: reduce split-K partials + RoPE -> g_q, g_k, g_v.
// ---------------------------------------------------------------------------
__global__ __launch_bounds__(256)
void rope_reduce(const float* __restrict__ fcos, const float* __restrict__ fsin)
{
    int idx = blockIdx.x * 256 + threadIdx.x;
    int b = idx / (NQKV / 2);
    int p = idx % (NQKV / 2);
    int col = 2 * p;

    float v0 = 0.f, v1 = 0.f;
    #pragma unroll
    for (int c = 0; c < NCH; c++) {
        float2 t = *(const float2*)&g_part[((size_t)c * BATCH + b) * NQKV + col];
        v0 += t.x; v1 += t.y;
    }

    if (col < 4096) {
        int d = col & (HD - 1);
        int dp = d >> 1;
        float c = fcos[dp], s = fsin[dp];
        g_q[b * 4096 + col]     = v0 * c - v1 * s;
        g_q[b * 4096 + col + 1] = v0 * s + v1 * c;
    } else if (col < 5120) {
        int cc = col - 4096;
        int d = cc & (HD - 1);
        int dp = d >> 1;
        float c = fcos[dp], s = fsin[dp];
        g_k[b * 1024 + cc]     = v0 * c - v1 * s;
        g_k[b * 1024 + cc + 1] = v0 * s + v1 * c;
    } else {
        int cc = col - 5120;
        g_v[b * 1024 + cc]     = v0;
        g_v[b * 1024 + cc + 1] = v1;
    }
}

// ---------------------------------------------------------------------------
// Probe pad: shifts attention into the ncu capture slot. No-op.
// ---------------------------------------------------------------------------
__global__ void probe_pad() {}

// ---------------------------------------------------------------------------
// Kernel C: flash-decode GQA attention, cp.async double-buffered K pipeline.
// grid (NKV, BATCH, NSPLIT), block 256 (8 warps), warp-autonomous.
// Chunk = 8 tokens/warp. Prefetch chunk c+1 while computing chunk c.
// Score: lane = (token 0-7, quarter 0-3). V: lane = dim-quad, coalesced.
// ---------------------------------------------------------------------------
__global__ __launch_bounds__(256)
void attention(const float* __restrict__ cache_k,
               const float* __restrict__ cache_v,
               const int* __restrict__ start_pos)
{
    __shared__ float4 ksm[8][2][CHT][32];     // 64 KB; reused for acc merge
    __shared__ float  qsm[4 * HD];            // 2 KB
    __shared__ float  psm[8][CHT * 4];        // 1 KB, warp-private
    __shared__ float  msm[8][NREP], lsm[8][NREP];

    const int hh  = blockIdx.x;               // kv head
    const int b   = blockIdx.y;
    const int spl = blockIdx.z;
    const int tx  = threadIdx.x;
    const int w   = tx >> 5;
    const int l   = tx & 31;
    const int tok = l & 7;                    // token within chunk
    const int qr  = l >> 3;                   // dim quarter (32 dims each)

    const int sp = *start_pos;                // 4095
    const int t0 = spl * TSPLIT;

    const float qscale = 1.4426950408889634f * 0.08838834764831845f;
    #pragma unroll
    for (int r = 0; r < 2; r++) {
        int o = tx + r * 256;
        qsm[o] = g_q[b * 4096 + (hh * NREP) * HD + o] * qscale;
    }
    __syncthreads();

    float m0 = -1e30f, m1 = -1e30f, m2 = -1e30f, m3 = -1e30f;
    float ls0 = 0.f, ls1 = 0.f, ls2 = 0.f, ls3 = 0.f;
    float acc[NREP][4];
    #pragma unroll
    for (int qi = 0; qi < NREP; qi++)
        #pragma unroll
        for (int j = 0; j < 4; j++) acc[qi][j] = 0.f;

    const size_t kv_bh = (size_t)b * MAXSEQ * NKV * HD + hh * HD;
    const float* gk = &g_k[(b * NKV + hh) * HD];
    const float* gv = &g_v[(b * NKV + hh) * HD];

    const u32 kbase = smem_u32(&ksm[w][0][0][0]);

    // stage chunk c into buffer buf via cp.async (1 row per lane-iteration)
    auto stage = [&](int c, int buf) {
        const int tb = t0 + c * CHT;
        #pragma unroll
        for (int r = 0; r < CHT; r++) {
            int tg = tb + r;
            const float* krow = (tg == sp) ? gk
                                           : cache_k + kv_bh + (size_t)tg * (NKV * HD);
            cp16(kbase + (u32)(((buf * CHT + r) * 32 + (l ^ r)) * 16),
                 krow + l * 4);
        }
        cp_commit();
    };

    // prologue: prefetch first chunk
    stage(w, 0);

    for (int j = 0; j < NCHUNK / 8; j++) {
        const int c  = w + j * 8;
        const int tb = t0 + c * CHT;
        const int buf = j & 1;

        if (j < NCHUNK / 8 - 1) { stage(c + 8, buf ^ 1); cp_wait<1>(); }
        else                    { cp_wait<0>(); }
        __syncwarp();

        // ---- score: lane = (token, quarter), 32 dims each ----
        float s0 = 0.f, s1 = 0.f, s2 = 0.f, s3 = 0.f;
        #pragma unroll
        for (int i = 0; i < 8; i++) {
            int col = qr * 8 + i;
            float4 k4 = ksm[w][buf][tok][col ^ tok];
            float4 q0 = *(const float4*)&qsm[0 * HD + col * 4];
            float4 q1 = *(const float4*)&qsm[1 * HD + col * 4];
            float4 q2 = *(const float4*)&qsm[2 * HD + col * 4];
            float4 q3 = *(const float4*)&qsm[3 * HD + col * 4];
            s0 += k4.x*q0.x + k4.y*q0.y + k4.z*q0.z + k4.w*q0.w;
            s1 += k4.x*q1.x + k4.y*q1.y + k4.z*q1.z + k4.w*q1.w;
            s2 += k4.x*q2.x + k4.y*q2.y + k4.z*q2.z + k4.w*q2.w;
            s3 += k4.x*q3.x + k4.y*q3.y + k4.z*q3.z + k4.w*q3.w;
        }
        // combine quarters (lanes differing in bits 3,4 hold partials)
        s0 += __shfl_xor_sync(0xffffffffu, s0, 8);
        s1 += __shfl_xor_sync(0xffffffffu, s1, 8);
        s2 += __shfl_xor_sync(0xffffffffu, s2, 8);
        s3 += __shfl_xor_sync(0xffffffffu, s3, 8);
        s0 += __shfl_xor_sync(0xffffffffu, s0, 16);
        s1 += __shfl_xor_sync(0xffffffffu, s1, 16);
        s2 += __shfl_xor_sync(0xffffffffu, s2, 16);
        s3 += __shfl_xor_sync(0xffffffffu, s3, 16);
        if (tb + tok > sp) { s0 = -1e30f; s1 = -1e30f; s2 = -1e30f; s3 = -1e30f; }

        // ---- chunk max over the 8 tokens (lane bits 0-2) ----
        float c0 = s0, c1 = s1, c2 = s2, c3 = s3;
        #pragma unroll
        for (int off = 4; off > 0; off >>= 1) {
            c0 = fmaxf(c0, __shfl_xor_sync(0xffffffffu, c0, off));
            c1 = fmaxf(c1, __shfl_xor_sync(0xffffffffu, c1, off));
            c2 = fmaxf(c2, __shfl_xor_sync(0xffffffffu, c2, off));
            c3 = fmaxf(c3, __shfl_xor_sync(0xffffffffu, c3, off));
        }
        if (c0 > m0) { float a = exp2f(m0 - c0); ls0 *= a;
            acc[0][0]*=a; acc[0][1]*=a; acc[0][2]*=a; acc[0][3]*=a; m0 = c0; }
        if (c1 > m1) { float a = exp2f(m1 - c1); ls1 *= a;
            acc[1][0]*=a; acc[1][1]*=a; acc[1][2]*=a; acc[1][3]*=a; m1 = c1; }
        if (c2 > m2) { float a = exp2f(m2 - c2); ls2 *= a;
            acc[2][0]*=a; acc[2][1]*=a; acc[2][2]*=a; acc[2][3]*=a; m2 = c2; }
        if (c3 > m3) { float a = exp2f(m3 - c3); ls3 *= a;
            acc[3][0]*=a; acc[3][1]*=a; acc[3][2]*=a; acc[3][3]*=a; m3 = c3; }

        float p0 = exp2f(s0 - m0), p1 = exp2f(s1 - m1);
        float p2 = exp2f(s2 - m2), p3 = exp2f(s3 - m3);
        if (qr == 0) {                        // one lane per token owns p
            ls0 += p0; ls1 += p1; ls2 += p2; ls3 += p3;
            *(float4*)&psm[w][tok * 4] = make_float4(p0, p1, p2, p3);
        }
        __syncwarp();

        // ---- V: lane = dim-quad, coalesced; p broadcast from smem ----
        const float* vlane = cache_v + kv_bh + l * 4;
        #pragma unroll
        for (int tt = 0; tt < CHT; tt++) {
            int tg = tb + tt;
            const float* vp = (tg == sp) ? gv + l * 4
                                         : vlane + (size_t)tg * (NKV * HD);
            float4 v4 = *(const float4*)vp;
            float4 p4 = *(const float4*)&psm[w][tt * 4];
            acc[0][0] += p4.x*v4.x; acc[0][1] += p4.x*v4.y; acc[0][2] += p4.x*v4.z; acc[0][3] += p4.x*v4.w;
            acc[1][0] += p4.y*v4.x; acc[1][1] += p4.y*v4.y; acc[1][2] += p4.y*v4.z; acc[1][3] += p4.y*v4.w;
            acc[2][0] += p4.z*v4.x; acc[2][1] += p4.z*v4.y; acc[2][2] += p4.z*v4.z; acc[2][3] += p4.z*v4.w;
            acc[3][0] += p4.w*v4.x; acc[3][1] += p4.w*v4.y; acc[3][2] += p4.w*v4.z; acc[3][3] += p4.w*v4.w;
        }
        __syncwarp();
    }

    // ---- lane-reduce lsums (only qr==0 lanes hold nonzero partials) ----
    #pragma unroll
    for (int off = 16; off > 0; off >>= 1) {
        ls0 += __shfl_xor_sync(0xffffffffu, ls0, off);
        ls1 += __shfl_xor_sync(0xffffffffu, ls1, off);
        ls2 += __shfl_xor_sync(0xffffffffu, ls2, off);
        ls3 += __shfl_xor_sync(0xffffffffu, ls3, off);
    }

    // ---- store warp partials (reuse ksm region for accs) ----
    __syncthreads();                          // all warps done with ksm
    float* accs = (float*)ksm;                // [8][NREP][HD]
    #pragma unroll
    for (int qi = 0; qi < NREP; qi++)
        *(float4*)&accs[(w * NREP + qi) * HD + l * 4] =
            make_float4(acc[qi][0], acc[qi][1], acc[qi][2], acc[qi][3]);
    if (l == 0) {
        msm[w][0] = m0; msm[w][1] = m1; msm[w][2] = m2; msm[w][3] = m3;
        lsm[w][0] = ls0; lsm[w][1] = ls1; lsm[w][2] = ls2; lsm[w][3] = ls3;
    }
    __syncthreads();

    // ---- block merge across 8 warps ----
    #pragma unroll
    for (int r = 0; r < 2; r++) {
        int o  = tx + r * 256;
        int qi = o >> 7;
        int d  = o & (HD - 1);
        float M = msm[0][qi];
        #pragma unroll
        for (int w2 = 1; w2 < 8; w2++) M = fmaxf(M, msm[w2][qi]);
        float num = 0.f, den = 0.f;
        #pragma unroll
        for (int w2 = 0; w2 < 8; w2++) {
            float wgt = exp2f(msm[w2][qi] - M);
            num += wgt * accs[(w2 * NREP + qi) * HD + d];
            den += wgt * lsm[w2][qi];
        }
        int pbase = ((b * NKV + hh) * NSPLIT + spl) * NREP + qi;
        g_pacc[(size_t)pbase * HD + d] = num;
        if (d == 0) { g_pl[pbase] = den; g_pm[pbase] = M; }
    }
}

// ---------------------------------------------------------------------------
// Kernel C2: merge the NSPLIT partials -> g_att. grid 256, block 512.
// ---------------------------------------------------------------------------
__global__ __launch_bounds__(512)
void att_merge()
{
    const int bh = blockIdx.x;
    const int o  = threadIdx.x;
    const int qi = o >> 7;
    const int d  = o & (HD - 1);
    const int base = bh * NSPLIT * NREP + qi;

    float M = -1e30f;
    #pragma unroll
    for (int s = 0; s < NSPLIT; s++) M = fmaxf(M, g_pm[base + s * NREP]);
    float num = 0.f, den = 0.f;
    #pragma unroll
    for (int s = 0; s < NSPLIT; s++) {
        int p = base + s * NREP;
        float wgt = exp2f(g_pm[p] - M);
        num += wgt * g_pacc[(size_t)p * HD + d];
        den += wgt * g_pl[p];
    }
    const int b = bh >> 3, h = bh & 7;
    g_att[b * 4096 + (h * NREP + qi) * HD + d] = num / den;
}

// ---------------------------------------------------------------------------
// Kernel D: output projection, split-K, packed f32x2 FMA. grid (32,16), 128.
// ---------------------------------------------------------------------------
__global__ __launch_bounds__(128)
void o_gemm(const float* __restrict__ wo)
{
    __shared__ float xs[BATCH * KC];
    const int tx = threadIdx.x;
    const int bx = blockIdx.x;
    const int by = blockIdx.y;
    const int k0 = by * KC;

    #pragma unroll
    for (int i = 0; i < 16; i++) {
        int s  = tx + i * 128;
        int b  = s >> 6;
        int k4 = s & 63;
        float4 v = *(const float4*)&g_att[b * DIM + k0 + k4 * 4];
        *(float4*)&xs[b * KC + k4 * 4] = v;
    }
    __syncthreads();

    const int q  = tx & 31;
    const int g  = tx >> 5;
    const int b0 = g * 8;
    const int gcol = bx * 128 + q * 4;
    const float* wp = wo + (size_t)k0 * DIM + gcol;

    ull acc01[8], acc23[8];
    #pragma unroll
    for (int i = 0; i < 8; i++) { acc01[i] = 0ULL; acc23[i] = 0ULL; }

    for (int kk = 0; kk < KC; kk += 4) {
        float xv[8][4];
        #pragma unroll
        for (int i = 0; i < 8; i++) {
            float4 t4 = *(const float4*)&xs[(b0 + i) * KC + kk];
            xv[i][0] = t4.x; xv[i][1] = t4.y; xv[i][2] = t4.z; xv[i][3] = t4.w;
        }
        #pragma unroll
        for (int j = 0; j < 4; j++) {
            float4 w4 = *(const float4*)&wp[(size_t)(kk + j) * DIM];
            ull w01 = pk2(w4.x, w4.y);
            ull w23 = pk2(w4.z, w4.w);
            #pragma unroll
            for (int i = 0; i < 8; i++) {
                ull xp = pk2(xv[i][j], xv[i][j]);
                acc01[i] = fma2(xp, w01, acc01[i]);
                acc23[i] = fma2(xp, w23, acc23[i]);
            }
        }
    }

    #pragma unroll
    for (int i = 0; i < 8; i++) {
        float4 r;
        upk2(acc01[i], r.x, r.y);
        upk2(acc23[i], r.z, r.w);
        *(float4*)&g_opart[((size_t)by * BATCH + b0 + i) * DIM + gcol] = r;
    }
}

// ---------------------------------------------------------------------------
// Kernel E: reduce O partials -> d_out
// ---------------------------------------------------------------------------
__global__ __launch_bounds__(256)
void o_reduce(float* __restrict__ out)
{
    int idx = blockIdx.x * 256 + threadIdx.x;
    float v = 0.f;
    #pragma unroll
    for (int c = 0; c < NCH; c++)
        v += g_opart[(size_t)c * (BATCH * DIM) + idx];
    out[idx] = v;
}

// ---------------------------------------------------------------------------
extern "C" void kernel_launch(void* const* d_in, const int* in_sizes, int n_in,
                              void* d_out, int out_size)
{
    const float* x        = (const float*)d_in[0];
    const float* cache_k  = (const float*)d_in[1];
    const float* cache_v  = (const float*)d_in[2];
    const float* fcos     = (const float*)d_in[3];
    const float* fsin     = (const float*)d_in[4];
    const float* wq       = (const float*)d_in[5];
    const float* wk       = (const float*)d_in[6];
    const float* wv       = (const float*)d_in[7];
    const float* wo       = (const float*)d_in[8];
    const int*   sp       = (const int*)d_in[9];
    float* out            = (float*)d_out;

    qkv_gemm<<<dim3(48, 16), 128>>>(x, wq, wk, wv);
    rope_reduce<<<(BATCH * (NQKV / 2)) / 256, 256>>>(fcos, fsin);
    probe_pad<<<1, 32>>>();                 // shifts attention into ncu slot 4
    attention<<<dim3(NKV, BATCH, NSPLIT), 256>>>(cache_k, cache_v, sp);
    att_merge<<<BATCH * NKV, 512>>>();
    o_gemm<<<dim3(32, 16), 128>>>(wo);
    o_reduce<<<(BATCH * DIM) / 256, 256>>>(out);
}

// round 12
// speedup vs baseline: 1.4503x; 1.0209x over previous
#include <cuda_runtime.h>
#include <cuda_bf16.h>
#include <math.h>
#include <cstdint>

// Problem constants (fixed by the dataset)
#define BATCH   32
#define DIM     4096
#define NH      32
#define NKV     8
#define HD      128
#define NREP    4          // NH / NKV
#define MAXSEQ  4096
#define NQKV    6144       // 4096 (q) + 1024 (k) + 1024 (v)
#define KC      256        // k-chunk for split-K GEMMs
#define NCH     16         // 4096 / KC
#define NSPLIT  8          // KV splits in attention
#define TSPLIT  512        // MAXSEQ / NSPLIT
#define CHT     8          // tokens per warp-chunk (double-buffered)
#define NCHUNK  64         // TSPLIT / CHT

typedef unsigned long long ull;
typedef unsigned int u32;

// Packed f32x2 helpers (Blackwell): FFMA2 only reachable via PTX fma.rn.f32x2
__device__ __forceinline__ ull pk2(float lo, float hi) {
    ull r; asm("mov.b64 %0, {%1, %2};" : "=l"(r) : "f"(lo), "f"(hi)); return r;
}
__device__ __forceinline__ ull fma2(ull a, ull b, ull c) {
    ull d; asm("fma.rn.f32x2 %0, %1, %2, %3;" : "=l"(d) : "l"(a), "l"(b), "l"(c));
    return d;
}
__device__ __forceinline__ void upk2(ull v, float& lo, float& hi) {
    asm("mov.b64 {%0, %1}, %2;" : "=f"(lo), "=f"(hi) : "l"(v));
}

// cp.async helpers
__device__ __forceinline__ u32 smem_u32(const void* p) {
    return (u32)__cvta_generic_to_shared(p);
}
__device__ __forceinline__ void cp16(u32 dst, const void* src) {
    asm volatile("cp.async.cg.shared.global [%0], [%1], 16;" :: "r"(dst), "l"(src));
}
__device__ __forceinline__ void cp_commit() {
    asm volatile("cp.async.commit_group;");
}
template<int N> __device__ __forceinline__ void cp_wait() {
    asm volatile("cp.async.wait_group %0;" :: "n"(N));
}

// Scratch (device globals; no allocation allowed)
__device__ float g_part [NCH * BATCH * NQKV];   // QKV split-K partials
__device__ float g_q    [BATCH * NH * HD];      // rope'd q
__device__ float g_k    [BATCH * NKV * HD];     // rope'd new k
__device__ float g_v    [BATCH * NKV * HD];     // new v
__device__ float g_att  [BATCH * NH * HD];      // attention output
__device__ float g_opart[NCH * BATCH * DIM];    // O-proj split-K partials
// Attention split-KV partials
__device__ float g_pm  [BATCH * NKV * NSPLIT * NREP];
__device__ float g_pl  [BATCH * NKV * NSPLIT * NREP];
__device__ float g_pacc[BATCH * NKV * NSPLIT * NREP * HD];

// ---------------------------------------------------------------------------
// Kernel A: QKV projection, split-K, packed f32x2 FMA. grid (48,16), block 128.
// ---------------------------------------------------------------------------
__global__ __launch_bounds__(128)
void qkv_gemm(const float* __restrict__ x,
              const float* __restrict__ wq,
              const float* __restrict__ wk,
              const float* __restrict__ wv)
{
    __shared__ float xs[BATCH * KC];   // 32 KB
    const int tx = threadIdx.x;
    const int bx = blockIdx.x;
    const int by = blockIdx.y;
    const int k0 = by * KC;

    #pragma unroll
    for (int i = 0; i < 16; i++) {
        int s  = tx + i * 128;
        int b  = s >> 6;
        int k4 = s & 63;
        float4 v = *(const float4*)&x[b * DIM + k0 + k4 * 4];
        *(float4*)&xs[b * KC + k4 * 4] = v;
    }
    __syncthreads();

    const int q  = tx & 31;
    const int g  = tx >> 5;
    const int b0 = g * 8;
    const int gcol = bx * 128 + q * 4;

    const float* w; int ncols; int wcol;
    if (gcol < 4096)      { w = wq; ncols = 4096; wcol = gcol; }
    else if (gcol < 5120) { w = wk; ncols = 1024; wcol = gcol - 4096; }
    else                  { w = wv; ncols = 1024; wcol = gcol - 5120; }
    const float* wp = w + (size_t)k0 * ncols + wcol;

    ull acc01[8], acc23[8];
    #pragma unroll
    for (int i = 0; i < 8; i++) { acc01[i] = 0ULL; acc23[i] = 0ULL; }

    for (int kk = 0; kk < KC; kk += 4) {
        float xv[8][4];
        #pragma unroll
        for (int i = 0; i < 8; i++) {
            float4 t4 = *(const float4*)&xs[(b0 + i) * KC + kk];
            xv[i][0] = t4.x; xv[i][1] = t4.y; xv[i][2] = t4.z; xv[i][3] = t4.w;
        }
        #pragma unroll
        for (int j = 0; j < 4; j++) {
            float4 w4 = *(const float4*)&wp[(size_t)(kk + j) * ncols];
            ull w01 = pk2(w4.x, w4.y);
            ull w23 = pk2(w4.z, w4.w);
            #pragma unroll
            for (int i = 0; i < 8; i++) {
                ull xp = pk2(xv[i][j], xv[i][j]);
                acc01[i] = fma2(xp, w01, acc01[i]);
                acc23[i] = fma2(xp, w23, acc23[i]);
            }
        }
    }

    #pragma unroll
    for (int i = 0; i < 8; i++) {
        float4 r;
        upk2(acc01[i], r.x, r.y);
        upk2(acc23[i], r.z, r.w);
        *(float4*)&g_part[((size_t)by * BATCH + b0 + i) * NQKV + gcol] = r;
    }
}

// ---------------------------------------------------------------------------
// Kernel B: reduce split-K partials + RoPE -> g_q, g_k, g_v.
// ---------------------------------------------------------------------------
__global__ __launch_bounds__(256)
void rope_reduce(const float* __restrict__ fcos, const float* __restrict__ fsin)
{
    int idx = blockIdx.x * 256 + threadIdx.x;
    int b = idx / (NQKV / 2);
    int p = idx % (NQKV / 2);
    int col = 2 * p;

    float v0 = 0.f, v1 = 0.f;
    #pragma unroll
    for (int c = 0; c < NCH; c++) {
        float2 t = *(const float2*)&g_part[((size_t)c * BATCH + b) * NQKV + col];
        v0 += t.x; v1 += t.y;
    }

    if (col < 4096) {
        int d = col & (HD - 1);
        int dp = d >> 1;
        float c = fcos[dp], s = fsin[dp];
        g_q[b * 4096 + col]     = v0 * c - v1 * s;
        g_q[b * 4096 + col + 1] = v0 * s + v1 * c;
    } else if (col < 5120) {
        int cc = col - 4096;
        int d = cc & (HD - 1);
        int dp = d >> 1;
        float c = fcos[dp], s = fsin[dp];
        g_k[b * 1024 + cc]     = v0 * c - v1 * s;
        g_k[b * 1024 + cc + 1] = v0 * s + v1 * c;
    } else {
        int cc = col - 5120;
        g_v[b * 1024 + cc]     = v0;
        g_v[b * 1024 + cc + 1] = v1;
    }
}

// ---------------------------------------------------------------------------
// Probe pad: shifts qkv_gemm into the ncu capture slot (4th launch). No-op.
// ---------------------------------------------------------------------------
__global__ void probe_pad() {}

// ---------------------------------------------------------------------------
// Kernel C: flash-decode GQA attention, cp.async double-buffered K pipeline.
// grid (NKV, BATCH, NSPLIT), block 256 (8 warps), warp-autonomous.
// __launch_bounds__(256,3): cap regs at 85 so 3 blocks/SM fit (was 87 -> 2
// blocks, occ 24% -- register-limited per R11 ncu). +50% warps to hide DRAM.
// ---------------------------------------------------------------------------
__global__ __launch_bounds__(256, 3)
void attention(const float* __restrict__ cache_k,
               const float* __restrict__ cache_v,
               const int* __restrict__ start_pos)
{
    __shared__ float4 ksm[8][2][CHT][32];     // 64 KB; reused for acc merge
    __shared__ float  qsm[4 * HD];            // 2 KB
    __shared__ float  psm[8][CHT * 4];        // 1 KB, warp-private
    __shared__ float  msm[8][NREP], lsm[8][NREP];

    const int hh  = blockIdx.x;               // kv head
    const int b   = blockIdx.y;
    const int spl = blockIdx.z;
    const int tx  = threadIdx.x;
    const int w   = tx >> 5;
    const int l   = tx & 31;
    const int tok = l & 7;                    // token within chunk
    const int qr  = l >> 3;                   // dim quarter (32 dims each)

    const int sp = *start_pos;                // 4095
    const int t0 = spl * TSPLIT;

    const float qscale = 1.4426950408889634f * 0.08838834764831845f;
    #pragma unroll
    for (int r = 0; r < 2; r++) {
        int o = tx + r * 256;
        qsm[o] = g_q[b * 4096 + (hh * NREP) * HD + o] * qscale;
    }
    __syncthreads();

    float m0 = -1e30f, m1 = -1e30f, m2 = -1e30f, m3 = -1e30f;
    float ls0 = 0.f, ls1 = 0.f, ls2 = 0.f, ls3 = 0.f;
    float acc[NREP][4];
    #pragma unroll
    for (int qi = 0; qi < NREP; qi++)
        #pragma unroll
        for (int j = 0; j < 4; j++) acc[qi][j] = 0.f;

    const size_t kv_bh = (size_t)b * MAXSEQ * NKV * HD + hh * HD;
    const float* gk = &g_k[(b * NKV + hh) * HD];
    const float* gv = &g_v[(b * NKV + hh) * HD];

    const u32 kbase = smem_u32(&ksm[w][0][0][0]);

    // stage chunk c into buffer buf via cp.async (1 row per lane-iteration)
    auto stage = [&](int c, int buf) {
        const int tb = t0 + c * CHT;
        #pragma unroll
        for (int r = 0; r < CHT; r++) {
            int tg = tb + r;
            const float* krow = (tg == sp) ? gk
                                           : cache_k + kv_bh + (size_t)tg * (NKV * HD);
            cp16(kbase + (u32)(((buf * CHT + r) * 32 + (l ^ r)) * 16),
                 krow + l * 4);
        }
        cp_commit();
    };

    // prologue: prefetch first chunk
    stage(w, 0);

    for (int j = 0; j < NCHUNK / 8; j++) {
        const int c  = w + j * 8;
        const int tb = t0 + c * CHT;
        const int buf = j & 1;

        if (j < NCHUNK / 8 - 1) { stage(c + 8, buf ^ 1); cp_wait<1>(); }
        else                    { cp_wait<0>(); }
        __syncwarp();

        // ---- score: lane = (token, quarter), 32 dims each ----
        float s0 = 0.f, s1 = 0.f, s2 = 0.f, s3 = 0.f;
        #pragma unroll
        for (int i = 0; i < 8; i++) {
            int col = qr * 8 + i;
            float4 k4 = ksm[w][buf][tok][col ^ tok];
            float4 q0 = *(const float4*)&qsm[0 * HD + col * 4];
            float4 q1 = *(const float4*)&qsm[1 * HD + col * 4];
            float4 q2 = *(const float4*)&qsm[2 * HD + col * 4];
            float4 q3 = *(const float4*)&qsm[3 * HD + col * 4];
            s0 += k4.x*q0.x + k4.y*q0.y + k4.z*q0.z + k4.w*q0.w;
            s1 += k4.x*q1.x + k4.y*q1.y + k4.z*q1.z + k4.w*q1.w;
            s2 += k4.x*q2.x + k4.y*q2.y + k4.z*q2.z + k4.w*q2.w;
            s3 += k4.x*q3.x + k4.y*q3.y + k4.z*q3.z + k4.w*q3.w;
        }
        // combine quarters (lanes differing in bits 3,4 hold partials)
        s0 += __shfl_xor_sync(0xffffffffu, s0, 8);
        s1 += __shfl_xor_sync(0xffffffffu, s1, 8);
        s2 += __shfl_xor_sync(0xffffffffu, s2, 8);
        s3 += __shfl_xor_sync(0xffffffffu, s3, 8);
        s0 += __shfl_xor_sync(0xffffffffu, s0, 16);
        s1 += __shfl_xor_sync(0xffffffffu, s1, 16);
        s2 += __shfl_xor_sync(0xffffffffu, s2, 16);
        s3 += __shfl_xor_sync(0xffffffffu, s3, 16);
        if (tb + tok > sp) { s0 = -1e30f; s1 = -1e30f; s2 = -1e30f; s3 = -1e30f; }

        // ---- chunk max over the 8 tokens (lane bits 0-2) ----
        float c0 = s0, c1 = s1, c2 = s2, c3 = s3;
        #pragma unroll
        for (int off = 4; off > 0; off >>= 1) {
            c0 = fmaxf(c0, __shfl_xor_sync(0xffffffffu, c0, off));
            c1 = fmaxf(c1, __shfl_xor_sync(0xffffffffu, c1, off));
            c2 = fmaxf(c2, __shfl_xor_sync(0xffffffffu, c2, off));
            c3 = fmaxf(c3, __shfl_xor_sync(0xffffffffu, c3, off));
        }
        if (c0 > m0) { float a = exp2f(m0 - c0); ls0 *= a;
            acc[0][0]*=a; acc[0][1]*=a; acc[0][2]*=a; acc[0][3]*=a; m0 = c0; }
        if (c1 > m1) { float a = exp2f(m1 - c1); ls1 *= a;
            acc[1][0]*=a; acc[1][1]*=a; acc[1][2]*=a; acc[1][3]*=a; m1 = c1; }
        if (c2 > m2) { float a = exp2f(m2 - c2); ls2 *= a;
            acc[2][0]*=a; acc[2][1]*=a; acc[2][2]*=a; acc[2][3]*=a; m2 = c2; }
        if (c3 > m3) { float a = exp2f(m3 - c3); ls3 *= a;
            acc[3][0]*=a; acc[3][1]*=a; acc[3][2]*=a; acc[3][3]*=a; m3 = c3; }

        float p0 = exp2f(s0 - m0), p1 = exp2f(s1 - m1);
        float p2 = exp2f(s2 - m2), p3 = exp2f(s3 - m3);
        if (qr == 0) {                        // one lane per token owns p
            ls0 += p0; ls1 += p1; ls2 += p2; ls3 += p3;
            *(float4*)&psm[w][tok * 4] = make_float4(p0, p1, p2, p3);
        }
        __syncwarp();

        // ---- V: lane = dim-quad, coalesced; p broadcast from smem ----
        const float* vlane = cache_v + kv_bh + l * 4;
        #pragma unroll
        for (int tt = 0; tt < CHT; tt++) {
            int tg = tb + tt;
            const float* vp = (tg == sp) ? gv + l * 4
                                         : vlane + (size_t)tg * (NKV * HD);
            float4 v4 = *(const float4*)vp;
            float4 p4 = *(const float4*)&psm[w][tt * 4];
            acc[0][0] += p4.x*v4.x; acc[0][1] += p4.x*v4.y; acc[0][2] += p4.x*v4.z; acc[0][3] += p4.x*v4.w;
            acc[1][0] += p4.y*v4.x; acc[1][1] += p4.y*v4.y; acc[1][2] += p4.y*v4.z; acc[1][3] += p4.y*v4.w;
            acc[2][0] += p4.z*v4.x; acc[2][1] += p4.z*v4.y; acc[2][2] += p4.z*v4.z; acc[2][3] += p4.z*v4.w;
            acc[3][0] += p4.w*v4.x; acc[3][1] += p4.w*v4.y; acc[3][2] += p4.w*v4.z; acc[3][3] += p4.w*v4.w;
        }
        __syncwarp();
    }

    // ---- lane-reduce lsums (only qr==0 lanes hold nonzero partials) ----
    #pragma unroll
    for (int off = 16; off > 0; off >>= 1) {
        ls0 += __shfl_xor_sync(0xffffffffu, ls0, off);
        ls1 += __shfl_xor_sync(0xffffffffu, ls1, off);
        ls2 += __shfl_xor_sync(0xffffffffu, ls2, off);
        ls3 += __shfl_xor_sync(0xffffffffu, ls3, off);
    }

    // ---- store warp partials (reuse ksm region for accs) ----
    __syncthreads();                          // all warps done with ksm
    float* accs = (float*)ksm;                // [8][NREP][HD]
    #pragma unroll
    for (int qi = 0; qi < NREP; qi++)
        *(float4*)&accs[(w * NREP + qi) * HD + l * 4] =
            make_float4(acc[qi][0], acc[qi][1], acc[qi][2], acc[qi][3]);
    if (l == 0) {
        msm[w][0] = m0; msm[w][1] = m1; msm[w][2] = m2; msm[w][3] = m3;
        lsm[w][0] = ls0; lsm[w][1] = ls1; lsm[w][2] = ls2; lsm[w][3] = ls3;
    }
    __syncthreads();

    // ---- block merge across 8 warps ----
    #pragma unroll
    for (int r = 0; r < 2; r++) {
        int o  = tx + r * 256;
        int qi = o >> 7;
        int d  = o & (HD - 1);
        float M = msm[0][qi];
        #pragma unroll
        for (int w2 = 1; w2 < 8; w2++) M = fmaxf(M, msm[w2][qi]);
        float num = 0.f, den = 0.f;
        #pragma unroll
        for (int w2 = 0; w2 < 8; w2++) {
            float wgt = exp2f(msm[w2][qi] - M);
            num += wgt * accs[(w2 * NREP + qi) * HD + d];
            den += wgt * lsm[w2][qi];
        }
        int pbase = ((b * NKV + hh) * NSPLIT + spl) * NREP + qi;
        g_pacc[(size_t)pbase * HD + d] = num;
        if (d == 0) { g_pl[pbase] = den; g_pm[pbase] = M; }
    }
}

// ---------------------------------------------------------------------------
// Kernel C2: merge the NSPLIT partials -> g_att. grid 256, block 512.
// ---------------------------------------------------------------------------
__global__ __launch_bounds__(512)
void att_merge()
{
    const int bh = blockIdx.x;
    const int o  = threadIdx.x;
    const int qi = o >> 7;
    const int d  = o & (HD - 1);
    const int base = bh * NSPLIT * NREP + qi;

    float M = -1e30f;
    #pragma unroll
    for (int s = 0; s < NSPLIT; s++) M = fmaxf(M, g_pm[base + s * NREP]);
    float num = 0.f, den = 0.f;
    #pragma unroll
    for (int s = 0; s < NSPLIT; s++) {
        int p = base + s * NREP;
        float wgt = exp2f(g_pm[p] - M);
        num += wgt * g_pacc[(size_t)p * HD + d];
        den += wgt * g_pl[p];
    }
    const int b = bh >> 3, h = bh & 7;
    g_att[b * 4096 + (h * NREP + qi) * HD + d] = num / den;
}

// ---------------------------------------------------------------------------
// Kernel D: output projection, split-K, packed f32x2 FMA. grid (32,16), 128.
// ---------------------------------------------------------------------------
__global__ __launch_bounds__(128)
void o_gemm(const float* __restrict__ wo)
{
    __shared__ float xs[BATCH * KC];
    const int tx = threadIdx.x;
    const int bx = blockIdx.x;
    const int by = blockIdx.y;
    const int k0 = by * KC;

    #pragma unroll
    for (int i = 0; i < 16; i++) {
        int s  = tx + i * 128;
        int b  = s >> 6;
        int k4 = s & 63;
        float4 v = *(const float4*)&g_att[b * DIM + k0 + k4 * 4];
        *(float4*)&xs[b * KC + k4 * 4] = v;
    }
    __syncthreads();

    const int q  = tx & 31;
    const int g  = tx >> 5;
    const int b0 = g * 8;
    const int gcol = bx * 128 + q * 4;
    const float* wp = wo + (size_t)k0 * DIM + gcol;

    ull acc01[8], acc23[8];
    #pragma unroll
    for (int i = 0; i < 8; i++) { acc01[i] = 0ULL; acc23[i] = 0ULL; }

    for (int kk = 0; kk < KC; kk += 4) {
        float xv[8][4];
        #pragma unroll
        for (int i = 0; i < 8; i++) {
            float4 t4 = *(const float4*)&xs[(b0 + i) * KC + kk];
            xv[i][0] = t4.x; xv[i][1] = t4.y; xv[i][2] = t4.z; xv[i][3] = t4.w;
        }
        #pragma unroll
        for (int j = 0; j < 4; j++) {
            float4 w4 = *(const float4*)&wp[(size_t)(kk + j) * DIM];
            ull w01 = pk2(w4.x, w4.y);
            ull w23 = pk2(w4.z, w4.w);
            #pragma unroll
            for (int i = 0; i < 8; i++) {
                ull xp = pk2(xv[i][j], xv[i][j]);
                acc01[i] = fma2(xp, w01, acc01[i]);
                acc23[i] = fma2(xp, w23, acc23[i]);
            }
        }
    }

    #pragma unroll
    for (int i = 0; i < 8; i++) {
        float4 r;
        upk2(acc01[i], r.x, r.y);
        upk2(acc23[i], r.z, r.w);
        *(float4*)&g_opart[((size_t)by * BATCH + b0 + i) * DIM + gcol] = r;
    }
}

// ---------------------------------------------------------------------------
// Kernel E: reduce O partials -> d_out
// ---------------------------------------------------------------------------
__global__ __launch_bounds__(256)
void o_reduce(float* __restrict__ out)
{
    int idx = blockIdx.x * 256 + threadIdx.x;
    float v = 0.f;
    #pragma unroll
    for (int c = 0; c < NCH; c++)
        v += g_opart[(size_t)c * (BATCH * DIM) + idx];
    out[idx] = v;
}

// ---------------------------------------------------------------------------
extern "C" void kernel_launch(void* const* d_in, const int* in_sizes, int n_in,
                              void* d_out, int out_size)
{
    const float* x        = (const float*)d_in[0];
    const float* cache_k  = (const float*)d_in[1];
    const float* cache_v  = (const float*)d_in[2];
    const float* fcos     = (const float*)d_in[3];
    const float* fsin     = (const float*)d_in[4];
    const float* wq       = (const float*)d_in[5];
    const float* wk       = (const float*)d_in[6];
    const float* wv       = (const float*)d_in[7];
    const float* wo       = (const float*)d_in[8];
    const int*   sp       = (const int*)d_in[9];
    float* out            = (float*)d_out;

    // 3 probes shift qkv_gemm into the 4th-launch ncu capture slot
    probe_pad<<<1, 32>>>();
    probe_pad<<<1, 32>>>();
    probe_pad<<<1, 32>>>();
    qkv_gemm<<<dim3(48, 16), 128>>>(x, wq, wk, wv);
    rope_reduce<<<(BATCH * (NQKV / 2)) / 256, 256>>>(fcos, fsin);
    attention<<<dim3(NKV, BATCH, NSPLIT), 256>>>(cache_k, cache_v, sp);
    att_merge<<<BATCH * NKV, 512>>>();
    o_gemm<<<dim3(32, 16), 128>>>(wo);
    o_reduce<<<(BATCH * DIM) / 256, 256>>>(out);
}

// round 13
// speedup vs baseline: 1.7692x; 1.2198x over previous
#include <cuda_runtime.h>
#include <cuda_bf16.h>
#include <math.h>
#include <cstdint>

// Problem constants (fixed by the dataset)
#define BATCH   32
#define DIM     4096
#define NH      32
#define NKV     8
#define HD      128
#define NREP    4          // NH / NKV
#define MAXSEQ  4096
#define NQKV    6144       // 4096 (q) + 1024 (k) + 1024 (v)
#define KC      256        // k-chunk for split-K GEMMs
#define NCH     16         // 4096 / KC
#define NSPLIT  8          // KV splits in attention
#define TSPLIT  512        // MAXSEQ / NSPLIT
#define CHT     8          // tokens per warp-chunk (double-buffered)
#define NCHUNK  64         // TSPLIT / CHT
#define WR      8          // weight rows per cp.async stage
#define NWST    (KC / WR)  // 32 stages per k-chunk

typedef unsigned long long ull;
typedef unsigned int u32;

// Packed f32x2 helpers (Blackwell): FFMA2 only reachable via PTX fma.rn.f32x2
__device__ __forceinline__ ull pk2(float lo, float hi) {
    ull r; asm("mov.b64 %0, {%1, %2};" : "=l"(r) : "f"(lo), "f"(hi)); return r;
}
__device__ __forceinline__ ull fma2(ull a, ull b, ull c) {
    ull d; asm("fma.rn.f32x2 %0, %1, %2, %3;" : "=l"(d) : "l"(a), "l"(b), "l"(c));
    return d;
}
__device__ __forceinline__ void upk2(ull v, float& lo, float& hi) {
    asm("mov.b64 {%0, %1}, %2;" : "=f"(lo), "=f"(hi) : "l"(v));
}

// cp.async helpers
__device__ __forceinline__ u32 smem_u32(const void* p) {
    return (u32)__cvta_generic_to_shared(p);
}
__device__ __forceinline__ void cp16(u32 dst, const void* src) {
    asm volatile("cp.async.cg.shared.global [%0], [%1], 16;" :: "r"(dst), "l"(src));
}
__device__ __forceinline__ void cp_commit() {
    asm volatile("cp.async.commit_group;");
}
template<int N> __device__ __forceinline__ void cp_wait() {
    asm volatile("cp.async.wait_group %0;" :: "n"(N));
}

// Scratch (device globals; no allocation allowed)
__device__ float g_part [NCH * BATCH * NQKV];   // QKV split-K partials
__device__ float g_q    [BATCH * NH * HD];      // rope'd q
__device__ float g_k    [BATCH * NKV * HD];     // rope'd new k
__device__ float g_v    [BATCH * NKV * HD];     // new v
__device__ float g_att  [BATCH * NH * HD];      // attention output
__device__ float g_opart[NCH * BATCH * DIM];    // O-proj split-K partials
// Attention split-KV partials
__device__ float g_pm  [BATCH * NKV * NSPLIT * NREP];
__device__ float g_pl  [BATCH * NKV * NSPLIT * NREP];
__device__ float g_pacc[BATCH * NKV * NSPLIT * NREP * HD];

// ---------------------------------------------------------------------------
// Kernel A: QKV projection, split-K, packed f32x2 FMA, cp.async-staged
// weights. grid (48,16), block 128. R12 ncu showed LDG-latency-bound
// (fma 23%, dram 15%, issue 20%): weights now stream through a 4-buffer
// 8-row smem pipeline, 3 stages in flight.
// ---------------------------------------------------------------------------
__global__ __launch_bounds__(128)
void qkv_gemm(const float* __restrict__ x,
              const float* __restrict__ wq,
              const float* __restrict__ wk,
              const float* __restrict__ wv)
{
    __shared__ float xs[BATCH * KC];      // 32 KB
    __shared__ float wsm[4][WR][128];     // 16 KB weight stages
    const int tx = threadIdx.x;
    const int bx = blockIdx.x;
    const int by = blockIdx.y;
    const int k0 = by * KC;

    #pragma unroll
    for (int i = 0; i < 16; i++) {
        int s  = tx + i * 128;
        int b  = s >> 6;
        int k4 = s & 63;
        float4 v = *(const float4*)&x[b * DIM + k0 + k4 * 4];
        *(float4*)&xs[b * KC + k4 * 4] = v;
    }

    const int q  = tx & 31;
    const int g  = tx >> 5;
    const int b0 = g * 8;
    const int gcol = bx * 128 + q * 4;

    const float* w; int ncols; int colbase;
    if (bx < 32)      { w = wq; ncols = 4096; colbase = bx * 128; }
    else if (bx < 40) { w = wk; ncols = 1024; colbase = (bx - 32) * 128; }
    else              { w = wv; ncols = 1024; colbase = (bx - 40) * 128; }

    const u32 wsb = smem_u32(&wsm[0][0][0]);
    // stage st (8 weight rows) into buffer buf; 128 threads x 2 rows-of-4
    auto stagew = [&](int st, int buf) {
        #pragma unroll
        for (int i = 0; i < 2; i++) {
            int r = g + i * 4;
            cp16(wsb + (u32)(((buf * WR + r) * 128 + q * 4) * 4),
                 w + (size_t)(k0 + st * WR + r) * ncols + colbase + q * 4);
        }
        cp_commit();
    };

    stagew(0, 0); stagew(1, 1); stagew(2, 2);
    __syncthreads();                      // xs ready

    ull acc01[8], acc23[8];
    #pragma unroll
    for (int i = 0; i < 8; i++) { acc01[i] = 0ULL; acc23[i] = 0ULL; }

    for (int st = 0; st < NWST; st++) {
        const int buf = st & 3;
        cp_wait<2>();                     // group st complete
        __syncthreads();

        #pragma unroll
        for (int rr = 0; rr < 2; rr++) {
            const int kk = st * WR + rr * 4;
            float xv[8][4];
            #pragma unroll
            for (int i = 0; i < 8; i++) {
                float4 t4 = *(const float4*)&xs[(b0 + i) * KC + kk];
                xv[i][0] = t4.x; xv[i][1] = t4.y; xv[i][2] = t4.z; xv[i][3] = t4.w;
            }
            #pragma unroll
            for (int j = 0; j < 4; j++) {
                float4 w4 = *(const float4*)&wsm[buf][rr * 4 + j][q * 4];
                ull w01 = pk2(w4.x, w4.y);
                ull w23 = pk2(w4.z, w4.w);
                #pragma unroll
                for (int i = 0; i < 8; i++) {
                    ull xp = pk2(xv[i][j], xv[i][j]);
                    acc01[i] = fma2(xp, w01, acc01[i]);
                    acc23[i] = fma2(xp, w23, acc23[i]);
                }
            }
        }
        __syncthreads();                  // done reading buf before restage
        if (st + 3 < NWST) stagew(st + 3, (st + 3) & 3);
        else               cp_commit();   // empty group keeps wait<2> exact
    }

    #pragma unroll
    for (int i = 0; i < 8; i++) {
        float4 r;
        upk2(acc01[i], r.x, r.y);
        upk2(acc23[i], r.z, r.w);
        *(float4*)&g_part[((size_t)by * BATCH + b0 + i) * NQKV + gcol] = r;
    }
}

// ---------------------------------------------------------------------------
// Kernel B: reduce split-K partials + RoPE -> g_q, g_k, g_v.
// ---------------------------------------------------------------------------
__global__ __launch_bounds__(256)
void rope_reduce(const float* __restrict__ fcos, const float* __restrict__ fsin)
{
    int idx = blockIdx.x * 256 + threadIdx.x;
    int b = idx / (NQKV / 2);
    int p = idx % (NQKV / 2);
    int col = 2 * p;

    float v0 = 0.f, v1 = 0.f;
    #pragma unroll
    for (int c = 0; c < NCH; c++) {
        float2 t = *(const float2*)&g_part[((size_t)c * BATCH + b) * NQKV + col];
        v0 += t.x; v1 += t.y;
    }

    if (col < 4096) {
        int d = col & (HD - 1);
        int dp = d >> 1;
        float c = fcos[dp], s = fsin[dp];
        g_q[b * 4096 + col]     = v0 * c - v1 * s;
        g_q[b * 4096 + col + 1] = v0 * s + v1 * c;
    } else if (col < 5120) {
        int cc = col - 4096;
        int d = cc & (HD - 1);
        int dp = d >> 1;
        float c = fcos[dp], s = fsin[dp];
        g_k[b * 1024 + cc]     = v0 * c - v1 * s;
        g_k[b * 1024 + cc + 1] = v0 * s + v1 * c;
    } else {
        int cc = col - 5120;
        g_v[b * 1024 + cc]     = v0;
        g_v[b * 1024 + cc + 1] = v1;
    }
}

// ---------------------------------------------------------------------------
// Probe pad: shifts qkv_gemm into the ncu capture slot (4th launch). No-op.
// ---------------------------------------------------------------------------
__global__ void probe_pad() {}

// ---------------------------------------------------------------------------
// Kernel C: flash-decode GQA attention, cp.async double-buffered K pipeline.
// (unchanged from R12 winner)
// ---------------------------------------------------------------------------
__global__ __launch_bounds__(256, 3)
void attention(const float* __restrict__ cache_k,
               const float* __restrict__ cache_v,
               const int* __restrict__ start_pos)
{
    __shared__ float4 ksm[8][2][CHT][32];     // 64 KB; reused for acc merge
    __shared__ float  qsm[4 * HD];            // 2 KB
    __shared__ float  psm[8][CHT * 4];        // 1 KB, warp-private
    __shared__ float  msm[8][NREP], lsm[8][NREP];

    const int hh  = blockIdx.x;               // kv head
    const int b   = blockIdx.y;
    const int spl = blockIdx.z;
    const int tx  = threadIdx.x;
    const int w   = tx >> 5;
    const int l   = tx & 31;
    const int tok = l & 7;                    // token within chunk
    const int qr  = l >> 3;                   // dim quarter (32 dims each)

    const int sp = *start_pos;                // 4095
    const int t0 = spl * TSPLIT;

    const float qscale = 1.4426950408889634f * 0.08838834764831845f;
    #pragma unroll
    for (int r = 0; r < 2; r++) {
        int o = tx + r * 256;
        qsm[o] = g_q[b * 4096 + (hh * NREP) * HD + o] * qscale;
    }
    __syncthreads();

    float m0 = -1e30f, m1 = -1e30f, m2 = -1e30f, m3 = -1e30f;
    float ls0 = 0.f, ls1 = 0.f, ls2 = 0.f, ls3 = 0.f;
    float acc[NREP][4];
    #pragma unroll
    for (int qi = 0; qi < NREP; qi++)
        #pragma unroll
        for (int j = 0; j < 4; j++) acc[qi][j] = 0.f;

    const size_t kv_bh = (size_t)b * MAXSEQ * NKV * HD + hh * HD;
    const float* gk = &g_k[(b * NKV + hh) * HD];
    const float* gv = &g_v[(b * NKV + hh) * HD];

    const u32 kbase = smem_u32(&ksm[w][0][0][0]);

    auto stage = [&](int c, int buf) {
        const int tb = t0 + c * CHT;
        #pragma unroll
        for (int r = 0; r < CHT; r++) {
            int tg = tb + r;
            const float* krow = (tg == sp) ? gk
                                           : cache_k + kv_bh + (size_t)tg * (NKV * HD);
            cp16(kbase + (u32)(((buf * CHT + r) * 32 + (l ^ r)) * 16),
                 krow + l * 4);
        }
        cp_commit();
    };

    stage(w, 0);

    for (int j = 0; j < NCHUNK / 8; j++) {
        const int c  = w + j * 8;
        const int tb = t0 + c * CHT;
        const int buf = j & 1;

        if (j < NCHUNK / 8 - 1) { stage(c + 8, buf ^ 1); cp_wait<1>(); }
        else                    { cp_wait<0>(); }
        __syncwarp();

        float s0 = 0.f, s1 = 0.f, s2 = 0.f, s3 = 0.f;
        #pragma unroll
        for (int i = 0; i < 8; i++) {
            int col = qr * 8 + i;
            float4 k4 = ksm[w][buf][tok][col ^ tok];
            float4 q0 = *(const float4*)&qsm[0 * HD + col * 4];
            float4 q1 = *(const float4*)&qsm[1 * HD + col * 4];
            float4 q2 = *(const float4*)&qsm[2 * HD + col * 4];
            float4 q3 = *(const float4*)&qsm[3 * HD + col * 4];
            s0 += k4.x*q0.x + k4.y*q0.y + k4.z*q0.z + k4.w*q0.w;
            s1 += k4.x*q1.x + k4.y*q1.y + k4.z*q1.z + k4.w*q1.w;
            s2 += k4.x*q2.x + k4.y*q2.y + k4.z*q2.z + k4.w*q2.w;
            s3 += k4.x*q3.x + k4.y*q3.y + k4.z*q3.z + k4.w*q3.w;
        }
        s0 += __shfl_xor_sync(0xffffffffu, s0, 8);
        s1 += __shfl_xor_sync(0xffffffffu, s1, 8);
        s2 += __shfl_xor_sync(0xffffffffu, s2, 8);
        s3 += __shfl_xor_sync(0xffffffffu, s3, 8);
        s0 += __shfl_xor_sync(0xffffffffu, s0, 16);
        s1 += __shfl_xor_sync(0xffffffffu, s1, 16);
        s2 += __shfl_xor_sync(0xffffffffu, s2, 16);
        s3 += __shfl_xor_sync(0xffffffffu, s3, 16);
        if (tb + tok > sp) { s0 = -1e30f; s1 = -1e30f; s2 = -1e30f; s3 = -1e30f; }

        float c0 = s0, c1 = s1, c2 = s2, c3 = s3;
        #pragma unroll
        for (int off = 4; off > 0; off >>= 1) {
            c0 = fmaxf(c0, __shfl_xor_sync(0xffffffffu, c0, off));
            c1 = fmaxf(c1, __shfl_xor_sync(0xffffffffu, c1, off));
            c2 = fmaxf(c2, __shfl_xor_sync(0xffffffffu, c2, off));
            c3 = fmaxf(c3, __shfl_xor_sync(0xffffffffu, c3, off));
        }
        if (c0 > m0) { float a = exp2f(m0 - c0); ls0 *= a;
            acc[0][0]*=a; acc[0][1]*=a; acc[0][2]*=a; acc[0][3]*=a; m0 = c0; }
        if (c1 > m1) { float a = exp2f(m1 - c1); ls1 *= a;
            acc[1][0]*=a; acc[1][1]*=a; acc[1][2]*=a; acc[1][3]*=a; m1 = c1; }
        if (c2 > m2) { float a = exp2f(m2 - c2); ls2 *= a;
            acc[2][0]*=a; acc[2][1]*=a; acc[2][2]*=a; acc[2][3]*=a; m2 = c2; }
        if (c3 > m3) { float a = exp2f(m3 - c3); ls3 *= a;
            acc[3][0]*=a; acc[3][1]*=a; acc[3][2]*=a; acc[3][3]*=a; m3 = c3; }

        float p0 = exp2f(s0 - m0), p1 = exp2f(s1 - m1);
        float p2 = exp2f(s2 - m2), p3 = exp2f(s3 - m3);
        if (qr == 0) {
            ls0 += p0; ls1 += p1; ls2 += p2; ls3 += p3;
            *(float4*)&psm[w][tok * 4] = make_float4(p0, p1, p2, p3);
        }
        __syncwarp();

        const float* vlane = cache_v + kv_bh + l * 4;
        #pragma unroll
        for (int tt = 0; tt < CHT; tt++) {
            int tg = tb + tt;
            const float* vp = (tg == sp) ? gv + l * 4
                                         : vlane + (size_t)tg * (NKV * HD);
            float4 v4 = *(const float4*)vp;
            float4 p4 = *(const float4*)&psm[w][tt * 4];
            acc[0][0] += p4.x*v4.x; acc[0][1] += p4.x*v4.y; acc[0][2] += p4.x*v4.z; acc[0][3] += p4.x*v4.w;
            acc[1][0] += p4.y*v4.x; acc[1][1] += p4.y*v4.y; acc[1][2] += p4.y*v4.z; acc[1][3] += p4.y*v4.w;
            acc[2][0] += p4.z*v4.x; acc[2][1] += p4.z*v4.y; acc[2][2] += p4.z*v4.z; acc[2][3] += p4.z*v4.w;
            acc[3][0] += p4.w*v4.x; acc[3][1] += p4.w*v4.y; acc[3][2] += p4.w*v4.z; acc[3][3] += p4.w*v4.w;
        }
        __syncwarp();
    }

    #pragma unroll
    for (int off = 16; off > 0; off >>= 1) {
        ls0 += __shfl_xor_sync(0xffffffffu, ls0, off);
        ls1 += __shfl_xor_sync(0xffffffffu, ls1, off);
        ls2 += __shfl_xor_sync(0xffffffffu, ls2, off);
        ls3 += __shfl_xor_sync(0xffffffffu, ls3, off);
    }

    __syncthreads();
    float* accs = (float*)ksm;                // [8][NREP][HD]
    #pragma unroll
    for (int qi = 0; qi < NREP; qi++)
        *(float4*)&accs[(w * NREP + qi) * HD + l * 4] =
            make_float4(acc[qi][0], acc[qi][1], acc[qi][2], acc[qi][3]);
    if (l == 0) {
        msm[w][0] = m0; msm[w][1] = m1; msm[w][2] = m2; msm[w][3] = m3;
        lsm[w][0] = ls0; lsm[w][1] = ls1; lsm[w][2] = ls2; lsm[w][3] = ls3;
    }
    __syncthreads();

    #pragma unroll
    for (int r = 0; r < 2; r++) {
        int o  = tx + r * 256;
        int qi = o >> 7;
        int d  = o & (HD - 1);
        float M = msm[0][qi];
        #pragma unroll
        for (int w2 = 1; w2 < 8; w2++) M = fmaxf(M, msm[w2][qi]);
        float num = 0.f, den = 0.f;
        #pragma unroll
        for (int w2 = 0; w2 < 8; w2++) {
            float wgt = exp2f(msm[w2][qi] - M);
            num += wgt * accs[(w2 * NREP + qi) * HD + d];
            den += wgt * lsm[w2][qi];
        }
        int pbase = ((b * NKV + hh) * NSPLIT + spl) * NREP + qi;
        g_pacc[(size_t)pbase * HD + d] = num;
        if (d == 0) { g_pl[pbase] = den; g_pm[pbase] = M; }
    }
}

// ---------------------------------------------------------------------------
// Kernel C2: merge the NSPLIT partials -> g_att. grid 256, block 512.
// ---------------------------------------------------------------------------
__global__ __launch_bounds__(512)
void att_merge()
{
    const int bh = blockIdx.x;
    const int o  = threadIdx.x;
    const int qi = o >> 7;
    const int d  = o & (HD - 1);
    const int base = bh * NSPLIT * NREP + qi;

    float M = -1e30f;
    #pragma unroll
    for (int s = 0; s < NSPLIT; s++) M = fmaxf(M, g_pm[base + s * NREP]);
    float num = 0.f, den = 0.f;
    #pragma unroll
    for (int s = 0; s < NSPLIT; s++) {
        int p = base + s * NREP;
        float wgt = exp2f(g_pm[p] - M);
        num += wgt * g_pacc[(size_t)p * HD + d];
        den += wgt * g_pl[p];
    }
    const int b = bh >> 3, h = bh & 7;
    g_att[b * 4096 + (h * NREP + qi) * HD + d] = num / den;
}

// ---------------------------------------------------------------------------
// Kernel D: output projection, split-K, packed f32x2 FMA, cp.async-staged
// weights (same pipeline as qkv_gemm). grid (32,16), block 128.
// ---------------------------------------------------------------------------
__global__ __launch_bounds__(128)
void o_gemm(const float* __restrict__ wo)
{
    __shared__ float xs[BATCH * KC];      // 32 KB
    __shared__ float wsm[4][WR][128];     // 16 KB
    const int tx = threadIdx.x;
    const int bx = blockIdx.x;
    const int by = blockIdx.y;
    const int k0 = by * KC;

    #pragma unroll
    for (int i = 0; i < 16; i++) {
        int s  = tx + i * 128;
        int b  = s >> 6;
        int k4 = s & 63;
        float4 v = *(const float4*)&g_att[b * DIM + k0 + k4 * 4];
        *(float4*)&xs[b * KC + k4 * 4] = v;
    }

    const int q  = tx & 31;
    const int g  = tx >> 5;
    const int b0 = g * 8;
    const int gcol = bx * 128 + q * 4;
    const int colbase = bx * 128;

    const u32 wsb = smem_u32(&wsm[0][0][0]);
    auto stagew = [&](int st, int buf) {
        #pragma unroll
        for (int i = 0; i < 2; i++) {
            int r = g + i * 4;
            cp16(wsb + (u32)(((buf * WR + r) * 128 + q * 4) * 4),
                 wo + (size_t)(k0 + st * WR + r) * DIM + colbase + q * 4);
        }
        cp_commit();
    };

    stagew(0, 0); stagew(1, 1); stagew(2, 2);
    __syncthreads();

    ull acc01[8], acc23[8];
    #pragma unroll
    for (int i = 0; i < 8; i++) { acc01[i] = 0ULL; acc23[i] = 0ULL; }

    for (int st = 0; st < NWST; st++) {
        const int buf = st & 3;
        cp_wait<2>();
        __syncthreads();

        #pragma unroll
        for (int rr = 0; rr < 2; rr++) {
            const int kk = st * WR + rr * 4;
            float xv[8][4];
            #pragma unroll
            for (int i = 0; i < 8; i++) {
                float4 t4 = *(const float4*)&xs[(b0 + i) * KC + kk];
                xv[i][0] = t4.x; xv[i][1] = t4.y; xv[i][2] = t4.z; xv[i][3] = t4.w;
            }
            #pragma unroll
            for (int j = 0; j < 4; j++) {
                float4 w4 = *(const float4*)&wsm[buf][rr * 4 + j][q * 4];
                ull w01 = pk2(w4.x, w4.y);
                ull w23 = pk2(w4.z, w4.w);
                #pragma unroll
                for (int i = 0; i < 8; i++) {
                    ull xp = pk2(xv[i][j], xv[i][j]);
                    acc01[i] = fma2(xp, w01, acc01[i]);
                    acc23[i] = fma2(xp, w23, acc23[i]);
                }
            }
        }
        __syncthreads();
        if (st + 3 < NWST) stagew(st + 3, (st + 3) & 3);
        else               cp_commit();
    }

    #pragma unroll
    for (int i = 0; i < 8; i++) {
        float4 r;
        upk2(acc01[i], r.x, r.y);
        upk2(acc23[i], r.z, r.w);
        *(float4*)&g_opart[((size_t)by * BATCH + b0 + i) * DIM + gcol] = r;
    }
}

// ---------------------------------------------------------------------------
// Kernel E: reduce O partials -> d_out
// ---------------------------------------------------------------------------
__global__ __launch_bounds__(256)
void o_reduce(float* __restrict__ out)
{
    int idx = blockIdx.x * 256 + threadIdx.x;
    float v = 0.f;
    #pragma unroll
    for (int c = 0; c < NCH; c++)
        v += g_opart[(size_t)c * (BATCH * DIM) + idx];
    out[idx] = v;
}

// ---------------------------------------------------------------------------
extern "C" void kernel_launch(void* const* d_in, const int* in_sizes, int n_in,
                              void* d_out, int out_size)
{
    const float* x        = (const float*)d_in[0];
    const float* cache_k  = (const float*)d_in[1];
    const float* cache_v  = (const float*)d_in[2];
    const float* fcos     = (const float*)d_in[3];
    const float* fsin     = (const float*)d_in[4];
    const float* wq       = (const float*)d_in[5];
    const float* wk       = (const float*)d_in[6];
    const float* wv       = (const float*)d_in[7];
    const float* wo       = (const float*)d_in[8];
    const int*   sp       = (const int*)d_in[9];
    float* out            = (float*)d_out;

    // 3 probes keep qkv_gemm in the 4th-launch ncu capture slot
    probe_pad<<<1, 32>>>();
    probe_pad<<<1, 32>>>();
    probe_pad<<<1, 32>>>();
    qkv_gemm<<<dim3(48, 16), 128>>>(x, wq, wk, wv);
    rope_reduce<<<(BATCH * (NQKV / 2)) / 256, 256>>>(fcos, fsin);
    attention<<<dim3(NKV, BATCH, NSPLIT), 256>>>(cache_k, cache_v, sp);
    att_merge<<<BATCH * NKV, 512>>>();
    o_gemm<<<dim3(32, 16), 128>>>(wo);
    o_reduce<<<(BATCH * DIM) / 256, 256>>>(out);
}

// round 14
// speedup vs baseline: 1.8221x; 1.0299x over previous
#include <cuda_runtime.h>
#include <cuda_bf16.h>
#include <math.h>
#include <cstdint>

// Problem constants (fixed by the dataset)
#define BATCH   32
#define DIM     4096
#define NH      32
#define NKV     8
#define HD      128
#define NREP    4          // NH / NKV
#define MAXSEQ  4096
#define NQKV    6144       // 4096 (q) + 1024 (k) + 1024 (v)
#define KC      256        // k-chunk for split-K GEMMs
#define NCH     16         // 4096 / KC
#define NSPLIT  8          // KV splits in attention
#define TSPLIT  512        // MAXSEQ / NSPLIT
#define CHT     8          // tokens per warp-chunk (double-buffered)
#define NCHUNK  64         // TSPLIT / CHT
#define WR      8          // weight rows per cp.async stage
#define NWST    (KC / WR)  // 32 stages per k-chunk

typedef unsigned long long ull;
typedef unsigned int u32;

// Packed f32x2 helpers (Blackwell): FFMA2 only reachable via PTX fma.rn.f32x2
__device__ __forceinline__ ull pk2(float lo, float hi) {
    ull r; asm("mov.b64 %0, {%1, %2};" : "=l"(r) : "f"(lo), "f"(hi)); return r;
}
__device__ __forceinline__ ull fma2(ull a, ull b, ull c) {
    ull d; asm("fma.rn.f32x2 %0, %1, %2, %3;" : "=l"(d) : "l"(a), "l"(b), "l"(c));
    return d;
}
__device__ __forceinline__ void upk2(ull v, float& lo, float& hi) {
    asm("mov.b64 {%0, %1}, %2;" : "=f"(lo), "=f"(hi) : "l"(v));
}

// cp.async helpers
__device__ __forceinline__ u32 smem_u32(const void* p) {
    return (u32)__cvta_generic_to_shared(p);
}
__device__ __forceinline__ void cp16(u32 dst, const void* src) {
    asm volatile("cp.async.cg.shared.global [%0], [%1], 16;" :: "r"(dst), "l"(src));
}
__device__ __forceinline__ void cp_commit() {
    asm volatile("cp.async.commit_group;");
}
template<int N> __device__ __forceinline__ void cp_wait() {
    asm volatile("cp.async.wait_group %0;" :: "n"(N));
}

// Scratch (device globals; no allocation allowed)
__device__ float g_part [NCH * BATCH * NQKV];   // QKV split-K partials
__device__ float g_q    [BATCH * NH * HD];      // rope'd q
__device__ float g_k    [BATCH * NKV * HD];     // rope'd new k
__device__ float g_v    [BATCH * NKV * HD];     // new v
__device__ float g_att  [BATCH * NH * HD];      // attention output
__device__ float g_opart[NCH * BATCH * DIM];    // O-proj split-K partials
// Attention split-KV partials
__device__ float g_pm  [BATCH * NKV * NSPLIT * NREP];
__device__ float g_pl  [BATCH * NKV * NSPLIT * NREP];
__device__ float g_pacc[BATCH * NKV * NSPLIT * NREP * HD];

// ---------------------------------------------------------------------------
// Kernel A: QKV projection, split-K, packed f32x2 FMA, cp.async-staged
// weights. grid (48,16), block 128. R13: one barrier per stage (the
// pre-restage sync was redundant: restage target buf (st+3)&3=(st-1)&3 was
// last read in stage st-1, already fenced by the top-of-stage sync), and
// restage moved before compute for earlier prefetch.
// ---------------------------------------------------------------------------
__global__ __launch_bounds__(128)
void qkv_gemm(const float* __restrict__ x,
              const float* __restrict__ wq,
              const float* __restrict__ wk,
              const float* __restrict__ wv)
{
    __shared__ float xs[BATCH * KC];      // 32 KB
    __shared__ float wsm[4][WR][128];     // 16 KB weight stages
    const int tx = threadIdx.x;
    const int bx = blockIdx.x;
    const int by = blockIdx.y;
    const int k0 = by * KC;

    #pragma unroll
    for (int i = 0; i < 16; i++) {
        int s  = tx + i * 128;
        int b  = s >> 6;
        int k4 = s & 63;
        float4 v = *(const float4*)&x[b * DIM + k0 + k4 * 4];
        *(float4*)&xs[b * KC + k4 * 4] = v;
    }

    const int q  = tx & 31;
    const int g  = tx >> 5;
    const int b0 = g * 8;
    const int gcol = bx * 128 + q * 4;

    const float* w; int ncols; int colbase;
    if (bx < 32)      { w = wq; ncols = 4096; colbase = bx * 128; }
    else if (bx < 40) { w = wk; ncols = 1024; colbase = (bx - 32) * 128; }
    else              { w = wv; ncols = 1024; colbase = (bx - 40) * 128; }

    const u32 wsb = smem_u32(&wsm[0][0][0]);
    // stage st (8 weight rows) into buffer buf; 128 threads x 2 rows-of-4
    auto stagew = [&](int st, int buf) {
        #pragma unroll
        for (int i = 0; i < 2; i++) {
            int r = g + i * 4;
            cp16(wsb + (u32)(((buf * WR + r) * 128 + q * 4) * 4),
                 w + (size_t)(k0 + st * WR + r) * ncols + colbase + q * 4);
        }
        cp_commit();
    };

    stagew(0, 0); stagew(1, 1); stagew(2, 2);
    __syncthreads();                      // xs ready

    ull acc01[8], acc23[8];
    #pragma unroll
    for (int i = 0; i < 8; i++) { acc01[i] = 0ULL; acc23[i] = 0ULL; }

    for (int st = 0; st < NWST; st++) {
        const int buf = st & 3;
        cp_wait<2>();                     // group st complete
        __syncthreads();                  // all warps done with buf (st-1)&3
        if (st + 3 < NWST) stagew(st + 3, (st + 3) & 3);
        else               cp_commit();   // empty group keeps wait<2> exact

        #pragma unroll
        for (int rr = 0; rr < 2; rr++) {
            const int kk = st * WR + rr * 4;
            float xv[8][4];
            #pragma unroll
            for (int i = 0; i < 8; i++) {
                float4 t4 = *(const float4*)&xs[(b0 + i) * KC + kk];
                xv[i][0] = t4.x; xv[i][1] = t4.y; xv[i][2] = t4.z; xv[i][3] = t4.w;
            }
            #pragma unroll
            for (int j = 0; j < 4; j++) {
                float4 w4 = *(const float4*)&wsm[buf][rr * 4 + j][q * 4];
                ull w01 = pk2(w4.x, w4.y);
                ull w23 = pk2(w4.z, w4.w);
                #pragma unroll
                for (int i = 0; i < 8; i++) {
                    ull xp = pk2(xv[i][j], xv[i][j]);
                    acc01[i] = fma2(xp, w01, acc01[i]);
                    acc23[i] = fma2(xp, w23, acc23[i]);
                }
            }
        }
    }

    #pragma unroll
    for (int i = 0; i < 8; i++) {
        float4 r;
        upk2(acc01[i], r.x, r.y);
        upk2(acc23[i], r.z, r.w);
        *(float4*)&g_part[((size_t)by * BATCH + b0 + i) * NQKV + gcol] = r;
    }
}

// ---------------------------------------------------------------------------
// Kernel B: reduce split-K partials + RoPE -> g_q, g_k, g_v.
// ---------------------------------------------------------------------------
__global__ __launch_bounds__(256)
void rope_reduce(const float* __restrict__ fcos, const float* __restrict__ fsin)
{
    int idx = blockIdx.x * 256 + threadIdx.x;
    int b = idx / (NQKV / 2);
    int p = idx % (NQKV / 2);
    int col = 2 * p;

    float v0 = 0.f, v1 = 0.f;
    #pragma unroll
    for (int c = 0; c < NCH; c++) {
        float2 t = *(const float2*)&g_part[((size_t)c * BATCH + b) * NQKV + col];
        v0 += t.x; v1 += t.y;
    }

    if (col < 4096) {
        int d = col & (HD - 1);
        int dp = d >> 1;
        float c = fcos[dp], s = fsin[dp];
        g_q[b * 4096 + col]     = v0 * c - v1 * s;
        g_q[b * 4096 + col + 1] = v0 * s + v1 * c;
    } else if (col < 5120) {
        int cc = col - 4096;
        int d = cc & (HD - 1);
        int dp = d >> 1;
        float c = fcos[dp], s = fsin[dp];
        g_k[b * 1024 + cc]     = v0 * c - v1 * s;
        g_k[b * 1024 + cc + 1] = v0 * s + v1 * c;
    } else {
        int cc = col - 5120;
        g_v[b * 1024 + cc]     = v0;
        g_v[b * 1024 + cc + 1] = v1;
    }
}

// ---------------------------------------------------------------------------
// Probe pad: shifts qkv_gemm into the ncu capture slot (4th launch). No-op.
// ---------------------------------------------------------------------------
__global__ void probe_pad() {}

// ---------------------------------------------------------------------------
// Kernel C: flash-decode GQA attention, cp.async double-buffered K pipeline.
// (unchanged from R13 winner)
// ---------------------------------------------------------------------------
__global__ __launch_bounds__(256, 3)
void attention(const float* __restrict__ cache_k,
               const float* __restrict__ cache_v,
               const int* __restrict__ start_pos)
{
    __shared__ float4 ksm[8][2][CHT][32];     // 64 KB; reused for acc merge
    __shared__ float  qsm[4 * HD];            // 2 KB
    __shared__ float  psm[8][CHT * 4];        // 1 KB, warp-private
    __shared__ float  msm[8][NREP], lsm[8][NREP];

    const int hh  = blockIdx.x;               // kv head
    const int b   = blockIdx.y;
    const int spl = blockIdx.z;
    const int tx  = threadIdx.x;
    const int w   = tx >> 5;
    const int l   = tx & 31;
    const int tok = l & 7;                    // token within chunk
    const int qr  = l >> 3;                   // dim quarter (32 dims each)

    const int sp = *start_pos;                // 4095
    const int t0 = spl * TSPLIT;

    const float qscale = 1.4426950408889634f * 0.08838834764831845f;
    #pragma unroll
    for (int r = 0; r < 2; r++) {
        int o = tx + r * 256;
        qsm[o] = g_q[b * 4096 + (hh * NREP) * HD + o] * qscale;
    }
    __syncthreads();

    float m0 = -1e30f, m1 = -1e30f, m2 = -1e30f, m3 = -1e30f;
    float ls0 = 0.f, ls1 = 0.f, ls2 = 0.f, ls3 = 0.f;
    float acc[NREP][4];
    #pragma unroll
    for (int qi = 0; qi < NREP; qi++)
        #pragma unroll
        for (int j = 0; j < 4; j++) acc[qi][j] = 0.f;

    const size_t kv_bh = (size_t)b * MAXSEQ * NKV * HD + hh * HD;
    const float* gk = &g_k[(b * NKV + hh) * HD];
    const float* gv = &g_v[(b * NKV + hh) * HD];

    const u32 kbase = smem_u32(&ksm[w][0][0][0]);

    auto stage = [&](int c, int buf) {
        const int tb = t0 + c * CHT;
        #pragma unroll
        for (int r = 0; r < CHT; r++) {
            int tg = tb + r;
            const float* krow = (tg == sp) ? gk
                                           : cache_k + kv_bh + (size_t)tg * (NKV * HD);
            cp16(kbase + (u32)(((buf * CHT + r) * 32 + (l ^ r)) * 16),
                 krow + l * 4);
        }
        cp_commit();
    };

    stage(w, 0);

    for (int j = 0; j < NCHUNK / 8; j++) {
        const int c  = w + j * 8;
        const int tb = t0 + c * CHT;
        const int buf = j & 1;

        if (j < NCHUNK / 8 - 1) { stage(c + 8, buf ^ 1); cp_wait<1>(); }
        else                    { cp_wait<0>(); }
        __syncwarp();

        float s0 = 0.f, s1 = 0.f, s2 = 0.f, s3 = 0.f;
        #pragma unroll
        for (int i = 0; i < 8; i++) {
            int col = qr * 8 + i;
            float4 k4 = ksm[w][buf][tok][col ^ tok];
            float4 q0 = *(const float4*)&qsm[0 * HD + col * 4];
            float4 q1 = *(const float4*)&qsm[1 * HD + col * 4];
            float4 q2 = *(const float4*)&qsm[2 * HD + col * 4];
            float4 q3 = *(const float4*)&qsm[3 * HD + col * 4];
            s0 += k4.x*q0.x + k4.y*q0.y + k4.z*q0.z + k4.w*q0.w;
            s1 += k4.x*q1.x + k4.y*q1.y + k4.z*q1.z + k4.w*q1.w;
            s2 += k4.x*q2.x + k4.y*q2.y + k4.z*q2.z + k4.w*q2.w;
            s3 += k4.x*q3.x + k4.y*q3.y + k4.z*q3.z + k4.w*q3.w;
        }
        s0 += __shfl_xor_sync(0xffffffffu, s0, 8);
        s1 += __shfl_xor_sync(0xffffffffu, s1, 8);
        s2 += __shfl_xor_sync(0xffffffffu, s2, 8);
        s3 += __shfl_xor_sync(0xffffffffu, s3, 8);
        s0 += __shfl_xor_sync(0xffffffffu, s0, 16);
        s1 += __shfl_xor_sync(0xffffffffu, s1, 16);
        s2 += __shfl_xor_sync(0xffffffffu, s2, 16);
        s3 += __shfl_xor_sync(0xffffffffu, s3, 16);
        if (tb + tok > sp) { s0 = -1e30f; s1 = -1e30f; s2 = -1e30f; s3 = -1e30f; }

        float c0 = s0, c1 = s1, c2 = s2, c3 = s3;
        #pragma unroll
        for (int off = 4; off > 0; off >>= 1) {
            c0 = fmaxf(c0, __shfl_xor_sync(0xffffffffu, c0, off));
            c1 = fmaxf(c1, __shfl_xor_sync(0xffffffffu, c1, off));
            c2 = fmaxf(c2, __shfl_xor_sync(0xffffffffu, c2, off));
            c3 = fmaxf(c3, __shfl_xor_sync(0xffffffffu, c3, off));
        }
        if (c0 > m0) { float a = exp2f(m0 - c0); ls0 *= a;
            acc[0][0]*=a; acc[0][1]*=a; acc[0][2]*=a; acc[0][3]*=a; m0 = c0; }
        if (c1 > m1) { float a = exp2f(m1 - c1); ls1 *= a;
            acc[1][0]*=a; acc[1][1]*=a; acc[1][2]*=a; acc[1][3]*=a; m1 = c1; }
        if (c2 > m2) { float a = exp2f(m2 - c2); ls2 *= a;
            acc[2][0]*=a; acc[2][1]*=a; acc[2][2]*=a; acc[2][3]*=a; m2 = c2; }
        if (c3 > m3) { float a = exp2f(m3 - c3); ls3 *= a;
            acc[3][0]*=a; acc[3][1]*=a; acc[3][2]*=a; acc[3][3]*=a; m3 = c3; }

        float p0 = exp2f(s0 - m0), p1 = exp2f(s1 - m1);
        float p2 = exp2f(s2 - m2), p3 = exp2f(s3 - m3);
        if (qr == 0) {
            ls0 += p0; ls1 += p1; ls2 += p2; ls3 += p3;
            *(float4*)&psm[w][tok * 4] = make_float4(p0, p1, p2, p3);
        }
        __syncwarp();

        const float* vlane = cache_v + kv_bh + l * 4;
        #pragma unroll
        for (int tt = 0; tt < CHT; tt++) {
            int tg = tb + tt;
            const float* vp = (tg == sp) ? gv + l * 4
                                         : vlane + (size_t)tg * (NKV * HD);
            float4 v4 = *(const float4*)vp;
            float4 p4 = *(const float4*)&psm[w][tt * 4];
            acc[0][0] += p4.x*v4.x; acc[0][1] += p4.x*v4.y; acc[0][2] += p4.x*v4.z; acc[0][3] += p4.x*v4.w;
            acc[1][0] += p4.y*v4.x; acc[1][1] += p4.y*v4.y; acc[1][2] += p4.y*v4.z; acc[1][3] += p4.y*v4.w;
            acc[2][0] += p4.z*v4.x; acc[2][1] += p4.z*v4.y; acc[2][2] += p4.z*v4.z; acc[2][3] += p4.z*v4.w;
            acc[3][0] += p4.w*v4.x; acc[3][1] += p4.w*v4.y; acc[3][2] += p4.w*v4.z; acc[3][3] += p4.w*v4.w;
        }
        __syncwarp();
    }

    #pragma unroll
    for (int off = 16; off > 0; off >>= 1) {
        ls0 += __shfl_xor_sync(0xffffffffu, ls0, off);
        ls1 += __shfl_xor_sync(0xffffffffu, ls1, off);
        ls2 += __shfl_xor_sync(0xffffffffu, ls2, off);
        ls3 += __shfl_xor_sync(0xffffffffu, ls3, off);
    }

    __syncthreads();
    float* accs = (float*)ksm;                // [8][NREP][HD]
    #pragma unroll
    for (int qi = 0; qi < NREP; qi++)
        *(float4*)&accs[(w * NREP + qi) * HD + l * 4] =
            make_float4(acc[qi][0], acc[qi][1], acc[qi][2], acc[qi][3]);
    if (l == 0) {
        msm[w][0] = m0; msm[w][1] = m1; msm[w][2] = m2; msm[w][3] = m3;
        lsm[w][0] = ls0; lsm[w][1] = ls1; lsm[w][2] = ls2; lsm[w][3] = ls3;
    }
    __syncthreads();

    #pragma unroll
    for (int r = 0; r < 2; r++) {
        int o  = tx + r * 256;
        int qi = o >> 7;
        int d  = o & (HD - 1);
        float M = msm[0][qi];
        #pragma unroll
        for (int w2 = 1; w2 < 8; w2++) M = fmaxf(M, msm[w2][qi]);
        float num = 0.f, den = 0.f;
        #pragma unroll
        for (int w2 = 0; w2 < 8; w2++) {
            float wgt = exp2f(msm[w2][qi] - M);
            num += wgt * accs[(w2 * NREP + qi) * HD + d];
            den += wgt * lsm[w2][qi];
        }
        int pbase = ((b * NKV + hh) * NSPLIT + spl) * NREP + qi;
        g_pacc[(size_t)pbase * HD + d] = num;
        if (d == 0) { g_pl[pbase] = den; g_pm[pbase] = M; }
    }
}

// ---------------------------------------------------------------------------
// Kernel C2: merge the NSPLIT partials -> g_att. grid 256, block 512.
// ---------------------------------------------------------------------------
__global__ __launch_bounds__(512)
void att_merge()
{
    const int bh = blockIdx.x;
    const int o  = threadIdx.x;
    const int qi = o >> 7;
    const int d  = o & (HD - 1);
    const int base = bh * NSPLIT * NREP + qi;

    float M = -1e30f;
    #pragma unroll
    for (int s = 0; s < NSPLIT; s++) M = fmaxf(M, g_pm[base + s * NREP]);
    float num = 0.f, den = 0.f;
    #pragma unroll
    for (int s = 0; s < NSPLIT; s++) {
        int p = base + s * NREP;
        float wgt = exp2f(g_pm[p] - M);
        num += wgt * g_pacc[(size_t)p * HD + d];
        den += wgt * g_pl[p];
    }
    const int b = bh >> 3, h = bh & 7;
    g_att[b * 4096 + (h * NREP + qi) * HD + d] = num / den;
}

// ---------------------------------------------------------------------------
// Kernel D: output projection, split-K, packed f32x2 FMA, cp.async-staged
// weights (same single-barrier pipeline as qkv_gemm). grid (32,16), block 128.
// ---------------------------------------------------------------------------
__global__ __launch_bounds__(128)
void o_gemm(const float* __restrict__ wo)
{
    __shared__ float xs[BATCH * KC];      // 32 KB
    __shared__ float wsm[4][WR][128];     // 16 KB
    const int tx = threadIdx.x;
    const int bx = blockIdx.x;
    const int by = blockIdx.y;
    const int k0 = by * KC;

    #pragma unroll
    for (int i = 0; i < 16; i++) {
        int s  = tx + i * 128;
        int b  = s >> 6;
        int k4 = s & 63;
        float4 v = *(const float4*)&g_att[b * DIM + k0 + k4 * 4];
        *(float4*)&xs[b * KC + k4 * 4] = v;
    }

    const int q  = tx & 31;
    const int g  = tx >> 5;
    const int b0 = g * 8;
    const int gcol = bx * 128 + q * 4;
    const int colbase = bx * 128;

    const u32 wsb = smem_u32(&wsm[0][0][0]);
    auto stagew = [&](int st, int buf) {
        #pragma unroll
        for (int i = 0; i < 2; i++) {
            int r = g + i * 4;
            cp16(wsb + (u32)(((buf * WR + r) * 128 + q * 4) * 4),
                 wo + (size_t)(k0 + st * WR + r) * DIM + colbase + q * 4);
        }
        cp_commit();
    };

    stagew(0, 0); stagew(1, 1); stagew(2, 2);
    __syncthreads();

    ull acc01[8], acc23[8];
    #pragma unroll
    for (int i = 0; i < 8; i++) { acc01[i] = 0ULL; acc23[i] = 0ULL; }

    for (int st = 0; st < NWST; st++) {
        const int buf = st & 3;
        cp_wait<2>();
        __syncthreads();                  // all warps done with buf (st-1)&3
        if (st + 3 < NWST) stagew(st + 3, (st + 3) & 3);
        else               cp_commit();

        #pragma unroll
        for (int rr = 0; rr < 2; rr++) {
            const int kk = st * WR + rr * 4;
            float xv[8][4];
            #pragma unroll
            for (int i = 0; i < 8; i++) {
                float4 t4 = *(const float4*)&xs[(b0 + i) * KC + kk];
                xv[i][0] = t4.x; xv[i][1] = t4.y; xv[i][2] = t4.z; xv[i][3] = t4.w;
            }
            #pragma unroll
            for (int j = 0; j < 4; j++) {
                float4 w4 = *(const float4*)&wsm[buf][rr * 4 + j][q * 4];
                ull w01 = pk2(w4.x, w4.y);
                ull w23 = pk2(w4.z, w4.w);
                #pragma unroll
                for (int i = 0; i < 8; i++) {
                    ull xp = pk2(xv[i][j], xv[i][j]);
                    acc01[i] = fma2(xp, w01, acc01[i]);
                    acc23[i] = fma2(xp, w23, acc23[i]);
                }
            }
        }
    }

    #pragma unroll
    for (int i = 0; i < 8; i++) {
        float4 r;
        upk2(acc01[i], r.x, r.y);
        upk2(acc23[i], r.z, r.w);
        *(float4*)&g_opart[((size_t)by * BATCH + b0 + i) * DIM + gcol] = r;
    }
}

// ---------------------------------------------------------------------------
// Kernel E: reduce O partials -> d_out
// ---------------------------------------------------------------------------
__global__ __launch_bounds__(256)
void o_reduce(float* __restrict__ out)
{
    int idx = blockIdx.x * 256 + threadIdx.x;
    float v = 0.f;
    #pragma unroll
    for (int c = 0; c < NCH; c++)
        v += g_opart[(size_t)c * (BATCH * DIM) + idx];
    out[idx] = v;
}

// ---------------------------------------------------------------------------
extern "C" void kernel_launch(void* const* d_in, const int* in_sizes, int n_in,
                              void* d_out, int out_size)
{
    const float* x        = (const float*)d_in[0];
    const float* cache_k  = (const float*)d_in[1];
    const float* cache_v  = (const float*)d_in[2];
    const float* fcos     = (const float*)d_in[3];
    const float* fsin     = (const float*)d_in[4];
    const float* wq       = (const float*)d_in[5];
    const float* wk       = (const float*)d_in[6];
    const float* wv       = (const float*)d_in[7];
    const float* wo       = (const float*)d_in[8];
    const int*   sp       = (const int*)d_in[9];
    float* out            = (float*)d_out;

    // 3 probes keep qkv_gemm in the 4th-launch ncu capture slot
    probe_pad<<<1, 32>>>();
    probe_pad<<<1, 32>>>();
    probe_pad<<<1, 32>>>();
    qkv_gemm<<<dim3(48, 16), 128>>>(x, wq, wk, wv);
    rope_reduce<<<(BATCH * (NQKV / 2)) / 256, 256>>>(fcos, fsin);
    attention<<<dim3(NKV, BATCH, NSPLIT), 256>>>(cache_k, cache_v, sp);
    att_merge<<<BATCH * NKV, 512>>>();
    o_gemm<<<dim3(32, 16), 128>>>(wo);
    o_reduce<<<(BATCH * DIM) / 256, 256>>>(out);
}

// round 15
// speedup vs baseline: 1.8239x; 1.0010x over previous
#include <cuda_runtime.h>
#include <cuda_bf16.h>
#include <math.h>
#include <cstdint>

// Problem constants (fixed by the dataset)
#define BATCH   32
#define DIM     4096
#define NH      32
#define NKV     8
#define HD      128
#define NREP    4          // NH / NKV
#define MAXSEQ  4096
#define NQKV    6144       // 4096 (q) + 1024 (k) + 1024 (v)
#define KC      256        // k-chunk for split-K GEMMs
#define NCH     16         // 4096 / KC
#define NSPLIT  8          // KV splits in attention
#define TSPLIT  512        // MAXSEQ / NSPLIT
#define CHT     8          // tokens per warp-chunk (double-buffered)
#define NCHUNK  64         // TSPLIT / CHT
#define WR      8          // weight rows per cp.async stage
#define NWST    (KC / WR)  // 32 stages per k-chunk

typedef unsigned long long ull;
typedef unsigned int u32;

// Packed f32x2 helpers (Blackwell): FFMA2 only reachable via PTX fma.rn.f32x2
__device__ __forceinline__ ull pk2(float lo, float hi) {
    ull r; asm("mov.b64 %0, {%1, %2};" : "=l"(r) : "f"(lo), "f"(hi)); return r;
}
__device__ __forceinline__ ull fma2(ull a, ull b, ull c) {
    ull d; asm("fma.rn.f32x2 %0, %1, %2, %3;" : "=l"(d) : "l"(a), "l"(b), "l"(c));
    return d;
}
__device__ __forceinline__ void upk2(ull v, float& lo, float& hi) {
    asm("mov.b64 {%0, %1}, %2;" : "=f"(lo), "=f"(hi) : "l"(v));
}

// cp.async helpers
__device__ __forceinline__ u32 smem_u32(const void* p) {
    return (u32)__cvta_generic_to_shared(p);
}
__device__ __forceinline__ void cp16(u32 dst, const void* src) {
    asm volatile("cp.async.cg.shared.global [%0], [%1], 16;" :: "r"(dst), "l"(src));
}
__device__ __forceinline__ void cp_commit() {
    asm volatile("cp.async.commit_group;");
}
template<int N> __device__ __forceinline__ void cp_wait() {
    asm volatile("cp.async.wait_group %0;" :: "n"(N));
}

// Scratch (device globals; no allocation allowed)
__device__ float g_part [NCH * BATCH * NQKV];   // QKV split-K partials
__device__ float g_q    [BATCH * NH * HD];      // rope'd q
__device__ float g_k    [BATCH * NKV * HD];     // rope'd new k
__device__ float g_v    [BATCH * NKV * HD];     // new v
__device__ float g_att  [BATCH * NH * HD];      // attention output
__device__ float g_opart[NCH * BATCH * DIM];    // O-proj split-K partials
// Attention split-KV partials
__device__ float g_pm  [BATCH * NKV * NSPLIT * NREP];
__device__ float g_pl  [BATCH * NKV * NSPLIT * NREP];
__device__ float g_pacc[BATCH * NKV * NSPLIT * NREP * HD];

// ---------------------------------------------------------------------------
// Kernel A: QKV projection, split-K, packed f32x2 FMA, cp.async-staged
// weights. grid (48,16), block 128. R15: 3-buffer weight ring (12 KB) cuts
// smem 49->45 KB so occupancy rises 4->5 blocks/SM (R14 ncu: smem-limited,
// issue 46%). Prefetch depth 2 stages, wait<1> per stage.
// ---------------------------------------------------------------------------
__global__ __launch_bounds__(128)
void qkv_gemm(const float* __restrict__ x,
              const float* __restrict__ wq,
              const float* __restrict__ wk,
              const float* __restrict__ wv)
{
    __shared__ float xs[BATCH * KC];      // 32 KB
    __shared__ float wsm[3][WR][128];     // 12 KB weight stages
    const int tx = threadIdx.x;
    const int bx = blockIdx.x;
    const int by = blockIdx.y;
    const int k0 = by * KC;

    #pragma unroll
    for (int i = 0; i < 16; i++) {
        int s  = tx + i * 128;
        int b  = s >> 6;
        int k4 = s & 63;
        float4 v = *(const float4*)&x[b * DIM + k0 + k4 * 4];
        *(float4*)&xs[b * KC + k4 * 4] = v;
    }

    const int q  = tx & 31;
    const int g  = tx >> 5;
    const int b0 = g * 8;
    const int gcol = bx * 128 + q * 4;

    const float* w; int ncols; int colbase;
    if (bx < 32)      { w = wq; ncols = 4096; colbase = bx * 128; }
    else if (bx < 40) { w = wk; ncols = 1024; colbase = (bx - 32) * 128; }
    else              { w = wv; ncols = 1024; colbase = (bx - 40) * 128; }

    const u32 wsb = smem_u32(&wsm[0][0][0]);
    // stage st (8 weight rows) into buffer buf; 128 threads x 2 rows-of-4
    auto stagew = [&](int st, int buf) {
        #pragma unroll
        for (int i = 0; i < 2; i++) {
            int r = g + i * 4;
            cp16(wsb + (u32)(((buf * WR + r) * 128 + q * 4) * 4),
                 w + (size_t)(k0 + st * WR + r) * ncols + colbase + q * 4);
        }
        cp_commit();
    };

    stagew(0, 0); stagew(1, 1);
    __syncthreads();                      // xs ready

    ull acc01[8], acc23[8];
    #pragma unroll
    for (int i = 0; i < 8; i++) { acc01[i] = 0ULL; acc23[i] = 0ULL; }

    int buf = 0;
    for (int st = 0; st < NWST; st++) {
        cp_wait<1>();                     // group st complete
        __syncthreads();                  // all warps done with restage target
        if (st + 2 < NWST) { int nb = buf + 2; if (nb >= 3) nb -= 3;
                             stagew(st + 2, nb); }
        else               cp_commit();   // empty group keeps wait<1> exact

        #pragma unroll
        for (int rr = 0; rr < 2; rr++) {
            const int kk = st * WR + rr * 4;
            float xv[8][4];
            #pragma unroll
            for (int i = 0; i < 8; i++) {
                float4 t4 = *(const float4*)&xs[(b0 + i) * KC + kk];
                xv[i][0] = t4.x; xv[i][1] = t4.y; xv[i][2] = t4.z; xv[i][3] = t4.w;
            }
            #pragma unroll
            for (int j = 0; j < 4; j++) {
                float4 w4 = *(const float4*)&wsm[buf][rr * 4 + j][q * 4];
                ull w01 = pk2(w4.x, w4.y);
                ull w23 = pk2(w4.z, w4.w);
                #pragma unroll
                for (int i = 0; i < 8; i++) {
                    ull xp = pk2(xv[i][j], xv[i][j]);
                    acc01[i] = fma2(xp, w01, acc01[i]);
                    acc23[i] = fma2(xp, w23, acc23[i]);
                }
            }
        }
        if (++buf == 3) buf = 0;
    }

    #pragma unroll
    for (int i = 0; i < 8; i++) {
        float4 r;
        upk2(acc01[i], r.x, r.y);
        upk2(acc23[i], r.z, r.w);
        *(float4*)&g_part[((size_t)by * BATCH + b0 + i) * NQKV + gcol] = r;
    }
}

// ---------------------------------------------------------------------------
// Kernel B: reduce split-K partials + RoPE -> g_q, g_k, g_v.
// ---------------------------------------------------------------------------
__global__ __launch_bounds__(256)
void rope_reduce(const float* __restrict__ fcos, const float* __restrict__ fsin)
{
    int idx = blockIdx.x * 256 + threadIdx.x;
    int b = idx / (NQKV / 2);
    int p = idx % (NQKV / 2);
    int col = 2 * p;

    float v0 = 0.f, v1 = 0.f;
    #pragma unroll
    for (int c = 0; c < NCH; c++) {
        float2 t = *(const float2*)&g_part[((size_t)c * BATCH + b) * NQKV + col];
        v0 += t.x; v1 += t.y;
    }

    if (col < 4096) {
        int d = col & (HD - 1);
        int dp = d >> 1;
        float c = fcos[dp], s = fsin[dp];
        g_q[b * 4096 + col]     = v0 * c - v1 * s;
        g_q[b * 4096 + col + 1] = v0 * s + v1 * c;
    } else if (col < 5120) {
        int cc = col - 4096;
        int d = cc & (HD - 1);
        int dp = d >> 1;
        float c = fcos[dp], s = fsin[dp];
        g_k[b * 1024 + cc]     = v0 * c - v1 * s;
        g_k[b * 1024 + cc + 1] = v0 * s + v1 * c;
    } else {
        int cc = col - 5120;
        g_v[b * 1024 + cc]     = v0;
        g_v[b * 1024 + cc + 1] = v1;
    }
}

// ---------------------------------------------------------------------------
// Probe pad: shifts qkv_gemm into the ncu capture slot (4th launch). No-op.
// ---------------------------------------------------------------------------
__global__ void probe_pad() {}

// ---------------------------------------------------------------------------
// Kernel C: flash-decode GQA attention, cp.async double-buffered K pipeline.
// (unchanged from R14 winner)
// ---------------------------------------------------------------------------
__global__ __launch_bounds__(256, 3)
void attention(const float* __restrict__ cache_k,
               const float* __restrict__ cache_v,
               const int* __restrict__ start_pos)
{
    __shared__ float4 ksm[8][2][CHT][32];     // 64 KB; reused for acc merge
    __shared__ float  qsm[4 * HD];            // 2 KB
    __shared__ float  psm[8][CHT * 4];        // 1 KB, warp-private
    __shared__ float  msm[8][NREP], lsm[8][NREP];

    const int hh  = blockIdx.x;               // kv head
    const int b   = blockIdx.y;
    const int spl = blockIdx.z;
    const int tx  = threadIdx.x;
    const int w   = tx >> 5;
    const int l   = tx & 31;
    const int tok = l & 7;                    // token within chunk
    const int qr  = l >> 3;                   // dim quarter (32 dims each)

    const int sp = *start_pos;                // 4095
    const int t0 = spl * TSPLIT;

    const float qscale = 1.4426950408889634f * 0.08838834764831845f;
    #pragma unroll
    for (int r = 0; r < 2; r++) {
        int o = tx + r * 256;
        qsm[o] = g_q[b * 4096 + (hh * NREP) * HD + o] * qscale;
    }
    __syncthreads();

    float m0 = -1e30f, m1 = -1e30f, m2 = -1e30f, m3 = -1e30f;
    float ls0 = 0.f, ls1 = 0.f, ls2 = 0.f, ls3 = 0.f;
    float acc[NREP][4];
    #pragma unroll
    for (int qi = 0; qi < NREP; qi++)
        #pragma unroll
        for (int j = 0; j < 4; j++) acc[qi][j] = 0.f;

    const size_t kv_bh = (size_t)b * MAXSEQ * NKV * HD + hh * HD;
    const float* gk = &g_k[(b * NKV + hh) * HD];
    const float* gv = &g_v[(b * NKV + hh) * HD];

    const u32 kbase = smem_u32(&ksm[w][0][0][0]);

    auto stage = [&](int c, int buf) {
        const int tb = t0 + c * CHT;
        #pragma unroll
        for (int r = 0; r < CHT; r++) {
            int tg = tb + r;
            const float* krow = (tg == sp) ? gk
                                           : cache_k + kv_bh + (size_t)tg * (NKV * HD);
            cp16(kbase + (u32)(((buf * CHT + r) * 32 + (l ^ r)) * 16),
                 krow + l * 4);
        }
        cp_commit();
    };

    stage(w, 0);

    for (int j = 0; j < NCHUNK / 8; j++) {
        const int c  = w + j * 8;
        const int tb = t0 + c * CHT;
        const int buf = j & 1;

        if (j < NCHUNK / 8 - 1) { stage(c + 8, buf ^ 1); cp_wait<1>(); }
        else                    { cp_wait<0>(); }
        __syncwarp();

        float s0 = 0.f, s1 = 0.f, s2 = 0.f, s3 = 0.f;
        #pragma unroll
        for (int i = 0; i < 8; i++) {
            int col = qr * 8 + i;
            float4 k4 = ksm[w][buf][tok][col ^ tok];
            float4 q0 = *(const float4*)&qsm[0 * HD + col * 4];
            float4 q1 = *(const float4*)&qsm[1 * HD + col * 4];
            float4 q2 = *(const float4*)&qsm[2 * HD + col * 4];
            float4 q3 = *(const float4*)&qsm[3 * HD + col * 4];
            s0 += k4.x*q0.x + k4.y*q0.y + k4.z*q0.z + k4.w*q0.w;
            s1 += k4.x*q1.x + k4.y*q1.y + k4.z*q1.z + k4.w*q1.w;
            s2 += k4.x*q2.x + k4.y*q2.y + k4.z*q2.z + k4.w*q2.w;
            s3 += k4.x*q3.x + k4.y*q3.y + k4.z*q3.z + k4.w*q3.w;
        }
        s0 += __shfl_xor_sync(0xffffffffu, s0, 8);
        s1 += __shfl_xor_sync(0xffffffffu, s1, 8);
        s2 += __shfl_xor_sync(0xffffffffu, s2, 8);
        s3 += __shfl_xor_sync(0xffffffffu, s3, 8);
        s0 += __shfl_xor_sync(0xffffffffu, s0, 16);
        s1 += __shfl_xor_sync(0xffffffffu, s1, 16);
        s2 += __shfl_xor_sync(0xffffffffu, s2, 16);
        s3 += __shfl_xor_sync(0xffffffffu, s3, 16);
        if (tb + tok > sp) { s0 = -1e30f; s1 = -1e30f; s2 = -1e30f; s3 = -1e30f; }

        float c0 = s0, c1 = s1, c2 = s2, c3 = s3;
        #pragma unroll
        for (int off = 4; off > 0; off >>= 1) {
            c0 = fmaxf(c0, __shfl_xor_sync(0xffffffffu, c0, off));
            c1 = fmaxf(c1, __shfl_xor_sync(0xffffffffu, c1, off));
            c2 = fmaxf(c2, __shfl_xor_sync(0xffffffffu, c2, off));
            c3 = fmaxf(c3, __shfl_xor_sync(0xffffffffu, c3, off));
        }
        if (c0 > m0) { float a = exp2f(m0 - c0); ls0 *= a;
            acc[0][0]*=a; acc[0][1]*=a; acc[0][2]*=a; acc[0][3]*=a; m0 = c0; }
        if (c1 > m1) { float a = exp2f(m1 - c1); ls1 *= a;
            acc[1][0]*=a; acc[1][1]*=a; acc[1][2]*=a; acc[1][3]*=a; m1 = c1; }
        if (c2 > m2) { float a = exp2f(m2 - c2); ls2 *= a;
            acc[2][0]*=a; acc[2][1]*=a; acc[2][2]*=a; acc[2][3]*=a; m2 = c2; }
        if (c3 > m3) { float a = exp2f(m3 - c3); ls3 *= a;
            acc[3][0]*=a; acc[3][1]*=a; acc[3][2]*=a; acc[3][3]*=a; m3 = c3; }

        float p0 = exp2f(s0 - m0), p1 = exp2f(s1 - m1);
        float p2 = exp2f(s2 - m2), p3 = exp2f(s3 - m3);
        if (qr == 0) {
            ls0 += p0; ls1 += p1; ls2 += p2; ls3 += p3;
            *(float4*)&psm[w][tok * 4] = make_float4(p0, p1, p2, p3);
        }
        __syncwarp();

        const float* vlane = cache_v + kv_bh + l * 4;
        #pragma unroll
        for (int tt = 0; tt < CHT; tt++) {
            int tg = tb + tt;
            const float* vp = (tg == sp) ? gv + l * 4
                                         : vlane + (size_t)tg * (NKV * HD);
            float4 v4 = *(const float4*)vp;
            float4 p4 = *(const float4*)&psm[w][tt * 4];
            acc[0][0] += p4.x*v4.x; acc[0][1] += p4.x*v4.y; acc[0][2] += p4.x*v4.z; acc[0][3] += p4.x*v4.w;
            acc[1][0] += p4.y*v4.x; acc[1][1] += p4.y*v4.y; acc[1][2] += p4.y*v4.z; acc[1][3] += p4.y*v4.w;
            acc[2][0] += p4.z*v4.x; acc[2][1] += p4.z*v4.y; acc[2][2] += p4.z*v4.z; acc[2][3] += p4.z*v4.w;
            acc[3][0] += p4.w*v4.x; acc[3][1] += p4.w*v4.y; acc[3][2] += p4.w*v4.z; acc[3][3] += p4.w*v4.w;
        }
        __syncwarp();
    }

    #pragma unroll
    for (int off = 16; off > 0; off >>= 1) {
        ls0 += __shfl_xor_sync(0xffffffffu, ls0, off);
        ls1 += __shfl_xor_sync(0xffffffffu, ls1, off);
        ls2 += __shfl_xor_sync(0xffffffffu, ls2, off);
        ls3 += __shfl_xor_sync(0xffffffffu, ls3, off);
    }

    __syncthreads();
    float* accs = (float*)ksm;                // [8][NREP][HD]
    #pragma unroll
    for (int qi = 0; qi < NREP; qi++)
        *(float4*)&accs[(w * NREP + qi) * HD + l * 4] =
            make_float4(acc[qi][0], acc[qi][1], acc[qi][2], acc[qi][3]);
    if (l == 0) {
        msm[w][0] = m0; msm[w][1] = m1; msm[w][2] = m2; msm[w][3] = m3;
        lsm[w][0] = ls0; lsm[w][1] = ls1; lsm[w][2] = ls2; lsm[w][3] = ls3;
    }
    __syncthreads();

    #pragma unroll
    for (int r = 0; r < 2; r++) {
        int o  = tx + r * 256;
        int qi = o >> 7;
        int d  = o & (HD - 1);
        float M = msm[0][qi];
        #pragma unroll
        for (int w2 = 1; w2 < 8; w2++) M = fmaxf(M, msm[w2][qi]);
        float num = 0.f, den = 0.f;
        #pragma unroll
        for (int w2 = 0; w2 < 8; w2++) {
            float wgt = exp2f(msm[w2][qi] - M);
            num += wgt * accs[(w2 * NREP + qi) * HD + d];
            den += wgt * lsm[w2][qi];
        }
        int pbase = ((b * NKV + hh) * NSPLIT + spl) * NREP + qi;
        g_pacc[(size_t)pbase * HD + d] = num;
        if (d == 0) { g_pl[pbase] = den; g_pm[pbase] = M; }
    }
}

// ---------------------------------------------------------------------------
// Kernel C2: merge the NSPLIT partials -> g_att. grid 256, block 512.
// ---------------------------------------------------------------------------
__global__ __launch_bounds__(512)
void att_merge()
{
    const int bh = blockIdx.x;
    const int o  = threadIdx.x;
    const int qi = o >> 7;
    const int d  = o & (HD - 1);
    const int base = bh * NSPLIT * NREP + qi;

    float M = -1e30f;
    #pragma unroll
    for (int s = 0; s < NSPLIT; s++) M = fmaxf(M, g_pm[base + s * NREP]);
    float num = 0.f, den = 0.f;
    #pragma unroll
    for (int s = 0; s < NSPLIT; s++) {
        int p = base + s * NREP;
        float wgt = exp2f(g_pm[p] - M);
        num += wgt * g_pacc[(size_t)p * HD + d];
        den += wgt * g_pl[p];
    }
    const int b = bh >> 3, h = bh & 7;
    g_att[b * 4096 + (h * NREP + qi) * HD + d] = num / den;
}

// ---------------------------------------------------------------------------
// Kernel D: output projection, split-K, packed f32x2 FMA, 3-buffer
// cp.async-staged weights (same pipeline as qkv_gemm). grid (32,16), 128.
// ---------------------------------------------------------------------------
__global__ __launch_bounds__(128)
void o_gemm(const float* __restrict__ wo)
{
    __shared__ float xs[BATCH * KC];      // 32 KB
    __shared__ float wsm[3][WR][128];     // 12 KB
    const int tx = threadIdx.x;
    const int bx = blockIdx.x;
    const int by = blockIdx.y;
    const int k0 = by * KC;

    #pragma unroll
    for (int i = 0; i < 16; i++) {
        int s  = tx + i * 128;
        int b  = s >> 6;
        int k4 = s & 63;
        float4 v = *(const float4*)&g_att[b * DIM + k0 + k4 * 4];
        *(float4*)&xs[b * KC + k4 * 4] = v;
    }

    const int q  = tx & 31;
    const int g  = tx >> 5;
    const int b0 = g * 8;
    const int gcol = bx * 128 + q * 4;
    const int colbase = bx * 128;

    const u32 wsb = smem_u32(&wsm[0][0][0]);
    auto stagew = [&](int st, int buf) {
        #pragma unroll
        for (int i = 0; i < 2; i++) {
            int r = g + i * 4;
            cp16(wsb + (u32)(((buf * WR + r) * 128 + q * 4) * 4),
                 wo + (size_t)(k0 + st * WR + r) * DIM + colbase + q * 4);
        }
        cp_commit();
    };

    stagew(0, 0); stagew(1, 1);
    __syncthreads();

    ull acc01[8], acc23[8];
    #pragma unroll
    for (int i = 0; i < 8; i++) { acc01[i] = 0ULL; acc23[i] = 0ULL; }

    int buf = 0;
    for (int st = 0; st < NWST; st++) {
        cp_wait<1>();
        __syncthreads();
        if (st + 2 < NWST) { int nb = buf + 2; if (nb >= 3) nb -= 3;
                             stagew(st + 2, nb); }
        else               cp_commit();

        #pragma unroll
        for (int rr = 0; rr < 2; rr++) {
            const int kk = st * WR + rr * 4;
            float xv[8][4];
            #pragma unroll
            for (int i = 0; i < 8; i++) {
                float4 t4 = *(const float4*)&xs[(b0 + i) * KC + kk];
                xv[i][0] = t4.x; xv[i][1] = t4.y; xv[i][2] = t4.z; xv[i][3] = t4.w;
            }
            #pragma unroll
            for (int j = 0; j < 4; j++) {
                float4 w4 = *(const float4*)&wsm[buf][rr * 4 + j][q * 4];
                ull w01 = pk2(w4.x, w4.y);
                ull w23 = pk2(w4.z, w4.w);
                #pragma unroll
                for (int i = 0; i < 8; i++) {
                    ull xp = pk2(xv[i][j], xv[i][j]);
                    acc01[i] = fma2(xp, w01, acc01[i]);
                    acc23[i] = fma2(xp, w23, acc23[i]);
                }
            }
        }
        if (++buf == 3) buf = 0;
    }

    #pragma unroll
    for (int i = 0; i < 8; i++) {
        float4 r;
        upk2(acc01[i], r.x, r.y);
        upk2(acc23[i], r.z, r.w);
        *(float4*)&g_opart[((size_t)by * BATCH + b0 + i) * DIM + gcol] = r;
    }
}

// ---------------------------------------------------------------------------
// Kernel E: reduce O partials -> d_out
// ---------------------------------------------------------------------------
__global__ __launch_bounds__(256)
void o_reduce(float* __restrict__ out)
{
    int idx = blockIdx.x * 256 + threadIdx.x;
    float v = 0.f;
    #pragma unroll
    for (int c = 0; c < NCH; c++)
        v += g_opart[(size_t)c * (BATCH * DIM) + idx];
    out[idx] = v;
}

// ---------------------------------------------------------------------------
extern "C" void kernel_launch(void* const* d_in, const int* in_sizes, int n_in,
                              void* d_out, int out_size)
{
    const float* x        = (const float*)d_in[0];
    const float* cache_k  = (const float*)d_in[1];
    const float* cache_v  = (const float*)d_in[2];
    const float* fcos     = (const float*)d_in[3];
    const float* fsin     = (const float*)d_in[4];
    const float* wq       = (const float*)d_in[5];
    const float* wk       = (const float*)d_in[6];
    const float* wv       = (const float*)d_in[7];
    const float* wo       = (const float*)d_in[8];
    const int*   sp       = (const int*)d_in[9];
    float* out            = (float*)d_out;

    // 3 probes keep qkv_gemm in the 4th-launch ncu capture slot
    probe_pad<<<1, 32>>>();
    probe_pad<<<1, 32>>>();
    probe_pad<<<1, 32>>>();
    qkv_gemm<<<dim3(48, 16), 128>>>(x, wq, wk, wv);
    rope_reduce<<<(BATCH * (NQKV / 2)) / 256, 256>>>(fcos, fsin);
    attention<<<dim3(NKV, BATCH, NSPLIT), 256>>>(cache_k, cache_v, sp);
    att_merge<<<BATCH * NKV, 512>>>();
    o_gemm<<<dim3(32, 16), 128>>>(wo);
    o_reduce<<<(BATCH * DIM) / 256, 256>>>(out);
}

// round 16
// speedup vs baseline: 1.8366x; 1.0070x over previous
#include <cuda_runtime.h>
#include <cuda_bf16.h>
#include <math.h>
#include <cstdint>

// Problem constants (fixed by the dataset)
#define BATCH   32
#define DIM     4096
#define NH      32
#define NKV     8
#define HD      128
#define NREP    4          // NH / NKV
#define MAXSEQ  4096
#define NQKV    6144       // 4096 (q) + 1024 (k) + 1024 (v)
#define KC      256        // k-chunk for split-K GEMMs
#define NCH     16         // 4096 / KC
#define NSPLIT  8          // KV splits in attention
#define TSPLIT  512        // MAXSEQ / NSPLIT
#define CHT     8          // tokens per warp-chunk (double-buffered)
#define NCHUNK  64         // TSPLIT / CHT
#define WR      8          // weight rows per cp.async stage
#define NWST    (KC / WR)  // 32 stages per k-chunk

typedef unsigned long long ull;
typedef unsigned int u32;

// Packed f32x2 helpers (Blackwell): FFMA2 only reachable via PTX fma.rn.f32x2
__device__ __forceinline__ ull pk2(float lo, float hi) {
    ull r; asm("mov.b64 %0, {%1, %2};" : "=l"(r) : "f"(lo), "f"(hi)); return r;
}
__device__ __forceinline__ ull fma2(ull a, ull b, ull c) {
    ull d; asm("fma.rn.f32x2 %0, %1, %2, %3;" : "=l"(d) : "l"(a), "l"(b), "l"(c));
    return d;
}
__device__ __forceinline__ void upk2(ull v, float& lo, float& hi) {
    asm("mov.b64 {%0, %1}, %2;" : "=f"(lo), "=f"(hi) : "l"(v));
}

// cp.async helpers
__device__ __forceinline__ u32 smem_u32(const void* p) {
    return (u32)__cvta_generic_to_shared(p);
}
__device__ __forceinline__ void cp16(u32 dst, const void* src) {
    asm volatile("cp.async.cg.shared.global [%0], [%1], 16;" :: "r"(dst), "l"(src));
}
__device__ __forceinline__ void cp_commit() {
    asm volatile("cp.async.commit_group;");
}
template<int N> __device__ __forceinline__ void cp_wait() {
    asm volatile("cp.async.wait_group %0;" :: "n"(N));
}

// Scratch (device globals; no allocation allowed)
__device__ float g_part [NCH * BATCH * NQKV];   // QKV split-K partials
__device__ float g_q    [BATCH * NH * HD];      // rope'd q
__device__ float g_k    [BATCH * NKV * HD];     // rope'd new k
__device__ float g_v    [BATCH * NKV * HD];     // new v
__device__ float g_att  [BATCH * NH * HD];      // attention output
__device__ float g_opart[NCH * BATCH * DIM];    // O-proj split-K partials
// Attention split-KV partials
__device__ float g_pm  [BATCH * NKV * NSPLIT * NREP];
__device__ float g_pl  [BATCH * NKV * NSPLIT * NREP];
__device__ float g_pacc[BATCH * NKV * NSPLIT * NREP * HD];

// ---------------------------------------------------------------------------
// Kernel A: QKV projection, split-K, batch-pair f32x2 FMA, cp.async-staged
// weights. grid (48,16), block 128. R16: x staged TRANSPOSED+swizzled
// (xs[k][b^SW], SW=(2*(k>>2))&30) so batch-pairs load as one broadcast
// LDS.64 -- removes the 64 pk2(x,x) duplication MOVs per stage that were
// ~30% of the issue stream (R15: issue-limited, occupancy falsified).
// w is the duplicated operand, reused across 4 pairs. Bit-identical math.
// ---------------------------------------------------------------------------
__global__ __launch_bounds__(128)
void qkv_gemm(const float* __restrict__ x,
              const float* __restrict__ wq,
              const float* __restrict__ wk,
              const float* __restrict__ wv)
{
    __shared__ float xs[KC * 32];         // 32 KB, transposed [k][b^sw]
    __shared__ float wsm[3][WR][128];     // 12 KB weight stages
    const int tx = threadIdx.x;
    const int bx = blockIdx.x;
    const int by = blockIdx.y;
    const int k0 = by * KC;

    // stage x transposed: slot s = (b, k4); write 4 swizzled scalars
    #pragma unroll
    for (int i = 0; i < 16; i++) {
        int s  = tx + i * 128;
        int b  = s >> 6;
        int k4 = s & 63;
        float4 v = *(const float4*)&x[b * DIM + k0 + k4 * 4];
        int e = b ^ ((2 * k4) & 30);
        xs[(k4 * 4 + 0) * 32 + e] = v.x;
        xs[(k4 * 4 + 1) * 32 + e] = v.y;
        xs[(k4 * 4 + 2) * 32 + e] = v.z;
        xs[(k4 * 4 + 3) * 32 + e] = v.w;
    }

    const int q  = tx & 31;
    const int g  = tx >> 5;
    const int b0 = g * 8;
    const int gcol = bx * 128 + q * 4;

    const float* w; int ncols; int colbase;
    if (bx < 32)      { w = wq; ncols = 4096; colbase = bx * 128; }
    else if (bx < 40) { w = wk; ncols = 1024; colbase = (bx - 32) * 128; }
    else              { w = wv; ncols = 1024; colbase = (bx - 40) * 128; }

    const u32 wsb = smem_u32(&wsm[0][0][0]);
    auto stagew = [&](int st, int buf) {
        #pragma unroll
        for (int i = 0; i < 2; i++) {
            int r = g + i * 4;
            cp16(wsb + (u32)(((buf * WR + r) * 128 + q * 4) * 4),
                 w + (size_t)(k0 + st * WR + r) * ncols + colbase + q * 4);
        }
        cp_commit();
    };

    stagew(0, 0); stagew(1, 1);
    __syncthreads();                      // xs ready

    ull accp[16];                         // [pair p][col c] -> p*4+c
    #pragma unroll
    for (int i = 0; i < 16; i++) accp[i] = 0ULL;

    int buf = 0;
    for (int st = 0; st < NWST; st++) {
        cp_wait<1>();                     // group st complete
        __syncthreads();                  // all warps done with restage target
        if (st + 2 < NWST) { int nb = buf + 2; if (nb >= 3) nb -= 3;
                             stagew(st + 2, nb); }
        else               cp_commit();   // empty group keeps wait<1> exact

        const int sw0 = (st * 4) & 30;
        #pragma unroll
        for (int r = 0; r < WR; r++) {
            const int k  = st * WR + r;
            const int sw = sw0 | ((r & 4) >> 1);
            const float* xrow = &xs[k * 32];
            ull xp0 = *(const ull*)&xrow[(b0 + 0) ^ sw];
            ull xp1 = *(const ull*)&xrow[(b0 + 2) ^ sw];
            ull xp2 = *(const ull*)&xrow[(b0 + 4) ^ sw];
            ull xp3 = *(const ull*)&xrow[(b0 + 6) ^ sw];
            float4 w4 = *(const float4*)&wsm[buf][r][q * 4];
            ull wd0 = pk2(w4.x, w4.x), wd1 = pk2(w4.y, w4.y);
            ull wd2 = pk2(w4.z, w4.z), wd3 = pk2(w4.w, w4.w);
            accp[0]  = fma2(xp0, wd0, accp[0]);
            accp[1]  = fma2(xp0, wd1, accp[1]);
            accp[2]  = fma2(xp0, wd2, accp[2]);
            accp[3]  = fma2(xp0, wd3, accp[3]);
            accp[4]  = fma2(xp1, wd0, accp[4]);
            accp[5]  = fma2(xp1, wd1, accp[5]);
            accp[6]  = fma2(xp1, wd2, accp[6]);
            accp[7]  = fma2(xp1, wd3, accp[7]);
            accp[8]  = fma2(xp2, wd0, accp[8]);
            accp[9]  = fma2(xp2, wd1, accp[9]);
            accp[10] = fma2(xp2, wd2, accp[10]);
            accp[11] = fma2(xp2, wd3, accp[11]);
            accp[12] = fma2(xp3, wd0, accp[12]);
            accp[13] = fma2(xp3, wd1, accp[13]);
            accp[14] = fma2(xp3, wd2, accp[14]);
            accp[15] = fma2(xp3, wd3, accp[15]);
        }
        if (++buf == 3) buf = 0;
    }

    #pragma unroll
    for (int p = 0; p < 4; p++) {
        float lo0, hi0, lo1, hi1, lo2, hi2, lo3, hi3;
        upk2(accp[p * 4 + 0], lo0, hi0);
        upk2(accp[p * 4 + 1], lo1, hi1);
        upk2(accp[p * 4 + 2], lo2, hi2);
        upk2(accp[p * 4 + 3], lo3, hi3);
        *(float4*)&g_part[((size_t)by * BATCH + b0 + 2 * p)     * NQKV + gcol]
            = make_float4(lo0, lo1, lo2, lo3);
        *(float4*)&g_part[((size_t)by * BATCH + b0 + 2 * p + 1) * NQKV + gcol]
            = make_float4(hi0, hi1, hi2, hi3);
    }
}

// ---------------------------------------------------------------------------
// Kernel B: reduce split-K partials + RoPE -> g_q, g_k, g_v.
// ---------------------------------------------------------------------------
__global__ __launch_bounds__(256)
void rope_reduce(const float* __restrict__ fcos, const float* __restrict__ fsin)
{
    int idx = blockIdx.x * 256 + threadIdx.x;
    int b = idx / (NQKV / 2);
    int p = idx % (NQKV / 2);
    int col = 2 * p;

    float v0 = 0.f, v1 = 0.f;
    #pragma unroll
    for (int c = 0; c < NCH; c++) {
        float2 t = *(const float2*)&g_part[((size_t)c * BATCH + b) * NQKV + col];
        v0 += t.x; v1 += t.y;
    }

    if (col < 4096) {
        int d = col & (HD - 1);
        int dp = d >> 1;
        float c = fcos[dp], s = fsin[dp];
        g_q[b * 4096 + col]     = v0 * c - v1 * s;
        g_q[b * 4096 + col + 1] = v0 * s + v1 * c;
    } else if (col < 5120) {
        int cc = col - 4096;
        int d = cc & (HD - 1);
        int dp = d >> 1;
        float c = fcos[dp], s = fsin[dp];
        g_k[b * 1024 + cc]     = v0 * c - v1 * s;
        g_k[b * 1024 + cc + 1] = v0 * s + v1 * c;
    } else {
        int cc = col - 5120;
        g_v[b * 1024 + cc]     = v0;
        g_v[b * 1024 + cc + 1] = v1;
    }
}

// ---------------------------------------------------------------------------
// Probe pad: shifts qkv_gemm into the ncu capture slot (4th launch). No-op.
// ---------------------------------------------------------------------------
__global__ void probe_pad() {}

// ---------------------------------------------------------------------------
// Kernel C: flash-decode GQA attention, cp.async double-buffered K pipeline.
// (unchanged from R15 winner)
// ---------------------------------------------------------------------------
__global__ __launch_bounds__(256, 3)
void attention(const float* __restrict__ cache_k,
               const float* __restrict__ cache_v,
               const int* __restrict__ start_pos)
{
    __shared__ float4 ksm[8][2][CHT][32];     // 64 KB; reused for acc merge
    __shared__ float  qsm[4 * HD];            // 2 KB
    __shared__ float  psm[8][CHT * 4];        // 1 KB, warp-private
    __shared__ float  msm[8][NREP], lsm[8][NREP];

    const int hh  = blockIdx.x;               // kv head
    const int b   = blockIdx.y;
    const int spl = blockIdx.z;
    const int tx  = threadIdx.x;
    const int w   = tx >> 5;
    const int l   = tx & 31;
    const int tok = l & 7;                    // token within chunk
    const int qr  = l >> 3;                   // dim quarter (32 dims each)

    const int sp = *start_pos;                // 4095
    const int t0 = spl * TSPLIT;

    const float qscale = 1.4426950408889634f * 0.08838834764831845f;
    #pragma unroll
    for (int r = 0; r < 2; r++) {
        int o = tx + r * 256;
        qsm[o] = g_q[b * 4096 + (hh * NREP) * HD + o] * qscale;
    }
    __syncthreads();

    float m0 = -1e30f, m1 = -1e30f, m2 = -1e30f, m3 = -1e30f;
    float ls0 = 0.f, ls1 = 0.f, ls2 = 0.f, ls3 = 0.f;
    float acc[NREP][4];
    #pragma unroll
    for (int qi = 0; qi < NREP; qi++)
        #pragma unroll
        for (int j = 0; j < 4; j++) acc[qi][j] = 0.f;

    const size_t kv_bh = (size_t)b * MAXSEQ * NKV * HD + hh * HD;
    const float* gk = &g_k[(b * NKV + hh) * HD];
    const float* gv = &g_v[(b * NKV + hh) * HD];

    const u32 kbase = smem_u32(&ksm[w][0][0][0]);

    auto stage = [&](int c, int buf) {
        const int tb = t0 + c * CHT;
        #pragma unroll
        for (int r = 0; r < CHT; r++) {
            int tg = tb + r;
            const float* krow = (tg == sp) ? gk
                                           : cache_k + kv_bh + (size_t)tg * (NKV * HD);
            cp16(kbase + (u32)(((buf * CHT + r) * 32 + (l ^ r)) * 16),
                 krow + l * 4);
        }
        cp_commit();
    };

    stage(w, 0);

    for (int j = 0; j < NCHUNK / 8; j++) {
        const int c  = w + j * 8;
        const int tb = t0 + c * CHT;
        const int buf = j & 1;

        if (j < NCHUNK / 8 - 1) { stage(c + 8, buf ^ 1); cp_wait<1>(); }
        else                    { cp_wait<0>(); }
        __syncwarp();

        float s0 = 0.f, s1 = 0.f, s2 = 0.f, s3 = 0.f;
        #pragma unroll
        for (int i = 0; i < 8; i++) {
            int col = qr * 8 + i;
            float4 k4 = ksm[w][buf][tok][col ^ tok];
            float4 q0 = *(const float4*)&qsm[0 * HD + col * 4];
            float4 q1 = *(const float4*)&qsm[1 * HD + col * 4];
            float4 q2 = *(const float4*)&qsm[2 * HD + col * 4];
            float4 q3 = *(const float4*)&qsm[3 * HD + col * 4];
            s0 += k4.x*q0.x + k4.y*q0.y + k4.z*q0.z + k4.w*q0.w;
            s1 += k4.x*q1.x + k4.y*q1.y + k4.z*q1.z + k4.w*q1.w;
            s2 += k4.x*q2.x + k4.y*q2.y + k4.z*q2.z + k4.w*q2.w;
            s3 += k4.x*q3.x + k4.y*q3.y + k4.z*q3.z + k4.w*q3.w;
        }
        s0 += __shfl_xor_sync(0xffffffffu, s0, 8);
        s1 += __shfl_xor_sync(0xffffffffu, s1, 8);
        s2 += __shfl_xor_sync(0xffffffffu, s2, 8);
        s3 += __shfl_xor_sync(0xffffffffu, s3, 8);
        s0 += __shfl_xor_sync(0xffffffffu, s0, 16);
        s1 += __shfl_xor_sync(0xffffffffu, s1, 16);
        s2 += __shfl_xor_sync(0xffffffffu, s2, 16);
        s3 += __shfl_xor_sync(0xffffffffu, s3, 16);
        if (tb + tok > sp) { s0 = -1e30f; s1 = -1e30f; s2 = -1e30f; s3 = -1e30f; }

        float c0 = s0, c1 = s1, c2 = s2, c3 = s3;
        #pragma unroll
        for (int off = 4; off > 0; off >>= 1) {
            c0 = fmaxf(c0, __shfl_xor_sync(0xffffffffu, c0, off));
            c1 = fmaxf(c1, __shfl_xor_sync(0xffffffffu, c1, off));
            c2 = fmaxf(c2, __shfl_xor_sync(0xffffffffu, c2, off));
            c3 = fmaxf(c3, __shfl_xor_sync(0xffffffffu, c3, off));
        }
        if (c0 > m0) { float a = exp2f(m0 - c0); ls0 *= a;
            acc[0][0]*=a; acc[0][1]*=a; acc[0][2]*=a; acc[0][3]*=a; m0 = c0; }
        if (c1 > m1) { float a = exp2f(m1 - c1); ls1 *= a;
            acc[1][0]*=a; acc[1][1]*=a; acc[1][2]*=a; acc[1][3]*=a; m1 = c1; }
        if (c2 > m2) { float a = exp2f(m2 - c2); ls2 *= a;
            acc[2][0]*=a; acc[2][1]*=a; acc[2][2]*=a; acc[2][3]*=a; m2 = c2; }
        if (c3 > m3) { float a = exp2f(m3 - c3); ls3 *= a;
            acc[3][0]*=a; acc[3][1]*=a; acc[3][2]*=a; acc[3][3]*=a; m3 = c3; }

        float p0 = exp2f(s0 - m0), p1 = exp2f(s1 - m1);
        float p2 = exp2f(s2 - m2), p3 = exp2f(s3 - m3);
        if (qr == 0) {
            ls0 += p0; ls1 += p1; ls2 += p2; ls3 += p3;
            *(float4*)&psm[w][tok * 4] = make_float4(p0, p1, p2, p3);
        }
        __syncwarp();

        const float* vlane = cache_v + kv_bh + l * 4;
        #pragma unroll
        for (int tt = 0; tt < CHT; tt++) {
            int tg = tb + tt;
            const float* vp = (tg == sp) ? gv + l * 4
                                         : vlane + (size_t)tg * (NKV * HD);
            float4 v4 = *(const float4*)vp;
            float4 p4 = *(const float4*)&psm[w][tt * 4];
            acc[0][0] += p4.x*v4.x; acc[0][1] += p4.x*v4.y; acc[0][2] += p4.x*v4.z; acc[0][3] += p4.x*v4.w;
            acc[1][0] += p4.y*v4.x; acc[1][1] += p4.y*v4.y; acc[1][2] += p4.y*v4.z; acc[1][3] += p4.y*v4.w;
            acc[2][0] += p4.z*v4.x; acc[2][1] += p4.z*v4.y; acc[2][2] += p4.z*v4.z; acc[2][3] += p4.z*v4.w;
            acc[3][0] += p4.w*v4.x; acc[3][1] += p4.w*v4.y; acc[3][2] += p4.w*v4.z; acc[3][3] += p4.w*v4.w;
        }
        __syncwarp();
    }

    #pragma unroll
    for (int off = 16; off > 0; off >>= 1) {
        ls0 += __shfl_xor_sync(0xffffffffu, ls0, off);
        ls1 += __shfl_xor_sync(0xffffffffu, ls1, off);
        ls2 += __shfl_xor_sync(0xffffffffu, ls2, off);
        ls3 += __shfl_xor_sync(0xffffffffu, ls3, off);
    }

    __syncthreads();
    float* accs = (float*)ksm;                // [8][NREP][HD]
    #pragma unroll
    for (int qi = 0; qi < NREP; qi++)
        *(float4*)&accs[(w * NREP + qi) * HD + l * 4] =
            make_float4(acc[qi][0], acc[qi][1], acc[qi][2], acc[qi][3]);
    if (l == 0) {
        msm[w][0] = m0; msm[w][1] = m1; msm[w][2] = m2; msm[w][3] = m3;
        lsm[w][0] = ls0; lsm[w][1] = ls1; lsm[w][2] = ls2; lsm[w][3] = ls3;
    }
    __syncthreads();

    #pragma unroll
    for (int r = 0; r < 2; r++) {
        int o  = tx + r * 256;
        int qi = o >> 7;
        int d  = o & (HD - 1);
        float M = msm[0][qi];
        #pragma unroll
        for (int w2 = 1; w2 < 8; w2++) M = fmaxf(M, msm[w2][qi]);
        float num = 0.f, den = 0.f;
        #pragma unroll
        for (int w2 = 0; w2 < 8; w2++) {
            float wgt = exp2f(msm[w2][qi] - M);
            num += wgt * accs[(w2 * NREP + qi) * HD + d];
            den += wgt * lsm[w2][qi];
        }
        int pbase = ((b * NKV + hh) * NSPLIT + spl) * NREP + qi;
        g_pacc[(size_t)pbase * HD + d] = num;
        if (d == 0) { g_pl[pbase] = den; g_pm[pbase] = M; }
    }
}

// ---------------------------------------------------------------------------
// Kernel C2: merge the NSPLIT partials -> g_att. grid 256, block 512.
// ---------------------------------------------------------------------------
__global__ __launch_bounds__(512)
void att_merge()
{
    const int bh = blockIdx.x;
    const int o  = threadIdx.x;
    const int qi = o >> 7;
    const int d  = o & (HD - 1);
    const int base = bh * NSPLIT * NREP + qi;

    float M = -1e30f;
    #pragma unroll
    for (int s = 0; s < NSPLIT; s++) M = fmaxf(M, g_pm[base + s * NREP]);
    float num = 0.f, den = 0.f;
    #pragma unroll
    for (int s = 0; s < NSPLIT; s++) {
        int p = base + s * NREP;
        float wgt = exp2f(g_pm[p] - M);
        num += wgt * g_pacc[(size_t)p * HD + d];
        den += wgt * g_pl[p];
    }
    const int b = bh >> 3, h = bh & 7;
    g_att[b * 4096 + (h * NREP + qi) * HD + d] = num / den;
}

// ---------------------------------------------------------------------------
// Kernel D: output projection, split-K, batch-pair f32x2 FMA, 3-buffer
// cp.async-staged weights (same transform as qkv_gemm). grid (32,16), 128.
// ---------------------------------------------------------------------------
__global__ __launch_bounds__(128)
void o_gemm(const float* __restrict__ wo)
{
    __shared__ float xs[KC * 32];         // 32 KB, transposed [k][b^sw]
    __shared__ float wsm[3][WR][128];     // 12 KB
    const int tx = threadIdx.x;
    const int bx = blockIdx.x;
    const int by = blockIdx.y;
    const int k0 = by * KC;

    #pragma unroll
    for (int i = 0; i < 16; i++) {
        int s  = tx + i * 128;
        int b  = s >> 6;
        int k4 = s & 63;
        float4 v = *(const float4*)&g_att[b * DIM + k0 + k4 * 4];
        int e = b ^ ((2 * k4) & 30);
        xs[(k4 * 4 + 0) * 32 + e] = v.x;
        xs[(k4 * 4 + 1) * 32 + e] = v.y;
        xs[(k4 * 4 + 2) * 32 + e] = v.z;
        xs[(k4 * 4 + 3) * 32 + e] = v.w;
    }

    const int q  = tx & 31;
    const int g  = tx >> 5;
    const int b0 = g * 8;
    const int gcol = bx * 128 + q * 4;
    const int colbase = bx * 128;

    const u32 wsb = smem_u32(&wsm[0][0][0]);
    auto stagew = [&](int st, int buf) {
        #pragma unroll
        for (int i = 0; i < 2; i++) {
            int r = g + i * 4;
            cp16(wsb + (u32)(((buf * WR + r) * 128 + q * 4) * 4),
                 wo + (size_t)(k0 + st * WR + r) * DIM + colbase + q * 4);
        }
        cp_commit();
    };

    stagew(0, 0); stagew(1, 1);
    __syncthreads();

    ull accp[16];
    #pragma unroll
    for (int i = 0; i < 16; i++) accp[i] = 0ULL;

    int buf = 0;
    for (int st = 0; st < NWST; st++) {
        cp_wait<1>();
        __syncthreads();
        if (st + 2 < NWST) { int nb = buf + 2; if (nb >= 3) nb -= 3;
                             stagew(st + 2, nb); }
        else               cp_commit();

        const int sw0 = (st * 4) & 30;
        #pragma unroll
        for (int r = 0; r < WR; r++) {
            const int k  = st * WR + r;
            const int sw = sw0 | ((r & 4) >> 1);
            const float* xrow = &xs[k * 32];
            ull xp0 = *(const ull*)&xrow[(b0 + 0) ^ sw];
            ull xp1 = *(const ull*)&xrow[(b0 + 2) ^ sw];
            ull xp2 = *(const ull*)&xrow[(b0 + 4) ^ sw];
            ull xp3 = *(const ull*)&xrow[(b0 + 6) ^ sw];
            float4 w4 = *(const float4*)&wsm[buf][r][q * 4];
            ull wd0 = pk2(w4.x, w4.x), wd1 = pk2(w4.y, w4.y);
            ull wd2 = pk2(w4.z, w4.z), wd3 = pk2(w4.w, w4.w);
            accp[0]  = fma2(xp0, wd0, accp[0]);
            accp[1]  = fma2(xp0, wd1, accp[1]);
            accp[2]  = fma2(xp0, wd2, accp[2]);
            accp[3]  = fma2(xp0, wd3, accp[3]);
            accp[4]  = fma2(xp1, wd0, accp[4]);
            accp[5]  = fma2(xp1, wd1, accp[5]);
            accp[6]  = fma2(xp1, wd2, accp[6]);
            accp[7]  = fma2(xp1, wd3, accp[7]);
            accp[8]  = fma2(xp2, wd0, accp[8]);
            accp[9]  = fma2(xp2, wd1, accp[9]);
            accp[10] = fma2(xp2, wd2, accp[10]);
            accp[11] = fma2(xp2, wd3, accp[11]);
            accp[12] = fma2(xp3, wd0, accp[12]);
            accp[13] = fma2(xp3, wd1, accp[13]);
            accp[14] = fma2(xp3, wd2, accp[14]);
            accp[15] = fma2(xp3, wd3, accp[15]);
        }
        if (++buf == 3) buf = 0;
    }

    #pragma unroll
    for (int p = 0; p < 4; p++) {
        float lo0, hi0, lo1, hi1, lo2, hi2, lo3, hi3;
        upk2(accp[p * 4 + 0], lo0, hi0);
        upk2(accp[p * 4 + 1], lo1, hi1);
        upk2(accp[p * 4 + 2], lo2, hi2);
        upk2(accp[p * 4 + 3], lo3, hi3);
        *(float4*)&g_opart[((size_t)by * BATCH + b0 + 2 * p)     * DIM + gcol]
            = make_float4(lo0, lo1, lo2, lo3);
        *(float4*)&g_opart[((size_t)by * BATCH + b0 + 2 * p + 1) * DIM + gcol]
            = make_float4(hi0, hi1, hi2, hi3);
    }
}

// ---------------------------------------------------------------------------
// Kernel E: reduce O partials -> d_out
// ---------------------------------------------------------------------------
__global__ __launch_bounds__(256)
void o_reduce(float* __restrict__ out)
{
    int idx = blockIdx.x * 256 + threadIdx.x;
    float v = 0.f;
    #pragma unroll
    for (int c = 0; c < NCH; c++)
        v += g_opart[(size_t)c * (BATCH * DIM) + idx];
    out[idx] = v;
}

// ---------------------------------------------------------------------------
extern "C" void kernel_launch(void* const* d_in, const int* in_sizes, int n_in,
                              void* d_out, int out_size)
{
    const float* x        = (const float*)d_in[0];
    const float* cache_k  = (const float*)d_in[1];
    const float* cache_v  = (const float*)d_in[2];
    const float* fcos     = (const float*)d_in[3];
    const float* fsin     = (const float*)d_in[4];
    const float* wq       = (const float*)d_in[5];
    const float* wk       = (const float*)d_in[6];
    const float* wv       = (const float*)d_in[7];
    const float* wo       = (const float*)d_in[8];
    const int*   sp       = (const int*)d_in[9];
    float* out            = (float*)d_out;

    // 3 probes keep qkv_gemm in the 4th-launch ncu capture slot
    probe_pad<<<1, 32>>>();
    probe_pad<<<1, 32>>>();
    probe_pad<<<1, 32>>>();
    qkv_gemm<<<dim3(48, 16), 128>>>(x, wq, wk, wv);
    rope_reduce<<<(BATCH * (NQKV / 2)) / 256, 256>>>(fcos, fsin);
    attention<<<dim3(NKV, BATCH, NSPLIT), 256>>>(cache_k, cache_v, sp);
    att_merge<<<BATCH * NKV, 512>>>();
    o_gemm<<<dim3(32, 16), 128>>>(wo);
    o_reduce<<<(BATCH * DIM) / 256, 256>>>(out);
}